// round 6
// baseline (speedup 1.0000x reference)
#include <cuda_runtime.h>
#include <cuda_bf16.h>
#include <math.h>
#include <stdint.h>

#define BB   4
#define LQd  1024
#define CCd  256
#define HHd  8
#define DHd  32
#define LLd  4
#define PPd  4
#define DFFd 1024
#define LSRCd 21760
#define BQd  (BB*LQd)   // 4096

// ------------------------- scratch (device globals; no allocs) ---------------
__device__ float g_qkproj[BQd*512];          // fused Q|K projection
__device__ float g_v     [BQd*CCd];
__device__ float g_o     [BQd*CCd];
__device__ float g_t2    [BQd*CCd];
__device__ float g_tgt1  [BQd*CCd];
__device__ float g_value [(size_t)BB*LSRCd*CCd];   // 89 MB
__device__ float g_offaw [BQd*384];          // fused offsets|attn-weights
__device__ float g_woffaw[384*CCd];
__device__ float g_boffaw[384];
__device__ float g_samp  [BQd*CCd];
__device__ float g_tgt2  [BQd*CCd];
__device__ float g_ffn   [BQd*DFFd];

// ------------------------- mma helpers ---------------------------------------
__device__ __forceinline__ uint32_t f2tf32(float x) {
    uint32_t r;
    asm("cvt.rna.tf32.f32 %0, %1;" : "=r"(r) : "f"(x));
    return r;
}

__device__ __forceinline__ void mma8(float4& d, const uint32_t* a, const uint32_t* b) {
    asm volatile("mma.sync.aligned.m16n8k8.row.col.f32.tf32.tf32.f32 "
                 "{%0,%1,%2,%3}, {%4,%5,%6,%7}, {%8,%9}, {%0,%1,%2,%3};"
                 : "+f"(d.x), "+f"(d.y), "+f"(d.z), "+f"(d.w)
                 : "r"(a[0]), "r"(a[1]), "r"(a[2]), "r"(a[3]),
                   "r"(b[0]), "r"(b[1]));
}

__device__ __forceinline__ void mma16bf(float4& d, const uint32_t* a, const uint32_t* b) {
    asm volatile("mma.sync.aligned.m16n8k16.row.col.f32.bf16.bf16.f32 "
                 "{%0,%1,%2,%3}, {%4,%5,%6,%7}, {%8,%9}, {%0,%1,%2,%3};"
                 : "+f"(d.x), "+f"(d.y), "+f"(d.z), "+f"(d.w)
                 : "r"(a[0]), "r"(a[1]), "r"(a[2]), "r"(a[3]),
                   "r"(b[0]), "r"(b[1]));
}

__device__ __forceinline__ uint32_t packbf(float x, float y) {
    __nv_bfloat162 h = __floats2bfloat162_rn(x, y);   // low = x, high = y
    return *reinterpret_cast<uint32_t*>(&h);
}

// ------------------------- TF32 tensor-core GEMM -----------------------------
// C = (A [+ A2]) @ W^T + bias.  A:(M,K) row-major, W:(N,K) row-major.
// 128x128 tile, BK=16, 256 threads = 8 warps (2x4), warp tile 64x32.
#define TSTR 20

__global__ __launch_bounds__(256) void gemm_tf32(
    const float* __restrict__ A, const float* __restrict__ A2,
    const float* __restrict__ W,
    const float* __restrict__ bias, float* __restrict__ C,
    int M, int N, int K, int relu)
{
    __shared__ uint32_t As[2][128][TSTR];
    __shared__ uint32_t Bs[2][128][TSTR];
    const int tid  = threadIdx.x;
    const int warp = tid >> 5, lane = tid & 31;
    const int g = lane >> 2, t = lane & 3;
    const int wm = (warp >> 2) * 64, wn = (warp & 3) * 32;
    const int m0 = blockIdx.y * 128, n0 = blockIdx.x * 128;
    const int r_ld = tid >> 2, c_ld = (tid & 3) * 4;

    const float* Ap  = A + (size_t)(m0 + r_ld) * K + c_ld;
    const float* Ap2 = A2 ? A2 + (size_t)(m0 + r_ld) * K + c_ld : nullptr;
    const float* Wp  = W + (size_t)(n0 + r_ld) * K + c_ld;

    float4 acc[4][4];
#pragma unroll
    for (int i = 0; i < 4; i++)
#pragma unroll
        for (int j = 0; j < 4; j++) acc[i][j] = make_float4(0.f, 0.f, 0.f, 0.f);

    // initial tile -> buffer 0
#pragma unroll
    for (int i = 0; i < 2; i++) {
        float4 a = *(const float4*)(Ap + (size_t)(64 * i) * K);
        if (Ap2) {
            float4 a2 = *(const float4*)(Ap2 + (size_t)(64 * i) * K);
            a.x += a2.x; a.y += a2.y; a.z += a2.z; a.w += a2.w;
        }
        float4 b = *(const float4*)(Wp + (size_t)(64 * i) * K);
        uint32_t* as = &As[0][r_ld + 64 * i][c_ld];
        uint32_t* bs = &Bs[0][r_ld + 64 * i][c_ld];
        as[0] = f2tf32(a.x); as[1] = f2tf32(a.y); as[2] = f2tf32(a.z); as[3] = f2tf32(a.w);
        bs[0] = f2tf32(b.x); bs[1] = f2tf32(b.y); bs[2] = f2tf32(b.z); bs[3] = f2tf32(b.w);
    }
    __syncthreads();

    int buf = 0;
    for (int k0 = 16; k0 < K; k0 += 16) {
        float4 pa0 = *(const float4*)(Ap + k0);
        float4 pa1 = *(const float4*)(Ap + (size_t)64 * K + k0);
        if (Ap2) {
            float4 q0v = *(const float4*)(Ap2 + k0);
            float4 q1v = *(const float4*)(Ap2 + (size_t)64 * K + k0);
            pa0.x += q0v.x; pa0.y += q0v.y; pa0.z += q0v.z; pa0.w += q0v.w;
            pa1.x += q1v.x; pa1.y += q1v.y; pa1.z += q1v.z; pa1.w += q1v.w;
        }
        float4 pb0 = *(const float4*)(Wp + k0);
        float4 pb1 = *(const float4*)(Wp + (size_t)64 * K + k0);

#pragma unroll
        for (int ks = 0; ks < 2; ks++) {
            const int kk = ks * 8;
            uint32_t af[4][4], bf[4][2];
#pragma unroll
            for (int mf = 0; mf < 4; mf++) {
                af[mf][0] = As[buf][wm + mf * 16 + g    ][kk + t];
                af[mf][1] = As[buf][wm + mf * 16 + g + 8][kk + t];
                af[mf][2] = As[buf][wm + mf * 16 + g    ][kk + t + 4];
                af[mf][3] = As[buf][wm + mf * 16 + g + 8][kk + t + 4];
            }
#pragma unroll
            for (int nf = 0; nf < 4; nf++) {
                bf[nf][0] = Bs[buf][wn + nf * 8 + g][kk + t];
                bf[nf][1] = Bs[buf][wn + nf * 8 + g][kk + t + 4];
            }
#pragma unroll
            for (int mf = 0; mf < 4; mf++)
#pragma unroll
                for (int nf = 0; nf < 4; nf++)
                    mma8(acc[mf][nf], af[mf], bf[nf]);
        }

        {
            uint32_t* as = &As[buf ^ 1][r_ld][c_ld];
            uint32_t* bs = &Bs[buf ^ 1][r_ld][c_ld];
            as[0] = f2tf32(pa0.x); as[1] = f2tf32(pa0.y); as[2] = f2tf32(pa0.z); as[3] = f2tf32(pa0.w);
            bs[0] = f2tf32(pb0.x); bs[1] = f2tf32(pb0.y); bs[2] = f2tf32(pb0.z); bs[3] = f2tf32(pb0.w);
            uint32_t* as2 = &As[buf ^ 1][r_ld + 64][c_ld];
            uint32_t* bs2 = &Bs[buf ^ 1][r_ld + 64][c_ld];
            as2[0] = f2tf32(pa1.x); as2[1] = f2tf32(pa1.y); as2[2] = f2tf32(pa1.z); as2[3] = f2tf32(pa1.w);
            bs2[0] = f2tf32(pb1.x); bs2[1] = f2tf32(pb1.y); bs2[2] = f2tf32(pb1.z); bs2[3] = f2tf32(pb1.w);
        }
        __syncthreads();
        buf ^= 1;
    }

#pragma unroll
    for (int ks = 0; ks < 2; ks++) {
        const int kk = ks * 8;
        uint32_t af[4][4], bf[4][2];
#pragma unroll
        for (int mf = 0; mf < 4; mf++) {
            af[mf][0] = As[buf][wm + mf * 16 + g    ][kk + t];
            af[mf][1] = As[buf][wm + mf * 16 + g + 8][kk + t];
            af[mf][2] = As[buf][wm + mf * 16 + g    ][kk + t + 4];
            af[mf][3] = As[buf][wm + mf * 16 + g + 8][kk + t + 4];
        }
#pragma unroll
        for (int nf = 0; nf < 4; nf++) {
            bf[nf][0] = Bs[buf][wn + nf * 8 + g][kk + t];
            bf[nf][1] = Bs[buf][wn + nf * 8 + g][kk + t + 4];
        }
#pragma unroll
        for (int mf = 0; mf < 4; mf++)
#pragma unroll
            for (int nf = 0; nf < 4; nf++)
                mma8(acc[mf][nf], af[mf], bf[nf]);
    }

#pragma unroll
    for (int mf = 0; mf < 4; mf++) {
        int row = m0 + wm + mf * 16 + g;
#pragma unroll
        for (int nf = 0; nf < 4; nf++) {
            int col = n0 + wn + nf * 8 + 2 * t;
            float b0 = bias[col], b1 = bias[col + 1];
            float4 v = acc[mf][nf];
            float2 lo = make_float2(v.x + b0, v.y + b1);
            float2 hi = make_float2(v.z + b0, v.w + b1);
            if (relu) {
                lo.x = fmaxf(lo.x, 0.f); lo.y = fmaxf(lo.y, 0.f);
                hi.x = fmaxf(hi.x, 0.f); hi.y = fmaxf(hi.y, 0.f);
            }
            *(float2*)&C[(size_t)row * N + col]       = lo;
            *(float2*)&C[(size_t)(row + 8) * N + col] = hi;
        }
    }
}

// ------------------------- BF16 tensor-core GEMM -----------------------------
// C = A @ W^T + bias. 128x128 tile, BK=16, m16n8k16 bf16 mma. Smem bf16-pairs
// stored as uint32, row stride 12 words (conflict-free frag loads).
__global__ __launch_bounds__(256) void gemm_bf16(
    const float* __restrict__ A, const float* __restrict__ W,
    const float* __restrict__ bias, float* __restrict__ C,
    int M, int N, int K, int relu)
{
    __shared__ uint32_t As[2][128][12];   // 8 pairs of bf16 per row (k=16) + pad
    __shared__ uint32_t Bs[2][128][12];
    const int tid  = threadIdx.x;
    const int warp = tid >> 5, lane = tid & 31;
    const int g = lane >> 2, t = lane & 3;
    const int wm = (warp >> 2) * 64, wn = (warp & 3) * 32;
    const int m0 = blockIdx.y * 128, n0 = blockIdx.x * 128;
    const int r_ld = tid >> 2, c_ld = (tid & 3) * 4;   // cols, pair idx = c_ld/2

    const float* Ap = A + (size_t)(m0 + r_ld) * K + c_ld;
    const float* Wp = W + (size_t)(n0 + r_ld) * K + c_ld;

    float4 acc[4][4];
#pragma unroll
    for (int i = 0; i < 4; i++)
#pragma unroll
        for (int j = 0; j < 4; j++) acc[i][j] = make_float4(0.f, 0.f, 0.f, 0.f);

#pragma unroll
    for (int i = 0; i < 2; i++) {
        float4 a = *(const float4*)(Ap + (size_t)(64 * i) * K);
        float4 b = *(const float4*)(Wp + (size_t)(64 * i) * K);
        uint32_t* as = &As[0][r_ld + 64 * i][c_ld >> 1];
        uint32_t* bs = &Bs[0][r_ld + 64 * i][c_ld >> 1];
        as[0] = packbf(a.x, a.y); as[1] = packbf(a.z, a.w);
        bs[0] = packbf(b.x, b.y); bs[1] = packbf(b.z, b.w);
    }
    __syncthreads();

    int buf = 0;
    for (int k0 = 16; k0 < K; k0 += 16) {
        float4 pa0 = *(const float4*)(Ap + k0);
        float4 pa1 = *(const float4*)(Ap + (size_t)64 * K + k0);
        float4 pb0 = *(const float4*)(Wp + k0);
        float4 pb1 = *(const float4*)(Wp + (size_t)64 * K + k0);

        {
            uint32_t af[4][4], bf[4][2];
#pragma unroll
            for (int mf = 0; mf < 4; mf++) {
                af[mf][0] = As[buf][wm + mf * 16 + g    ][t];
                af[mf][1] = As[buf][wm + mf * 16 + g + 8][t];
                af[mf][2] = As[buf][wm + mf * 16 + g    ][t + 4];
                af[mf][3] = As[buf][wm + mf * 16 + g + 8][t + 4];
            }
#pragma unroll
            for (int nf = 0; nf < 4; nf++) {
                bf[nf][0] = Bs[buf][wn + nf * 8 + g][t];
                bf[nf][1] = Bs[buf][wn + nf * 8 + g][t + 4];
            }
#pragma unroll
            for (int mf = 0; mf < 4; mf++)
#pragma unroll
                for (int nf = 0; nf < 4; nf++)
                    mma16bf(acc[mf][nf], af[mf], bf[nf]);
        }

        {
            uint32_t* as = &As[buf ^ 1][r_ld][c_ld >> 1];
            uint32_t* bs = &Bs[buf ^ 1][r_ld][c_ld >> 1];
            as[0] = packbf(pa0.x, pa0.y); as[1] = packbf(pa0.z, pa0.w);
            bs[0] = packbf(pb0.x, pb0.y); bs[1] = packbf(pb0.z, pb0.w);
            uint32_t* as2 = &As[buf ^ 1][r_ld + 64][c_ld >> 1];
            uint32_t* bs2 = &Bs[buf ^ 1][r_ld + 64][c_ld >> 1];
            as2[0] = packbf(pa1.x, pa1.y); as2[1] = packbf(pa1.z, pa1.w);
            bs2[0] = packbf(pb1.x, pb1.y); bs2[1] = packbf(pb1.z, pb1.w);
        }
        __syncthreads();
        buf ^= 1;
    }

    {
        uint32_t af[4][4], bf[4][2];
#pragma unroll
        for (int mf = 0; mf < 4; mf++) {
            af[mf][0] = As[buf][wm + mf * 16 + g    ][t];
            af[mf][1] = As[buf][wm + mf * 16 + g + 8][t];
            af[mf][2] = As[buf][wm + mf * 16 + g    ][t + 4];
            af[mf][3] = As[buf][wm + mf * 16 + g + 8][t + 4];
        }
#pragma unroll
        for (int nf = 0; nf < 4; nf++) {
            bf[nf][0] = Bs[buf][wn + nf * 8 + g][t];
            bf[nf][1] = Bs[buf][wn + nf * 8 + g][t + 4];
        }
#pragma unroll
        for (int mf = 0; mf < 4; mf++)
#pragma unroll
            for (int nf = 0; nf < 4; nf++)
                mma16bf(acc[mf][nf], af[mf], bf[nf]);
    }

#pragma unroll
    for (int mf = 0; mf < 4; mf++) {
        int row = m0 + wm + mf * 16 + g;
#pragma unroll
        for (int nf = 0; nf < 4; nf++) {
            int col = n0 + wn + nf * 8 + 2 * t;
            float b0 = bias[col], b1 = bias[col + 1];
            float4 v = acc[mf][nf];
            float2 lo = make_float2(v.x + b0, v.y + b1);
            float2 hi = make_float2(v.z + b0, v.w + b1);
            if (relu) {
                lo.x = fmaxf(lo.x, 0.f); lo.y = fmaxf(lo.y, 0.f);
                hi.x = fmaxf(hi.x, 0.f); hi.y = fmaxf(hi.y, 0.f);
            }
            *(float2*)&C[(size_t)row * N + col]       = lo;
            *(float2*)&C[(size_t)(row + 8) * N + col] = hi;
        }
    }
}

// ------------------------- tensor-core flash attention -----------------------
// grid (LQ/128=8, B*H=32), 256 thr = 8 warps; warp = 16 q-rows x 64 keys.
// Q,K from fused proj (row stride 512), V stride 256. tf32 mma everywhere.
__global__ __launch_bounds__(256) void flash_attn_mma(
    const float* __restrict__ qkproj, const float* __restrict__ vsrc,
    float* __restrict__ O)
{
    __shared__ uint32_t Ks[64][36];
    __shared__ uint32_t Vs[32][68];
    __shared__ uint32_t Ps[8][16][68];   // per-warp P; also Q staging (needs 128*36)

    const int bh = blockIdx.y, b = bh >> 3, h = bh & 7;
    const int q0 = blockIdx.x * 128;
    const int tid = threadIdx.x, warp = tid >> 5, lane = tid & 31;
    const int g = lane >> 2, t = lane & 3;
    const float SC = 0.1767766952966368932f;

    const float* qp = qkproj + (size_t)b * LQd * 512 + h * DHd;
    const float* kp = qp + 256;
    const float* vp = vsrc + (size_t)b * LQd * CCd + h * DHd;

    // stage Q (scaled) into Ps region, then load frags to registers
    uint32_t* Qstage = &Ps[0][0][0];
#pragma unroll
    for (int i = 0; i < 16; i++) {
        int idx = tid + i * 256;
        int row = idx >> 5, d = idx & 31;
        Qstage[row * 36 + d] = f2tf32(qp[(size_t)(q0 + row) * 512 + d] * SC);
    }
    __syncthreads();
    uint32_t qf[4][4];
#pragma unroll
    for (int kc = 0; kc < 4; kc++) {
        int r = (warp * 16 + g) * 36;
        qf[kc][0] = Qstage[r + kc * 8 + t];
        qf[kc][1] = Qstage[r + 8 * 36 + kc * 8 + t];
        qf[kc][2] = Qstage[r + kc * 8 + t + 4];
        qf[kc][3] = Qstage[r + 8 * 36 + kc * 8 + t + 4];
    }

    float m0r = -1e30f, m1r = -1e30f, l0r = 0.f, l1r = 0.f;
    float4 oacc[4];
#pragma unroll
    for (int i = 0; i < 4; i++) oacc[i] = make_float4(0.f, 0.f, 0.f, 0.f);

    for (int kt = 0; kt < 16; kt++) {
        const float* kbase = kp + (size_t)kt * 64 * 512;
        const float* vbase = vp + (size_t)kt * 64 * 256;
        __syncthreads();   // Q frags read / previous iter's Ks,Vs reads done
#pragma unroll
        for (int i = 0; i < 8; i++) {
            int idx = tid + i * 256;
            int key = idx >> 5, d = idx & 31;
            Ks[key][d] = f2tf32(kbase[(size_t)key * 512 + d]);
            Vs[d][key] = f2tf32(vbase[(size_t)key * 256 + d]);
        }
        __syncthreads();

        // S = Q K^T  (16x64 per warp)
        float4 sacc[8];
#pragma unroll
        for (int nf = 0; nf < 8; nf++) sacc[nf] = make_float4(0.f, 0.f, 0.f, 0.f);
#pragma unroll
        for (int nf = 0; nf < 8; nf++) {
#pragma unroll
            for (int kc = 0; kc < 4; kc++) {
                uint32_t bf[2];
                bf[0] = Ks[nf * 8 + g][kc * 8 + t];
                bf[1] = Ks[nf * 8 + g][kc * 8 + t + 4];
                mma8(sacc[nf], qf[kc], bf);
            }
        }

        // online softmax (rows g and g+8 of this warp)
        float mx0 = -1e30f, mx1 = -1e30f;
#pragma unroll
        for (int nf = 0; nf < 8; nf++) {
            mx0 = fmaxf(mx0, fmaxf(sacc[nf].x, sacc[nf].y));
            mx1 = fmaxf(mx1, fmaxf(sacc[nf].z, sacc[nf].w));
        }
        mx0 = fmaxf(mx0, __shfl_xor_sync(0xffffffffu, mx0, 1));
        mx0 = fmaxf(mx0, __shfl_xor_sync(0xffffffffu, mx0, 2));
        mx1 = fmaxf(mx1, __shfl_xor_sync(0xffffffffu, mx1, 1));
        mx1 = fmaxf(mx1, __shfl_xor_sync(0xffffffffu, mx1, 2));
        float mn0 = fmaxf(m0r, mx0), mn1 = fmaxf(m1r, mx1);
        float cf0 = __expf(m0r - mn0), cf1 = __expf(m1r - mn1);
        float rs0 = 0.f, rs1 = 0.f;
#pragma unroll
        for (int nf = 0; nf < 8; nf++) {
            float p0 = __expf(sacc[nf].x - mn0);
            float p1 = __expf(sacc[nf].y - mn0);
            float p2 = __expf(sacc[nf].z - mn1);
            float p3 = __expf(sacc[nf].w - mn1);
            rs0 += p0 + p1; rs1 += p2 + p3;
            Ps[warp][g    ][nf * 8 + 2 * t]     = f2tf32(p0);
            Ps[warp][g    ][nf * 8 + 2 * t + 1] = f2tf32(p1);
            Ps[warp][g + 8][nf * 8 + 2 * t]     = f2tf32(p2);
            Ps[warp][g + 8][nf * 8 + 2 * t + 1] = f2tf32(p3);
        }
        rs0 += __shfl_xor_sync(0xffffffffu, rs0, 1);
        rs0 += __shfl_xor_sync(0xffffffffu, rs0, 2);
        rs1 += __shfl_xor_sync(0xffffffffu, rs1, 1);
        rs1 += __shfl_xor_sync(0xffffffffu, rs1, 2);
        l0r = l0r * cf0 + rs0; l1r = l1r * cf1 + rs1;
        m0r = mn0; m1r = mn1;
#pragma unroll
        for (int nf = 0; nf < 4; nf++) {
            oacc[nf].x *= cf0; oacc[nf].y *= cf0;
            oacc[nf].z *= cf1; oacc[nf].w *= cf1;
        }
        __syncwarp();

        // O += P V  (16x32 per warp)
#pragma unroll
        for (int kc = 0; kc < 8; kc++) {
            uint32_t af[4];
            af[0] = Ps[warp][g    ][kc * 8 + t];
            af[1] = Ps[warp][g + 8][kc * 8 + t];
            af[2] = Ps[warp][g    ][kc * 8 + t + 4];
            af[3] = Ps[warp][g + 8][kc * 8 + t + 4];
#pragma unroll
            for (int nf = 0; nf < 4; nf++) {
                uint32_t bf[2];
                bf[0] = Vs[nf * 8 + g][kc * 8 + t];
                bf[1] = Vs[nf * 8 + g][kc * 8 + t + 4];
                mma8(oacc[nf], af, bf);
            }
        }
    }

    float inv0 = 1.f / l0r, inv1 = 1.f / l1r;
    int row = q0 + warp * 16 + g;
#pragma unroll
    for (int nf = 0; nf < 4; nf++) {
        int col = h * DHd + nf * 8 + 2 * t;
        *(float2*)&O[(size_t)(b * LQd + row) * CCd + col] =
            make_float2(oacc[nf].x * inv0, oacc[nf].y * inv0);
        *(float2*)&O[(size_t)(b * LQd + row + 8) * CCd + col] =
            make_float2(oacc[nf].z * inv1, oacc[nf].w * inv1);
    }
}

// ------------------------- fused residual + LayerNorm ------------------------
__global__ void add_ln(const float* __restrict__ a, const float* __restrict__ b,
                       const float* __restrict__ g, const float* __restrict__ bet,
                       float* __restrict__ out)
{
    __shared__ float sh[256];
    int row = blockIdx.x, t = threadIdx.x;
    size_t idx = (size_t)row * CCd + t;
    float v = a[idx] + b[idx];
    sh[t] = v; __syncthreads();
    for (int s = 128; s > 0; s >>= 1) { if (t < s) sh[t] += sh[t + s]; __syncthreads(); }
    float mean = sh[0] * (1.f / 256.f);
    __syncthreads();
    float d = v - mean;
    sh[t] = d * d; __syncthreads();
    for (int s = 128; s > 0; s >>= 1) { if (t < s) sh[t] += sh[t + s]; __syncthreads(); }
    float var = sh[0] * (1.f / 256.f);
    out[idx] = d * rsqrtf(var + 1e-5f) * g[t] + bet[t];
}

// ------------------------- attention-weight softmax over L*P=16 --------------
__global__ void aw_softmax(float* __restrict__ a)
{
    int gi = blockIdx.x * blockDim.x + threadIdx.x;
    if (gi >= BQd * HHd) return;
    int bq = gi >> 3, h = gi & 7;
    float* p = a + (size_t)bq * 384 + 256 + h * 16;
    float x[16];
    float m = -1e30f;
#pragma unroll
    for (int i = 0; i < 16; i++) { x[i] = p[i]; m = fmaxf(m, x[i]); }
    float s = 0.f;
#pragma unroll
    for (int i = 0; i < 16; i++) { x[i] = __expf(x[i] - m); s += x[i]; }
    float inv = 1.f / s;
#pragma unroll
    for (int i = 0; i < 16; i++) p[i] = x[i] * inv;
}

// ------------------------- multi-scale deformable sampling -------------------
__global__ void deform_sample(const float* __restrict__ value, const float* __restrict__ ref,
                              const float* __restrict__ offaw, float* __restrict__ out)
{
    const int levH[4] = {128, 64, 32, 16};
    const int levW[4] = {128, 64, 32, 16};
    const int levS[4] = {0, 16384, 20480, 21504};
    int bq = blockIdx.x;
    int b  = bq >> 10;
    int h  = threadIdx.x >> 5;
    int d  = threadIdx.x & 31;
    float acc = 0.f;
#pragma unroll
    for (int l = 0; l < 4; l++) {
        float rx = ref[((size_t)bq * LLd + l) * 2 + 0];
        float ry = ref[((size_t)bq * LLd + l) * 2 + 1];
        int w = levW[l], hh = levH[l], st = levS[l];
        float fw = (float)w, fh = (float)hh;
#pragma unroll
        for (int p = 0; p < 4; p++) {
            size_t oidx = (size_t)bq * 384 + h * 32 + (l * 4 + p) * 2;
            float lx = rx + offaw[oidx]     / fw;
            float ly = ry + offaw[oidx + 1] / fh;
            float x = lx * fw - 0.5f;
            float y = ly * fh - 0.5f;
            float x0f = floorf(x), y0f = floorf(y);
            int x0 = (int)x0f, y0 = (int)y0f;
            float wx1 = x - x0f, wx0 = 1.f - wx1;
            float wy1 = y - y0f, wy0 = 1.f - wy1;
            float a = offaw[(size_t)bq * 384 + 256 + h * 16 + l * 4 + p];
            float s = 0.f;
#pragma unroll
            for (int cy = 0; cy < 2; cy++) {
#pragma unroll
                for (int cx = 0; cx < 2; cx++) {
                    int ix = x0 + cx, iy = y0 + cy;
                    if (ix >= 0 && ix < w && iy >= 0 && iy < hh) {
                        float wgt = (cx ? wx1 : wx0) * (cy ? wy1 : wy0);
                        size_t vidx = (((size_t)(b * LSRCd + st + iy * w + ix)) * HHd + h) * DHd + d;
                        s += wgt * value[vidx];
                    }
                }
            }
            acc += a * s;
        }
    }
    out[(size_t)bq * CCd + h * DHd + d] = acc;
}

// ------------------------- launch --------------------------------------------
extern "C" void kernel_launch(void* const* d_in, const int* in_sizes, int n_in,
                              void* d_out, int out_size)
{
    (void)in_sizes; (void)n_in; (void)out_size;
    const float* tgt   = (const float*)d_in[0];
    const float* qpos  = (const float*)d_in[1];
    const float* ref   = (const float*)d_in[2];
    const float* src   = (const float*)d_in[3];
    const float* in_w  = (const float*)d_in[4];
    const float* in_b  = (const float*)d_in[5];
    const float* sa_w  = (const float*)d_in[6];
    const float* sa_b  = (const float*)d_in[7];
    const float* off_w = (const float*)d_in[8];
    const float* off_b = (const float*)d_in[9];
    const float* aw_w  = (const float*)d_in[10];
    const float* aw_b  = (const float*)d_in[11];
    const float* val_w = (const float*)d_in[12];
    const float* val_b = (const float*)d_in[13];
    const float* co_w  = (const float*)d_in[14];
    const float* co_b  = (const float*)d_in[15];
    const float* ln1_g = (const float*)d_in[16];
    const float* ln1_b = (const float*)d_in[17];
    const float* ln2_g = (const float*)d_in[18];
    const float* ln2_b = (const float*)d_in[19];
    const float* ln3_g = (const float*)d_in[20];
    const float* ln3_b = (const float*)d_in[21];
    const float* f1_w  = (const float*)d_in[22];
    const float* f1_b  = (const float*)d_in[23];
    const float* f2_w  = (const float*)d_in[24];
    const float* f2_b  = (const float*)d_in[25];
    float* out = (float*)d_out;

    float *qkproj, *v, *o, *t2, *tgt1, *value, *offaw, *woffaw, *boffaw, *samp, *tgt2, *ffn;
    cudaGetSymbolAddress((void**)&qkproj, g_qkproj);
    cudaGetSymbolAddress((void**)&v,      g_v);
    cudaGetSymbolAddress((void**)&o,      g_o);
    cudaGetSymbolAddress((void**)&t2,     g_t2);
    cudaGetSymbolAddress((void**)&tgt1,   g_tgt1);
    cudaGetSymbolAddress((void**)&value,  g_value);
    cudaGetSymbolAddress((void**)&offaw,  g_offaw);
    cudaGetSymbolAddress((void**)&woffaw, g_woffaw);
    cudaGetSymbolAddress((void**)&boffaw, g_boffaw);
    cudaGetSymbolAddress((void**)&samp,   g_samp);
    cudaGetSymbolAddress((void**)&tgt2,   g_tgt2);
    cudaGetSymbolAddress((void**)&ffn,    g_ffn);

    // fuse off/aw weights into one (384,256) matrix + (384,) bias
    cudaMemcpyAsync(woffaw,             off_w, 256 * 256 * sizeof(float), cudaMemcpyDeviceToDevice);
    cudaMemcpyAsync(woffaw + 256 * 256, aw_w,  128 * 256 * sizeof(float), cudaMemcpyDeviceToDevice);
    cudaMemcpyAsync(boffaw,             off_b, 256 * sizeof(float),       cudaMemcpyDeviceToDevice);
    cudaMemcpyAsync(boffaw + 256,       aw_b,  128 * sizeof(float),       cudaMemcpyDeviceToDevice);

    // ---- self-attention ----
    gemm_tf32<<<dim3(4, 32), 256>>>(tgt, qpos, in_w, in_b, qkproj, BQd, 512, CCd, 0);  // fused Q|K on tgt+pos
    gemm_tf32<<<dim3(2, 32), 256>>>(tgt, nullptr, in_w + 2 * CCd * CCd, in_b + 2 * CCd, v, BQd, CCd, CCd, 0);
    flash_attn_mma<<<dim3(8, 32), 256>>>(qkproj, v, o);
    gemm_tf32<<<dim3(2, 32), 256>>>(o, nullptr, sa_w, sa_b, t2, BQd, CCd, CCd, 0);
    add_ln<<<BQd, 256>>>(tgt, t2, ln2_g, ln2_b, tgt1);

    // ---- deformable cross-attention ----
    gemm_bf16<<<dim3(2, 680), 256>>>(src, val_w, val_b, value, BB * LSRCd, CCd, CCd, 0);
    gemm_tf32<<<dim3(3, 32), 256>>>(tgt1, qpos, woffaw, boffaw, offaw, BQd, 384, CCd, 0); // fused off|aw on tgt1+pos
    aw_softmax<<<(BQd * HHd + 255) / 256, 256>>>(offaw);
    deform_sample<<<BQd, 256>>>(value, ref, offaw, samp);
    gemm_tf32<<<dim3(2, 32), 256>>>(samp, nullptr, co_w, co_b, t2, BQd, CCd, CCd, 0);
    add_ln<<<BQd, 256>>>(tgt1, t2, ln1_g, ln1_b, tgt2);

    // ---- FFN ----
    gemm_bf16<<<dim3(8, 32), 256>>>(tgt2, f1_w, f1_b, ffn, BQd, DFFd, CCd, 1);
    gemm_bf16<<<dim3(2, 32), 256>>>(ffn, f2_w, f2_b, t2, BQd, CCd, DFFd, 0);
    add_ln<<<BQd, 256>>>(tgt2, t2, ln3_g, ln3_b, out);
}

// round 9
// speedup vs baseline: 1.3315x; 1.3315x over previous
#include <cuda_runtime.h>
#include <cuda_bf16.h>
#include <math.h>
#include <stdint.h>

#define BB   4
#define LQd  1024
#define CCd  256
#define HHd  8
#define DHd  32
#define LLd  4
#define PPd  4
#define DFFd 1024
#define LSRCd 21760
#define BQd  (BB*LQd)   // 4096

// ------------------------- scratch (device globals; no allocs) ---------------
__device__ float g_qkproj[BQd*512];
__device__ float g_v     [BQd*CCd];
__device__ float g_o     [BQd*CCd];
__device__ float g_t2    [BQd*CCd];
__device__ float g_tgt1  [BQd*CCd];
__device__ float g_value [(size_t)BB*LSRCd*CCd];
__device__ float g_offaw [BQd*384];
__device__ float g_woffaw[384*CCd];
__device__ float g_boffaw[384];
__device__ float g_samp  [BQd*CCd];
__device__ float g_tgt2  [BQd*CCd];
__device__ float g_ffn   [BQd*DFFd];

// ------------------------- mma helpers ---------------------------------------
__device__ __forceinline__ uint32_t f2tf32(float x) {
    uint32_t r;
    asm("cvt.rna.tf32.f32 %0, %1;" : "=r"(r) : "f"(x));
    return r;
}

__device__ __forceinline__ void mma8(float4& d, const uint32_t* a, const uint32_t* b) {
    asm volatile("mma.sync.aligned.m16n8k8.row.col.f32.tf32.tf32.f32 "
                 "{%0,%1,%2,%3}, {%4,%5,%6,%7}, {%8,%9}, {%0,%1,%2,%3};"
                 : "+f"(d.x), "+f"(d.y), "+f"(d.z), "+f"(d.w)
                 : "r"(a[0]), "r"(a[1]), "r"(a[2]), "r"(a[3]),
                   "r"(b[0]), "r"(b[1]));
}

__device__ __forceinline__ void mma16bf(float4& d, const uint32_t* a, const uint32_t* b) {
    asm volatile("mma.sync.aligned.m16n8k16.row.col.f32.bf16.bf16.f32 "
                 "{%0,%1,%2,%3}, {%4,%5,%6,%7}, {%8,%9}, {%0,%1,%2,%3};"
                 : "+f"(d.x), "+f"(d.y), "+f"(d.z), "+f"(d.w)
                 : "r"(a[0]), "r"(a[1]), "r"(a[2]), "r"(a[3]),
                   "r"(b[0]), "r"(b[1]));
}

__device__ __forceinline__ uint32_t packbf(float x, float y) {
    __nv_bfloat162 h = __floats2bfloat162_rn(x, y);
    return *reinterpret_cast<uint32_t*>(&h);
}

// ------------------------- TF32 GEMM, 64x64 tile, 128 threads ----------------
// C = (A [+A2]) @ W^T + bias. High CTA count for small-N projections.
#define TSTR 20

__global__ __launch_bounds__(128) void gemm_tf32_64(
    const float* __restrict__ A, const float* __restrict__ A2,
    const float* __restrict__ W,
    const float* __restrict__ bias, float* __restrict__ C,
    int M, int N, int K, int relu)
{
    __shared__ uint32_t As[2][64][TSTR];
    __shared__ uint32_t Bs[2][64][TSTR];
    const int tid  = threadIdx.x;
    const int warp = tid >> 5, lane = tid & 31;
    const int g = lane >> 2, t = lane & 3;
    const int wm = (warp >> 1) * 32, wn = (warp & 1) * 32;
    const int m0 = blockIdx.y * 64, n0 = blockIdx.x * 64;
    const int r_ld = tid >> 2, c_ld = (tid & 3) * 4;

    const float* Ap  = A + (size_t)(m0 + r_ld) * K + c_ld;
    const float* Ap2 = A2 ? A2 + (size_t)(m0 + r_ld) * K + c_ld : nullptr;
    const float* Wp  = W + (size_t)(n0 + r_ld) * K + c_ld;

    float4 acc[2][4];
#pragma unroll
    for (int i = 0; i < 2; i++)
#pragma unroll
        for (int j = 0; j < 4; j++) acc[i][j] = make_float4(0.f, 0.f, 0.f, 0.f);

#pragma unroll
    for (int i = 0; i < 2; i++) {
        float4 a = *(const float4*)(Ap + (size_t)(32 * i) * K);
        if (Ap2) {
            float4 a2 = *(const float4*)(Ap2 + (size_t)(32 * i) * K);
            a.x += a2.x; a.y += a2.y; a.z += a2.z; a.w += a2.w;
        }
        float4 b = *(const float4*)(Wp + (size_t)(32 * i) * K);
        uint32_t* as = &As[0][r_ld + 32 * i][c_ld];
        uint32_t* bs = &Bs[0][r_ld + 32 * i][c_ld];
        as[0] = f2tf32(a.x); as[1] = f2tf32(a.y); as[2] = f2tf32(a.z); as[3] = f2tf32(a.w);
        bs[0] = f2tf32(b.x); bs[1] = f2tf32(b.y); bs[2] = f2tf32(b.z); bs[3] = f2tf32(b.w);
    }
    __syncthreads();

    int buf = 0;
    for (int k0 = 16; k0 < K; k0 += 16) {
        float4 pa0 = *(const float4*)(Ap + k0);
        float4 pa1 = *(const float4*)(Ap + (size_t)32 * K + k0);
        if (Ap2) {
            float4 q0v = *(const float4*)(Ap2 + k0);
            float4 q1v = *(const float4*)(Ap2 + (size_t)32 * K + k0);
            pa0.x += q0v.x; pa0.y += q0v.y; pa0.z += q0v.z; pa0.w += q0v.w;
            pa1.x += q1v.x; pa1.y += q1v.y; pa1.z += q1v.z; pa1.w += q1v.w;
        }
        float4 pb0 = *(const float4*)(Wp + k0);
        float4 pb1 = *(const float4*)(Wp + (size_t)32 * K + k0);

#pragma unroll
        for (int ks = 0; ks < 2; ks++) {
            const int kk = ks * 8;
            uint32_t af[2][4], bf[4][2];
#pragma unroll
            for (int mf = 0; mf < 2; mf++) {
                af[mf][0] = As[buf][wm + mf * 16 + g    ][kk + t];
                af[mf][1] = As[buf][wm + mf * 16 + g + 8][kk + t];
                af[mf][2] = As[buf][wm + mf * 16 + g    ][kk + t + 4];
                af[mf][3] = As[buf][wm + mf * 16 + g + 8][kk + t + 4];
            }
#pragma unroll
            for (int nf = 0; nf < 4; nf++) {
                bf[nf][0] = Bs[buf][wn + nf * 8 + g][kk + t];
                bf[nf][1] = Bs[buf][wn + nf * 8 + g][kk + t + 4];
            }
#pragma unroll
            for (int mf = 0; mf < 2; mf++)
#pragma unroll
                for (int nf = 0; nf < 4; nf++)
                    mma8(acc[mf][nf], af[mf], bf[nf]);
        }

        {
            uint32_t* as = &As[buf ^ 1][r_ld][c_ld];
            uint32_t* bs = &Bs[buf ^ 1][r_ld][c_ld];
            as[0] = f2tf32(pa0.x); as[1] = f2tf32(pa0.y); as[2] = f2tf32(pa0.z); as[3] = f2tf32(pa0.w);
            bs[0] = f2tf32(pb0.x); bs[1] = f2tf32(pb0.y); bs[2] = f2tf32(pb0.z); bs[3] = f2tf32(pb0.w);
            uint32_t* as2 = &As[buf ^ 1][r_ld + 32][c_ld];
            uint32_t* bs2 = &Bs[buf ^ 1][r_ld + 32][c_ld];
            as2[0] = f2tf32(pa1.x); as2[1] = f2tf32(pa1.y); as2[2] = f2tf32(pa1.z); as2[3] = f2tf32(pa1.w);
            bs2[0] = f2tf32(pb1.x); bs2[1] = f2tf32(pb1.y); bs2[2] = f2tf32(pb1.z); bs2[3] = f2tf32(pb1.w);
        }
        __syncthreads();
        buf ^= 1;
    }

#pragma unroll
    for (int ks = 0; ks < 2; ks++) {
        const int kk = ks * 8;
        uint32_t af[2][4], bf[4][2];
#pragma unroll
        for (int mf = 0; mf < 2; mf++) {
            af[mf][0] = As[buf][wm + mf * 16 + g    ][kk + t];
            af[mf][1] = As[buf][wm + mf * 16 + g + 8][kk + t];
            af[mf][2] = As[buf][wm + mf * 16 + g    ][kk + t + 4];
            af[mf][3] = As[buf][wm + mf * 16 + g + 8][kk + t + 4];
        }
#pragma unroll
        for (int nf = 0; nf < 4; nf++) {
            bf[nf][0] = Bs[buf][wn + nf * 8 + g][kk + t];
            bf[nf][1] = Bs[buf][wn + nf * 8 + g][kk + t + 4];
        }
#pragma unroll
        for (int mf = 0; mf < 2; mf++)
#pragma unroll
            for (int nf = 0; nf < 4; nf++)
                mma8(acc[mf][nf], af[mf], bf[nf]);
    }

#pragma unroll
    for (int mf = 0; mf < 2; mf++) {
        int row = m0 + wm + mf * 16 + g;
#pragma unroll
        for (int nf = 0; nf < 4; nf++) {
            int col = n0 + wn + nf * 8 + 2 * t;
            float b0 = bias[col], b1 = bias[col + 1];
            float4 v = acc[mf][nf];
            float2 lo = make_float2(v.x + b0, v.y + b1);
            float2 hi = make_float2(v.z + b0, v.w + b1);
            if (relu) {
                lo.x = fmaxf(lo.x, 0.f); lo.y = fmaxf(lo.y, 0.f);
                hi.x = fmaxf(hi.x, 0.f); hi.y = fmaxf(hi.y, 0.f);
            }
            *(float2*)&C[(size_t)row * N + col]       = lo;
            *(float2*)&C[(size_t)(row + 8) * N + col] = hi;
        }
    }
}

// ------------------------- BF16 tensor-core GEMM (128x128) -------------------
__global__ __launch_bounds__(256) void gemm_bf16(
    const float* __restrict__ A, const float* __restrict__ W,
    const float* __restrict__ bias, float* __restrict__ C,
    int M, int N, int K, int relu)
{
    __shared__ uint32_t As[2][128][12];
    __shared__ uint32_t Bs[2][128][12];
    const int tid  = threadIdx.x;
    const int warp = tid >> 5, lane = tid & 31;
    const int g = lane >> 2, t = lane & 3;
    const int wm = (warp >> 2) * 64, wn = (warp & 3) * 32;
    const int m0 = blockIdx.y * 128, n0 = blockIdx.x * 128;
    const int r_ld = tid >> 2, c_ld = (tid & 3) * 4;

    const float* Ap = A + (size_t)(m0 + r_ld) * K + c_ld;
    const float* Wp = W + (size_t)(n0 + r_ld) * K + c_ld;

    float4 acc[4][4];
#pragma unroll
    for (int i = 0; i < 4; i++)
#pragma unroll
        for (int j = 0; j < 4; j++) acc[i][j] = make_float4(0.f, 0.f, 0.f, 0.f);

#pragma unroll
    for (int i = 0; i < 2; i++) {
        float4 a = *(const float4*)(Ap + (size_t)(64 * i) * K);
        float4 b = *(const float4*)(Wp + (size_t)(64 * i) * K);
        uint32_t* as = &As[0][r_ld + 64 * i][c_ld >> 1];
        uint32_t* bs = &Bs[0][r_ld + 64 * i][c_ld >> 1];
        as[0] = packbf(a.x, a.y); as[1] = packbf(a.z, a.w);
        bs[0] = packbf(b.x, b.y); bs[1] = packbf(b.z, b.w);
    }
    __syncthreads();

    int buf = 0;
    for (int k0 = 16; k0 < K; k0 += 16) {
        float4 pa0 = *(const float4*)(Ap + k0);
        float4 pa1 = *(const float4*)(Ap + (size_t)64 * K + k0);
        float4 pb0 = *(const float4*)(Wp + k0);
        float4 pb1 = *(const float4*)(Wp + (size_t)64 * K + k0);

        {
            uint32_t af[4][4], bf[4][2];
#pragma unroll
            for (int mf = 0; mf < 4; mf++) {
                af[mf][0] = As[buf][wm + mf * 16 + g    ][t];
                af[mf][1] = As[buf][wm + mf * 16 + g + 8][t];
                af[mf][2] = As[buf][wm + mf * 16 + g    ][t + 4];
                af[mf][3] = As[buf][wm + mf * 16 + g + 8][t + 4];
            }
#pragma unroll
            for (int nf = 0; nf < 4; nf++) {
                bf[nf][0] = Bs[buf][wn + nf * 8 + g][t];
                bf[nf][1] = Bs[buf][wn + nf * 8 + g][t + 4];
            }
#pragma unroll
            for (int mf = 0; mf < 4; mf++)
#pragma unroll
                for (int nf = 0; nf < 4; nf++)
                    mma16bf(acc[mf][nf], af[mf], bf[nf]);
        }

        {
            uint32_t* as = &As[buf ^ 1][r_ld][c_ld >> 1];
            uint32_t* bs = &Bs[buf ^ 1][r_ld][c_ld >> 1];
            as[0] = packbf(pa0.x, pa0.y); as[1] = packbf(pa0.z, pa0.w);
            bs[0] = packbf(pb0.x, pb0.y); bs[1] = packbf(pb0.z, pb0.w);
            uint32_t* as2 = &As[buf ^ 1][r_ld + 64][c_ld >> 1];
            uint32_t* bs2 = &Bs[buf ^ 1][r_ld + 64][c_ld >> 1];
            as2[0] = packbf(pa1.x, pa1.y); as2[1] = packbf(pa1.z, pa1.w);
            bs2[0] = packbf(pb1.x, pb1.y); bs2[1] = packbf(pb1.z, pb1.w);
        }
        __syncthreads();
        buf ^= 1;
    }

    {
        uint32_t af[4][4], bf[4][2];
#pragma unroll
        for (int mf = 0; mf < 4; mf++) {
            af[mf][0] = As[buf][wm + mf * 16 + g    ][t];
            af[mf][1] = As[buf][wm + mf * 16 + g + 8][t];
            af[mf][2] = As[buf][wm + mf * 16 + g    ][t + 4];
            af[mf][3] = As[buf][wm + mf * 16 + g + 8][t + 4];
        }
#pragma unroll
        for (int nf = 0; nf < 4; nf++) {
            bf[nf][0] = Bs[buf][wn + nf * 8 + g][t];
            bf[nf][1] = Bs[buf][wn + nf * 8 + g][t + 4];
        }
#pragma unroll
        for (int mf = 0; mf < 4; mf++)
#pragma unroll
            for (int nf = 0; nf < 4; nf++)
                mma16bf(acc[mf][nf], af[mf], bf[nf]);
    }

#pragma unroll
    for (int mf = 0; mf < 4; mf++) {
        int row = m0 + wm + mf * 16 + g;
#pragma unroll
        for (int nf = 0; nf < 4; nf++) {
            int col = n0 + wn + nf * 8 + 2 * t;
            float b0 = bias[col], b1 = bias[col + 1];
            float4 v = acc[mf][nf];
            float2 lo = make_float2(v.x + b0, v.y + b1);
            float2 hi = make_float2(v.z + b0, v.w + b1);
            if (relu) {
                lo.x = fmaxf(lo.x, 0.f); lo.y = fmaxf(lo.y, 0.f);
                hi.x = fmaxf(hi.x, 0.f); hi.y = fmaxf(hi.y, 0.f);
            }
            *(float2*)&C[(size_t)row * N + col]       = lo;
            *(float2*)&C[(size_t)(row + 8) * N + col] = hi;
        }
    }
}

// ------------------------- tensor-core flash attention -----------------------
// grid (8, 32), 256 thr = 8 warps; warp = 16 q-rows x 64 keys per tile.
// QK^T in tf32; P,V packed bf16, PV via m16n8k16. Smem 32.3KB.
__global__ __launch_bounds__(256) void flash_attn_mma(
    const float* __restrict__ qkproj, const float* __restrict__ vsrc,
    float* __restrict__ O)
{
    __shared__ uint32_t sm[8064];
    uint32_t* Ks = sm;              // [64][36] tf32
    uint32_t* Vs = sm + 2304;      // [32][36] bf16 pairs: Vs[d][kp]=pack(V[2kp][d],V[2kp+1][d])
    uint32_t* Ps = sm + 3456;      // [8][16][36] bf16 pairs per warp
    uint32_t* Qstage = sm;         // overlay [128][36] (used before loop only)

    const int bh = blockIdx.y, b = bh >> 3, h = bh & 7;
    const int q0 = blockIdx.x * 128;
    const int tid = threadIdx.x, warp = tid >> 5, lane = tid & 31;
    const int g = lane >> 2, t = lane & 3;
    const float SC = 0.1767766952966368932f;

    const float* qp = qkproj + (size_t)b * LQd * 512 + h * DHd;
    const float* kp = qp + 256;
    const float* vp = vsrc + (size_t)b * LQd * CCd + h * DHd;

#pragma unroll
    for (int i = 0; i < 16; i++) {
        int idx = tid + i * 256;
        int row = idx >> 5, d = idx & 31;
        Qstage[row * 36 + d] = f2tf32(qp[(size_t)(q0 + row) * 512 + d] * SC);
    }
    __syncthreads();
    uint32_t qf[4][4];
#pragma unroll
    for (int kc = 0; kc < 4; kc++) {
        int r = (warp * 16 + g) * 36;
        qf[kc][0] = Qstage[r + kc * 8 + t];
        qf[kc][1] = Qstage[r + 8 * 36 + kc * 8 + t];
        qf[kc][2] = Qstage[r + kc * 8 + t + 4];
        qf[kc][3] = Qstage[r + 8 * 36 + kc * 8 + t + 4];
    }

    uint32_t* Pw = Ps + warp * 16 * 36;
    float m0r = -1e30f, m1r = -1e30f, l0r = 0.f, l1r = 0.f;
    float4 oacc[4];
#pragma unroll
    for (int i = 0; i < 4; i++) oacc[i] = make_float4(0.f, 0.f, 0.f, 0.f);

    for (int kt = 0; kt < 16; kt++) {
        const float* kbase = kp + (size_t)kt * 64 * 512;
        const float* vbase = vp + (size_t)kt * 64 * 256;
        __syncthreads();
#pragma unroll
        for (int i = 0; i < 8; i++) {
            int idx = tid + i * 256;
            int key = idx >> 5, d = idx & 31;
            Ks[key * 36 + d] = f2tf32(kbase[(size_t)key * 512 + d]);
        }
#pragma unroll
        for (int i = 0; i < 4; i++) {
            int idx = tid + i * 256;
            int kpair = idx >> 5, d = idx & 31;
            float v0 = vbase[(size_t)(2 * kpair) * 256 + d];
            float v1 = vbase[(size_t)(2 * kpair + 1) * 256 + d];
            Vs[d * 36 + kpair] = packbf(v0, v1);
        }
        __syncthreads();

        // S = Q K^T (16x64 per warp)
        float4 sacc[8];
#pragma unroll
        for (int nf = 0; nf < 8; nf++) sacc[nf] = make_float4(0.f, 0.f, 0.f, 0.f);
#pragma unroll
        for (int nf = 0; nf < 8; nf++) {
#pragma unroll
            for (int kc = 0; kc < 4; kc++) {
                uint32_t bfr[2];
                bfr[0] = Ks[(nf * 8 + g) * 36 + kc * 8 + t];
                bfr[1] = Ks[(nf * 8 + g) * 36 + kc * 8 + t + 4];
                mma8(sacc[nf], qf[kc], bfr);
            }
        }

        // online softmax (rows g and g+8)
        float mx0 = -1e30f, mx1 = -1e30f;
#pragma unroll
        for (int nf = 0; nf < 8; nf++) {
            mx0 = fmaxf(mx0, fmaxf(sacc[nf].x, sacc[nf].y));
            mx1 = fmaxf(mx1, fmaxf(sacc[nf].z, sacc[nf].w));
        }
        mx0 = fmaxf(mx0, __shfl_xor_sync(0xffffffffu, mx0, 1));
        mx0 = fmaxf(mx0, __shfl_xor_sync(0xffffffffu, mx0, 2));
        mx1 = fmaxf(mx1, __shfl_xor_sync(0xffffffffu, mx1, 1));
        mx1 = fmaxf(mx1, __shfl_xor_sync(0xffffffffu, mx1, 2));
        float mn0 = fmaxf(m0r, mx0), mn1 = fmaxf(m1r, mx1);
        float cf0 = __expf(m0r - mn0), cf1 = __expf(m1r - mn1);
        float rs0 = 0.f, rs1 = 0.f;
#pragma unroll
        for (int nf = 0; nf < 8; nf++) {
            float p0 = __expf(sacc[nf].x - mn0);
            float p1 = __expf(sacc[nf].y - mn0);
            float p2 = __expf(sacc[nf].z - mn1);
            float p3 = __expf(sacc[nf].w - mn1);
            rs0 += p0 + p1; rs1 += p2 + p3;
            Pw[(g    ) * 36 + nf * 4 + t] = packbf(p0, p1);
            Pw[(g + 8) * 36 + nf * 4 + t] = packbf(p2, p3);
        }
        rs0 += __shfl_xor_sync(0xffffffffu, rs0, 1);
        rs0 += __shfl_xor_sync(0xffffffffu, rs0, 2);
        rs1 += __shfl_xor_sync(0xffffffffu, rs1, 1);
        rs1 += __shfl_xor_sync(0xffffffffu, rs1, 2);
        l0r = l0r * cf0 + rs0; l1r = l1r * cf1 + rs1;
        m0r = mn0; m1r = mn1;
#pragma unroll
        for (int nf = 0; nf < 4; nf++) {
            oacc[nf].x *= cf0; oacc[nf].y *= cf0;
            oacc[nf].z *= cf1; oacc[nf].w *= cf1;
        }
        __syncwarp();

        // O += P V : m16n8k16 bf16, 4 key-chunks of 16 (8 pairs)
#pragma unroll
        for (int kc = 0; kc < 4; kc++) {
            uint32_t af[4];
            af[0] = Pw[(g    ) * 36 + kc * 8 + t];
            af[1] = Pw[(g + 8) * 36 + kc * 8 + t];
            af[2] = Pw[(g    ) * 36 + kc * 8 + t + 4];
            af[3] = Pw[(g + 8) * 36 + kc * 8 + t + 4];
#pragma unroll
            for (int nf = 0; nf < 4; nf++) {
                uint32_t bfr[2];
                bfr[0] = Vs[(nf * 8 + g) * 36 + kc * 8 + t];
                bfr[1] = Vs[(nf * 8 + g) * 36 + kc * 8 + t + 4];
                mma16bf(oacc[nf], af, bfr);
            }
        }
    }

    float inv0 = 1.f / l0r, inv1 = 1.f / l1r;
    int row = q0 + warp * 16 + g;
#pragma unroll
    for (int nf = 0; nf < 4; nf++) {
        int col = h * DHd + nf * 8 + 2 * t;
        *(float2*)&O[(size_t)(b * LQd + row) * CCd + col] =
            make_float2(oacc[nf].x * inv0, oacc[nf].y * inv0);
        *(float2*)&O[(size_t)(b * LQd + row + 8) * CCd + col] =
            make_float2(oacc[nf].z * inv1, oacc[nf].w * inv1);
    }
}

// ------------------------- fused residual + LayerNorm ------------------------
__global__ void add_ln(const float* __restrict__ a, const float* __restrict__ b,
                       const float* __restrict__ g, const float* __restrict__ bet,
                       float* __restrict__ out)
{
    __shared__ float sh[256];
    int row = blockIdx.x, t = threadIdx.x;
    size_t idx = (size_t)row * CCd + t;
    float v = a[idx] + b[idx];
    sh[t] = v; __syncthreads();
    for (int s = 128; s > 0; s >>= 1) { if (t < s) sh[t] += sh[t + s]; __syncthreads(); }
    float mean = sh[0] * (1.f / 256.f);
    __syncthreads();
    float d = v - mean;
    sh[t] = d * d; __syncthreads();
    for (int s = 128; s > 0; s >>= 1) { if (t < s) sh[t] += sh[t + s]; __syncthreads(); }
    float var = sh[0] * (1.f / 256.f);
    out[idx] = d * rsqrtf(var + 1e-5f) * g[t] + bet[t];
}

// ------------------------- attention-weight softmax over L*P=16 --------------
__global__ void aw_softmax(float* __restrict__ a)
{
    int gi = blockIdx.x * blockDim.x + threadIdx.x;
    if (gi >= BQd * HHd) return;
    int bq = gi >> 3, h = gi & 7;
    float* p = a + (size_t)bq * 384 + 256 + h * 16;
    float x[16];
    float m = -1e30f;
#pragma unroll
    for (int i = 0; i < 16; i++) { x[i] = p[i]; m = fmaxf(m, x[i]); }
    float s = 0.f;
#pragma unroll
    for (int i = 0; i < 16; i++) { x[i] = __expf(x[i] - m); s += x[i]; }
    float inv = 1.f / s;
#pragma unroll
    for (int i = 0; i < 16; i++) p[i] = x[i] * inv;
}

// ------------------------- multi-scale deformable sampling -------------------
__global__ void deform_sample(const float* __restrict__ value, const float* __restrict__ ref,
                              const float* __restrict__ offaw, float* __restrict__ out)
{
    const int levH[4] = {128, 64, 32, 16};
    const int levW[4] = {128, 64, 32, 16};
    const int levS[4] = {0, 16384, 20480, 21504};
    int bq = blockIdx.x;
    int b  = bq >> 10;
    int h  = threadIdx.x >> 5;
    int d  = threadIdx.x & 31;
    float acc = 0.f;
#pragma unroll
    for (int l = 0; l < 4; l++) {
        float rx = ref[((size_t)bq * LLd + l) * 2 + 0];
        float ry = ref[((size_t)bq * LLd + l) * 2 + 1];
        int w = levW[l], hh = levH[l], st = levS[l];
        float fw = (float)w, fh = (float)hh;
#pragma unroll
        for (int p = 0; p < 4; p++) {
            size_t oidx = (size_t)bq * 384 + h * 32 + (l * 4 + p) * 2;
            float lx = rx + offaw[oidx]     / fw;
            float ly = ry + offaw[oidx + 1] / fh;
            float x = lx * fw - 0.5f;
            float y = ly * fh - 0.5f;
            float x0f = floorf(x), y0f = floorf(y);
            int x0 = (int)x0f, y0 = (int)y0f;
            float wx1 = x - x0f, wx0 = 1.f - wx1;
            float wy1 = y - y0f, wy0 = 1.f - wy1;
            float a = offaw[(size_t)bq * 384 + 256 + h * 16 + l * 4 + p];
            float s = 0.f;
#pragma unroll
            for (int cy = 0; cy < 2; cy++) {
#pragma unroll
                for (int cx = 0; cx < 2; cx++) {
                    int ix = x0 + cx, iy = y0 + cy;
                    if (ix >= 0 && ix < w && iy >= 0 && iy < hh) {
                        float wgt = (cx ? wx1 : wx0) * (cy ? wy1 : wy0);
                        size_t vidx = (((size_t)(b * LSRCd + st + iy * w + ix)) * HHd + h) * DHd + d;
                        s += wgt * value[vidx];
                    }
                }
            }
            acc += a * s;
        }
    }
    out[(size_t)bq * CCd + h * DHd + d] = acc;
}

// ------------------------- launch --------------------------------------------
extern "C" void kernel_launch(void* const* d_in, const int* in_sizes, int n_in,
                              void* d_out, int out_size)
{
    (void)in_sizes; (void)n_in; (void)out_size;
    const float* tgt   = (const float*)d_in[0];
    const float* qpos  = (const float*)d_in[1];
    const float* ref   = (const float*)d_in[2];
    const float* src   = (const float*)d_in[3];
    const float* in_w  = (const float*)d_in[4];
    const float* in_b  = (const float*)d_in[5];
    const float* sa_w  = (const float*)d_in[6];
    const float* sa_b  = (const float*)d_in[7];
    const float* off_w = (const float*)d_in[8];
    const float* off_b = (const float*)d_in[9];
    const float* aw_w  = (const float*)d_in[10];
    const float* aw_b  = (const float*)d_in[11];
    const float* val_w = (const float*)d_in[12];
    const float* val_b = (const float*)d_in[13];
    const float* co_w  = (const float*)d_in[14];
    const float* co_b  = (const float*)d_in[15];
    const float* ln1_g = (const float*)d_in[16];
    const float* ln1_b = (const float*)d_in[17];
    const float* ln2_g = (const float*)d_in[18];
    const float* ln2_b = (const float*)d_in[19];
    const float* ln3_g = (const float*)d_in[20];
    const float* ln3_b = (const float*)d_in[21];
    const float* f1_w  = (const float*)d_in[22];
    const float* f1_b  = (const float*)d_in[23];
    const float* f2_w  = (const float*)d_in[24];
    const float* f2_b  = (const float*)d_in[25];
    float* out = (float*)d_out;

    float *qkproj, *v, *o, *t2, *tgt1, *value, *offaw, *woffaw, *boffaw, *samp, *tgt2, *ffn;
    cudaGetSymbolAddress((void**)&qkproj, g_qkproj);
    cudaGetSymbolAddress((void**)&v,      g_v);
    cudaGetSymbolAddress((void**)&o,      g_o);
    cudaGetSymbolAddress((void**)&t2,     g_t2);
    cudaGetSymbolAddress((void**)&tgt1,   g_tgt1);
    cudaGetSymbolAddress((void**)&value,  g_value);
    cudaGetSymbolAddress((void**)&offaw,  g_offaw);
    cudaGetSymbolAddress((void**)&woffaw, g_woffaw);
    cudaGetSymbolAddress((void**)&boffaw, g_boffaw);
    cudaGetSymbolAddress((void**)&samp,   g_samp);
    cudaGetSymbolAddress((void**)&tgt2,   g_tgt2);
    cudaGetSymbolAddress((void**)&ffn,    g_ffn);

    // fuse off/aw weights into one (384,256) matrix + (384,) bias
    cudaMemcpyAsync(woffaw,             off_w, 256 * 256 * sizeof(float), cudaMemcpyDeviceToDevice);
    cudaMemcpyAsync(woffaw + 256 * 256, aw_w,  128 * 256 * sizeof(float), cudaMemcpyDeviceToDevice);
    cudaMemcpyAsync(boffaw,             off_b, 256 * sizeof(float),       cudaMemcpyDeviceToDevice);
    cudaMemcpyAsync(boffaw + 256,       aw_b,  128 * sizeof(float),       cudaMemcpyDeviceToDevice);

    // ---- self-attention ----
    gemm_tf32_64<<<dim3(8, 64), 128>>>(tgt, qpos, in_w, in_b, qkproj, BQd, 512, CCd, 0);
    gemm_tf32_64<<<dim3(4, 64), 128>>>(tgt, nullptr, in_w + 2 * CCd * CCd, in_b + 2 * CCd, v, BQd, CCd, CCd, 0);
    flash_attn_mma<<<dim3(8, 32), 256>>>(qkproj, v, o);
    gemm_tf32_64<<<dim3(4, 64), 128>>>(o, nullptr, sa_w, sa_b, t2, BQd, CCd, CCd, 0);
    add_ln<<<BQd, 256>>>(tgt, t2, ln2_g, ln2_b, tgt1);

    // ---- deformable cross-attention ----
    gemm_bf16<<<dim3(2, 680), 256>>>(src, val_w, val_b, value, BB * LSRCd, CCd, CCd, 0);
    gemm_tf32_64<<<dim3(6, 64), 128>>>(tgt1, qpos, woffaw, boffaw, offaw, BQd, 384, CCd, 0);
    aw_softmax<<<(BQd * HHd + 255) / 256, 256>>>(offaw);
    deform_sample<<<BQd, 256>>>(value, ref, offaw, samp);
    gemm_tf32_64<<<dim3(4, 64), 128>>>(samp, nullptr, co_w, co_b, t2, BQd, CCd, CCd, 0);
    add_ln<<<BQd, 256>>>(tgt1, t2, ln1_g, ln1_b, tgt2);

    // ---- FFN ----
    gemm_bf16<<<dim3(8, 32), 256>>>(tgt2, f1_w, f1_b, ffn, BQd, DFFd, CCd, 1);
    gemm_tf32_64<<<dim3(4, 64), 128>>>(ffn, nullptr, f2_w, f2_b, t2, BQd, CCd, DFFd, 0);
    add_ln<<<BQd, 256>>>(tgt2, t2, ln3_g, ln3_b, out);
}

// round 10
// speedup vs baseline: 1.4248x; 1.0700x over previous
#include <cuda_runtime.h>
#include <cuda_bf16.h>
#include <math.h>
#include <stdint.h>

#define BB   4
#define LQd  1024
#define CCd  256
#define HHd  8
#define DHd  32
#define LLd  4
#define PPd  4
#define DFFd 1024
#define LSRCd 21760
#define BQd  (BB*LQd)   // 4096

// ------------------------- scratch (device globals; no allocs) ---------------
__device__ float g_qkproj[BQd*512];
__device__ float g_v     [BQd*CCd];
__device__ float g_o     [BQd*CCd];
__device__ float g_t2    [BQd*CCd];
__device__ float g_tgt1  [BQd*CCd];
__device__ float g_value [(size_t)BB*LSRCd*CCd];
__device__ float g_offaw [BQd*384];
__device__ float g_woffaw[384*CCd];
__device__ float g_boffaw[384];
__device__ float g_samp  [BQd*CCd];
__device__ float g_tgt2  [BQd*CCd];
__device__ float g_ffn   [BQd*DFFd];

// ------------------------- mma helpers ---------------------------------------
__device__ __forceinline__ uint32_t f2tf32(float x) {
    uint32_t r;
    asm("cvt.rna.tf32.f32 %0, %1;" : "=r"(r) : "f"(x));
    return r;
}

__device__ __forceinline__ void mma8(float4& d, const uint32_t* a, const uint32_t* b) {
    asm volatile("mma.sync.aligned.m16n8k8.row.col.f32.tf32.tf32.f32 "
                 "{%0,%1,%2,%3}, {%4,%5,%6,%7}, {%8,%9}, {%0,%1,%2,%3};"
                 : "+f"(d.x), "+f"(d.y), "+f"(d.z), "+f"(d.w)
                 : "r"(a[0]), "r"(a[1]), "r"(a[2]), "r"(a[3]),
                   "r"(b[0]), "r"(b[1]));
}

__device__ __forceinline__ void mma16bf(float4& d, const uint32_t* a, const uint32_t* b) {
    asm volatile("mma.sync.aligned.m16n8k16.row.col.f32.bf16.bf16.f32 "
                 "{%0,%1,%2,%3}, {%4,%5,%6,%7}, {%8,%9}, {%0,%1,%2,%3};"
                 : "+f"(d.x), "+f"(d.y), "+f"(d.z), "+f"(d.w)
                 : "r"(a[0]), "r"(a[1]), "r"(a[2]), "r"(a[3]),
                   "r"(b[0]), "r"(b[1]));
}

__device__ __forceinline__ uint32_t packbf(float x, float y) {
    __nv_bfloat162 h = __floats2bfloat162_rn(x, y);
    return *reinterpret_cast<uint32_t*>(&h);
}

// ------------------------- TF32 GEMM, 64x64 tile, 128 threads ----------------
#define TSTR 20

__global__ __launch_bounds__(128) void gemm_tf32_64(
    const float* __restrict__ A, const float* __restrict__ A2,
    const float* __restrict__ W,
    const float* __restrict__ bias, float* __restrict__ C,
    int M, int N, int K, int relu)
{
    __shared__ uint32_t As[2][64][TSTR];
    __shared__ uint32_t Bs[2][64][TSTR];
    const int tid  = threadIdx.x;
    const int warp = tid >> 5, lane = tid & 31;
    const int g = lane >> 2, t = lane & 3;
    const int wm = (warp >> 1) * 32, wn = (warp & 1) * 32;
    const int m0 = blockIdx.y * 64, n0 = blockIdx.x * 64;
    const int r_ld = tid >> 2, c_ld = (tid & 3) * 4;

    const float* Ap  = A + (size_t)(m0 + r_ld) * K + c_ld;
    const float* Ap2 = A2 ? A2 + (size_t)(m0 + r_ld) * K + c_ld : nullptr;
    const float* Wp  = W + (size_t)(n0 + r_ld) * K + c_ld;

    float4 acc[2][4];
#pragma unroll
    for (int i = 0; i < 2; i++)
#pragma unroll
        for (int j = 0; j < 4; j++) acc[i][j] = make_float4(0.f, 0.f, 0.f, 0.f);

#pragma unroll
    for (int i = 0; i < 2; i++) {
        float4 a = *(const float4*)(Ap + (size_t)(32 * i) * K);
        if (Ap2) {
            float4 a2 = *(const float4*)(Ap2 + (size_t)(32 * i) * K);
            a.x += a2.x; a.y += a2.y; a.z += a2.z; a.w += a2.w;
        }
        float4 b = *(const float4*)(Wp + (size_t)(32 * i) * K);
        uint32_t* as = &As[0][r_ld + 32 * i][c_ld];
        uint32_t* bs = &Bs[0][r_ld + 32 * i][c_ld];
        as[0] = f2tf32(a.x); as[1] = f2tf32(a.y); as[2] = f2tf32(a.z); as[3] = f2tf32(a.w);
        bs[0] = f2tf32(b.x); bs[1] = f2tf32(b.y); bs[2] = f2tf32(b.z); bs[3] = f2tf32(b.w);
    }
    __syncthreads();

    int buf = 0;
    for (int k0 = 16; k0 < K; k0 += 16) {
        float4 pa0 = *(const float4*)(Ap + k0);
        float4 pa1 = *(const float4*)(Ap + (size_t)32 * K + k0);
        if (Ap2) {
            float4 q0v = *(const float4*)(Ap2 + k0);
            float4 q1v = *(const float4*)(Ap2 + (size_t)32 * K + k0);
            pa0.x += q0v.x; pa0.y += q0v.y; pa0.z += q0v.z; pa0.w += q0v.w;
            pa1.x += q1v.x; pa1.y += q1v.y; pa1.z += q1v.z; pa1.w += q1v.w;
        }
        float4 pb0 = *(const float4*)(Wp + k0);
        float4 pb1 = *(const float4*)(Wp + (size_t)32 * K + k0);

#pragma unroll
        for (int ks = 0; ks < 2; ks++) {
            const int kk = ks * 8;
            uint32_t af[2][4], bf[4][2];
#pragma unroll
            for (int mf = 0; mf < 2; mf++) {
                af[mf][0] = As[buf][wm + mf * 16 + g    ][kk + t];
                af[mf][1] = As[buf][wm + mf * 16 + g + 8][kk + t];
                af[mf][2] = As[buf][wm + mf * 16 + g    ][kk + t + 4];
                af[mf][3] = As[buf][wm + mf * 16 + g + 8][kk + t + 4];
            }
#pragma unroll
            for (int nf = 0; nf < 4; nf++) {
                bf[nf][0] = Bs[buf][wn + nf * 8 + g][kk + t];
                bf[nf][1] = Bs[buf][wn + nf * 8 + g][kk + t + 4];
            }
#pragma unroll
            for (int mf = 0; mf < 2; mf++)
#pragma unroll
                for (int nf = 0; nf < 4; nf++)
                    mma8(acc[mf][nf], af[mf], bf[nf]);
        }

        {
            uint32_t* as = &As[buf ^ 1][r_ld][c_ld];
            uint32_t* bs = &Bs[buf ^ 1][r_ld][c_ld];
            as[0] = f2tf32(pa0.x); as[1] = f2tf32(pa0.y); as[2] = f2tf32(pa0.z); as[3] = f2tf32(pa0.w);
            bs[0] = f2tf32(pb0.x); bs[1] = f2tf32(pb0.y); bs[2] = f2tf32(pb0.z); bs[3] = f2tf32(pb0.w);
            uint32_t* as2 = &As[buf ^ 1][r_ld + 32][c_ld];
            uint32_t* bs2 = &Bs[buf ^ 1][r_ld + 32][c_ld];
            as2[0] = f2tf32(pa1.x); as2[1] = f2tf32(pa1.y); as2[2] = f2tf32(pa1.z); as2[3] = f2tf32(pa1.w);
            bs2[0] = f2tf32(pb1.x); bs2[1] = f2tf32(pb1.y); bs2[2] = f2tf32(pb1.z); bs2[3] = f2tf32(pb1.w);
        }
        __syncthreads();
        buf ^= 1;
    }

#pragma unroll
    for (int ks = 0; ks < 2; ks++) {
        const int kk = ks * 8;
        uint32_t af[2][4], bf[4][2];
#pragma unroll
        for (int mf = 0; mf < 2; mf++) {
            af[mf][0] = As[buf][wm + mf * 16 + g    ][kk + t];
            af[mf][1] = As[buf][wm + mf * 16 + g + 8][kk + t];
            af[mf][2] = As[buf][wm + mf * 16 + g    ][kk + t + 4];
            af[mf][3] = As[buf][wm + mf * 16 + g + 8][kk + t + 4];
        }
#pragma unroll
        for (int nf = 0; nf < 4; nf++) {
            bf[nf][0] = Bs[buf][wn + nf * 8 + g][kk + t];
            bf[nf][1] = Bs[buf][wn + nf * 8 + g][kk + t + 4];
        }
#pragma unroll
        for (int mf = 0; mf < 2; mf++)
#pragma unroll
            for (int nf = 0; nf < 4; nf++)
                mma8(acc[mf][nf], af[mf], bf[nf]);
    }

#pragma unroll
    for (int mf = 0; mf < 2; mf++) {
        int row = m0 + wm + mf * 16 + g;
#pragma unroll
        for (int nf = 0; nf < 4; nf++) {
            int col = n0 + wn + nf * 8 + 2 * t;
            float b0 = bias[col], b1 = bias[col + 1];
            float4 v = acc[mf][nf];
            float2 lo = make_float2(v.x + b0, v.y + b1);
            float2 hi = make_float2(v.z + b0, v.w + b1);
            if (relu) {
                lo.x = fmaxf(lo.x, 0.f); lo.y = fmaxf(lo.y, 0.f);
                hi.x = fmaxf(hi.x, 0.f); hi.y = fmaxf(hi.y, 0.f);
            }
            *(float2*)&C[(size_t)row * N + col]       = lo;
            *(float2*)&C[(size_t)(row + 8) * N + col] = hi;
        }
    }
}

// ------------------------- BF16 tensor-core GEMM (128x128) -------------------
__global__ __launch_bounds__(256) void gemm_bf16(
    const float* __restrict__ A, const float* __restrict__ W,
    const float* __restrict__ bias, float* __restrict__ C,
    int M, int N, int K, int relu)
{
    __shared__ uint32_t As[2][128][12];
    __shared__ uint32_t Bs[2][128][12];
    const int tid  = threadIdx.x;
    const int warp = tid >> 5, lane = tid & 31;
    const int g = lane >> 2, t = lane & 3;
    const int wm = (warp >> 2) * 64, wn = (warp & 3) * 32;
    const int m0 = blockIdx.y * 128, n0 = blockIdx.x * 128;
    const int r_ld = tid >> 2, c_ld = (tid & 3) * 4;

    const float* Ap = A + (size_t)(m0 + r_ld) * K + c_ld;
    const float* Wp = W + (size_t)(n0 + r_ld) * K + c_ld;

    float4 acc[4][4];
#pragma unroll
    for (int i = 0; i < 4; i++)
#pragma unroll
        for (int j = 0; j < 4; j++) acc[i][j] = make_float4(0.f, 0.f, 0.f, 0.f);

#pragma unroll
    for (int i = 0; i < 2; i++) {
        float4 a = *(const float4*)(Ap + (size_t)(64 * i) * K);
        float4 b = *(const float4*)(Wp + (size_t)(64 * i) * K);
        uint32_t* as = &As[0][r_ld + 64 * i][c_ld >> 1];
        uint32_t* bs = &Bs[0][r_ld + 64 * i][c_ld >> 1];
        as[0] = packbf(a.x, a.y); as[1] = packbf(a.z, a.w);
        bs[0] = packbf(b.x, b.y); bs[1] = packbf(b.z, b.w);
    }
    __syncthreads();

    int buf = 0;
    for (int k0 = 16; k0 < K; k0 += 16) {
        float4 pa0 = *(const float4*)(Ap + k0);
        float4 pa1 = *(const float4*)(Ap + (size_t)64 * K + k0);
        float4 pb0 = *(const float4*)(Wp + k0);
        float4 pb1 = *(const float4*)(Wp + (size_t)64 * K + k0);

        {
            uint32_t af[4][4], bf[4][2];
#pragma unroll
            for (int mf = 0; mf < 4; mf++) {
                af[mf][0] = As[buf][wm + mf * 16 + g    ][t];
                af[mf][1] = As[buf][wm + mf * 16 + g + 8][t];
                af[mf][2] = As[buf][wm + mf * 16 + g    ][t + 4];
                af[mf][3] = As[buf][wm + mf * 16 + g + 8][t + 4];
            }
#pragma unroll
            for (int nf = 0; nf < 4; nf++) {
                bf[nf][0] = Bs[buf][wn + nf * 8 + g][t];
                bf[nf][1] = Bs[buf][wn + nf * 8 + g][t + 4];
            }
#pragma unroll
            for (int mf = 0; mf < 4; mf++)
#pragma unroll
                for (int nf = 0; nf < 4; nf++)
                    mma16bf(acc[mf][nf], af[mf], bf[nf]);
        }

        {
            uint32_t* as = &As[buf ^ 1][r_ld][c_ld >> 1];
            uint32_t* bs = &Bs[buf ^ 1][r_ld][c_ld >> 1];
            as[0] = packbf(pa0.x, pa0.y); as[1] = packbf(pa0.z, pa0.w);
            bs[0] = packbf(pb0.x, pb0.y); bs[1] = packbf(pb0.z, pb0.w);
            uint32_t* as2 = &As[buf ^ 1][r_ld + 64][c_ld >> 1];
            uint32_t* bs2 = &Bs[buf ^ 1][r_ld + 64][c_ld >> 1];
            as2[0] = packbf(pa1.x, pa1.y); as2[1] = packbf(pa1.z, pa1.w);
            bs2[0] = packbf(pb1.x, pb1.y); bs2[1] = packbf(pb1.z, pb1.w);
        }
        __syncthreads();
        buf ^= 1;
    }

    {
        uint32_t af[4][4], bf[4][2];
#pragma unroll
        for (int mf = 0; mf < 4; mf++) {
            af[mf][0] = As[buf][wm + mf * 16 + g    ][t];
            af[mf][1] = As[buf][wm + mf * 16 + g + 8][t];
            af[mf][2] = As[buf][wm + mf * 16 + g    ][t + 4];
            af[mf][3] = As[buf][wm + mf * 16 + g + 8][t + 4];
        }
#pragma unroll
        for (int nf = 0; nf < 4; nf++) {
            bf[nf][0] = Bs[buf][wn + nf * 8 + g][t];
            bf[nf][1] = Bs[buf][wn + nf * 8 + g][t + 4];
        }
#pragma unroll
        for (int mf = 0; mf < 4; mf++)
#pragma unroll
            for (int nf = 0; nf < 4; nf++)
                mma16bf(acc[mf][nf], af[mf], bf[nf]);
    }

#pragma unroll
    for (int mf = 0; mf < 4; mf++) {
        int row = m0 + wm + mf * 16 + g;
#pragma unroll
        for (int nf = 0; nf < 4; nf++) {
            int col = n0 + wn + nf * 8 + 2 * t;
            float b0 = bias[col], b1 = bias[col + 1];
            float4 v = acc[mf][nf];
            float2 lo = make_float2(v.x + b0, v.y + b1);
            float2 hi = make_float2(v.z + b0, v.w + b1);
            if (relu) {
                lo.x = fmaxf(lo.x, 0.f); lo.y = fmaxf(lo.y, 0.f);
                hi.x = fmaxf(hi.x, 0.f); hi.y = fmaxf(hi.y, 0.f);
            }
            *(float2*)&C[(size_t)row * N + col]       = lo;
            *(float2*)&C[(size_t)(row + 8) * N + col] = hi;
        }
    }
}

// ------------------------- tensor-core flash attention -----------------------
__global__ __launch_bounds__(256) void flash_attn_mma(
    const float* __restrict__ qkproj, const float* __restrict__ vsrc,
    float* __restrict__ O)
{
    __shared__ uint32_t sm[8064];
    uint32_t* Ks = sm;
    uint32_t* Vs = sm + 2304;
    uint32_t* Ps = sm + 3456;
    uint32_t* Qstage = sm;

    const int bh = blockIdx.y, b = bh >> 3, h = bh & 7;
    const int q0 = blockIdx.x * 128;
    const int tid = threadIdx.x, warp = tid >> 5, lane = tid & 31;
    const int g = lane >> 2, t = lane & 3;
    const float SC = 0.1767766952966368932f;

    const float* qp = qkproj + (size_t)b * LQd * 512 + h * DHd;
    const float* kp = qp + 256;
    const float* vp = vsrc + (size_t)b * LQd * CCd + h * DHd;

#pragma unroll
    for (int i = 0; i < 16; i++) {
        int idx = tid + i * 256;
        int row = idx >> 5, d = idx & 31;
        Qstage[row * 36 + d] = f2tf32(qp[(size_t)(q0 + row) * 512 + d] * SC);
    }
    __syncthreads();
    uint32_t qf[4][4];
#pragma unroll
    for (int kc = 0; kc < 4; kc++) {
        int r = (warp * 16 + g) * 36;
        qf[kc][0] = Qstage[r + kc * 8 + t];
        qf[kc][1] = Qstage[r + 8 * 36 + kc * 8 + t];
        qf[kc][2] = Qstage[r + kc * 8 + t + 4];
        qf[kc][3] = Qstage[r + 8 * 36 + kc * 8 + t + 4];
    }

    uint32_t* Pw = Ps + warp * 16 * 36;
    float m0r = -1e30f, m1r = -1e30f, l0r = 0.f, l1r = 0.f;
    float4 oacc[4];
#pragma unroll
    for (int i = 0; i < 4; i++) oacc[i] = make_float4(0.f, 0.f, 0.f, 0.f);

    for (int kt = 0; kt < 16; kt++) {
        const float* kbase = kp + (size_t)kt * 64 * 512;
        const float* vbase = vp + (size_t)kt * 64 * 256;
        __syncthreads();
#pragma unroll
        for (int i = 0; i < 8; i++) {
            int idx = tid + i * 256;
            int key = idx >> 5, d = idx & 31;
            Ks[key * 36 + d] = f2tf32(kbase[(size_t)key * 512 + d]);
        }
#pragma unroll
        for (int i = 0; i < 4; i++) {
            int idx = tid + i * 256;
            int kpair = idx >> 5, d = idx & 31;
            float v0 = vbase[(size_t)(2 * kpair) * 256 + d];
            float v1 = vbase[(size_t)(2 * kpair + 1) * 256 + d];
            Vs[d * 36 + kpair] = packbf(v0, v1);
        }
        __syncthreads();

        float4 sacc[8];
#pragma unroll
        for (int nf = 0; nf < 8; nf++) sacc[nf] = make_float4(0.f, 0.f, 0.f, 0.f);
#pragma unroll
        for (int nf = 0; nf < 8; nf++) {
#pragma unroll
            for (int kc = 0; kc < 4; kc++) {
                uint32_t bfr[2];
                bfr[0] = Ks[(nf * 8 + g) * 36 + kc * 8 + t];
                bfr[1] = Ks[(nf * 8 + g) * 36 + kc * 8 + t + 4];
                mma8(sacc[nf], qf[kc], bfr);
            }
        }

        float mx0 = -1e30f, mx1 = -1e30f;
#pragma unroll
        for (int nf = 0; nf < 8; nf++) {
            mx0 = fmaxf(mx0, fmaxf(sacc[nf].x, sacc[nf].y));
            mx1 = fmaxf(mx1, fmaxf(sacc[nf].z, sacc[nf].w));
        }
        mx0 = fmaxf(mx0, __shfl_xor_sync(0xffffffffu, mx0, 1));
        mx0 = fmaxf(mx0, __shfl_xor_sync(0xffffffffu, mx0, 2));
        mx1 = fmaxf(mx1, __shfl_xor_sync(0xffffffffu, mx1, 1));
        mx1 = fmaxf(mx1, __shfl_xor_sync(0xffffffffu, mx1, 2));
        float mn0 = fmaxf(m0r, mx0), mn1 = fmaxf(m1r, mx1);
        float cf0 = __expf(m0r - mn0), cf1 = __expf(m1r - mn1);
        float rs0 = 0.f, rs1 = 0.f;
#pragma unroll
        for (int nf = 0; nf < 8; nf++) {
            float p0 = __expf(sacc[nf].x - mn0);
            float p1 = __expf(sacc[nf].y - mn0);
            float p2 = __expf(sacc[nf].z - mn1);
            float p3 = __expf(sacc[nf].w - mn1);
            rs0 += p0 + p1; rs1 += p2 + p3;
            Pw[(g    ) * 36 + nf * 4 + t] = packbf(p0, p1);
            Pw[(g + 8) * 36 + nf * 4 + t] = packbf(p2, p3);
        }
        rs0 += __shfl_xor_sync(0xffffffffu, rs0, 1);
        rs0 += __shfl_xor_sync(0xffffffffu, rs0, 2);
        rs1 += __shfl_xor_sync(0xffffffffu, rs1, 1);
        rs1 += __shfl_xor_sync(0xffffffffu, rs1, 2);
        l0r = l0r * cf0 + rs0; l1r = l1r * cf1 + rs1;
        m0r = mn0; m1r = mn1;
#pragma unroll
        for (int nf = 0; nf < 4; nf++) {
            oacc[nf].x *= cf0; oacc[nf].y *= cf0;
            oacc[nf].z *= cf1; oacc[nf].w *= cf1;
        }
        __syncwarp();

#pragma unroll
        for (int kc = 0; kc < 4; kc++) {
            uint32_t af[4];
            af[0] = Pw[(g    ) * 36 + kc * 8 + t];
            af[1] = Pw[(g + 8) * 36 + kc * 8 + t];
            af[2] = Pw[(g    ) * 36 + kc * 8 + t + 4];
            af[3] = Pw[(g + 8) * 36 + kc * 8 + t + 4];
#pragma unroll
            for (int nf = 0; nf < 4; nf++) {
                uint32_t bfr[2];
                bfr[0] = Vs[(nf * 8 + g) * 36 + kc * 8 + t];
                bfr[1] = Vs[(nf * 8 + g) * 36 + kc * 8 + t + 4];
                mma16bf(oacc[nf], af, bfr);
            }
        }
    }

    float inv0 = 1.f / l0r, inv1 = 1.f / l1r;
    int row = q0 + warp * 16 + g;
#pragma unroll
    for (int nf = 0; nf < 4; nf++) {
        int col = h * DHd + nf * 8 + 2 * t;
        *(float2*)&O[(size_t)(b * LQd + row) * CCd + col] =
            make_float2(oacc[nf].x * inv0, oacc[nf].y * inv0);
        *(float2*)&O[(size_t)(b * LQd + row + 8) * CCd + col] =
            make_float2(oacc[nf].z * inv1, oacc[nf].w * inv1);
    }
}

// ------------------------- fused residual + LayerNorm ------------------------
__global__ void add_ln(const float* __restrict__ a, const float* __restrict__ b,
                       const float* __restrict__ g, const float* __restrict__ bet,
                       float* __restrict__ out)
{
    __shared__ float sh[256];
    int row = blockIdx.x, t = threadIdx.x;
    size_t idx = (size_t)row * CCd + t;
    float v = a[idx] + b[idx];
    sh[t] = v; __syncthreads();
    for (int s = 128; s > 0; s >>= 1) { if (t < s) sh[t] += sh[t + s]; __syncthreads(); }
    float mean = sh[0] * (1.f / 256.f);
    __syncthreads();
    float d = v - mean;
    sh[t] = d * d; __syncthreads();
    for (int s = 128; s > 0; s >>= 1) { if (t < s) sh[t] += sh[t + s]; __syncthreads(); }
    float var = sh[0] * (1.f / 256.f);
    out[idx] = d * rsqrtf(var + 1e-5f) * g[t] + bet[t];
}

// ------------------------- attention-weight softmax over L*P=16 --------------
__global__ void aw_softmax(float* __restrict__ a)
{
    int gi = blockIdx.x * blockDim.x + threadIdx.x;
    if (gi >= BQd * HHd) return;
    int bq = gi >> 3, h = gi & 7;
    float* p = a + (size_t)bq * 384 + 256 + h * 16;
    float x[16];
    float m = -1e30f;
#pragma unroll
    for (int i = 0; i < 16; i++) { x[i] = p[i]; m = fmaxf(m, x[i]); }
    float s = 0.f;
#pragma unroll
    for (int i = 0; i < 16; i++) { x[i] = __expf(x[i] - m); s += x[i]; }
    float inv = 1.f / s;
#pragma unroll
    for (int i = 0; i < 16; i++) p[i] = x[i] * inv;
}

// ------------------------- multi-scale deformable sampling -------------------
__global__ void deform_sample(const float* __restrict__ value, const float* __restrict__ ref,
                              const float* __restrict__ offaw, float* __restrict__ out)
{
    const int levH[4] = {128, 64, 32, 16};
    const int levW[4] = {128, 64, 32, 16};
    const int levS[4] = {0, 16384, 20480, 21504};
    int bq = blockIdx.x;
    int b  = bq >> 10;
    int h  = threadIdx.x >> 5;
    int d  = threadIdx.x & 31;
    float acc = 0.f;
#pragma unroll
    for (int l = 0; l < 4; l++) {
        float rx = ref[((size_t)bq * LLd + l) * 2 + 0];
        float ry = ref[((size_t)bq * LLd + l) * 2 + 1];
        int w = levW[l], hh = levH[l], st = levS[l];
        float fw = (float)w, fh = (float)hh;
#pragma unroll
        for (int p = 0; p < 4; p++) {
            size_t oidx = (size_t)bq * 384 + h * 32 + (l * 4 + p) * 2;
            float lx = rx + offaw[oidx]     / fw;
            float ly = ry + offaw[oidx + 1] / fh;
            float x = lx * fw - 0.5f;
            float y = ly * fh - 0.5f;
            float x0f = floorf(x), y0f = floorf(y);
            int x0 = (int)x0f, y0 = (int)y0f;
            float wx1 = x - x0f, wx0 = 1.f - wx1;
            float wy1 = y - y0f, wy0 = 1.f - wy1;
            float a = offaw[(size_t)bq * 384 + 256 + h * 16 + l * 4 + p];
            float s = 0.f;
#pragma unroll
            for (int cy = 0; cy < 2; cy++) {
#pragma unroll
                for (int cx = 0; cx < 2; cx++) {
                    int ix = x0 + cx, iy = y0 + cy;
                    if (ix >= 0 && ix < w && iy >= 0 && iy < hh) {
                        float wgt = (cx ? wx1 : wx0) * (cy ? wy1 : wy0);
                        size_t vidx = (((size_t)(b * LSRCd + st + iy * w + ix)) * HHd + h) * DHd + d;
                        s += wgt * value[vidx];
                    }
                }
            }
            acc += a * s;
        }
    }
    out[(size_t)bq * CCd + h * DHd + d] = acc;
}

// ------------------------- launch --------------------------------------------
extern "C" void kernel_launch(void* const* d_in, const int* in_sizes, int n_in,
                              void* d_out, int out_size)
{
    (void)in_sizes; (void)n_in; (void)out_size;
    const float* tgt   = (const float*)d_in[0];
    const float* qpos  = (const float*)d_in[1];
    const float* ref   = (const float*)d_in[2];
    const float* src   = (const float*)d_in[3];
    const float* in_w  = (const float*)d_in[4];
    const float* in_b  = (const float*)d_in[5];
    const float* sa_w  = (const float*)d_in[6];
    const float* sa_b  = (const float*)d_in[7];
    const float* off_w = (const float*)d_in[8];
    const float* off_b = (const float*)d_in[9];
    const float* aw_w  = (const float*)d_in[10];
    const float* aw_b  = (const float*)d_in[11];
    const float* val_w = (const float*)d_in[12];
    const float* val_b = (const float*)d_in[13];
    const float* co_w  = (const float*)d_in[14];
    const float* co_b  = (const float*)d_in[15];
    const float* ln1_g = (const float*)d_in[16];
    const float* ln1_b = (const float*)d_in[17];
    const float* ln2_g = (const float*)d_in[18];
    const float* ln2_b = (const float*)d_in[19];
    const float* ln3_g = (const float*)d_in[20];
    const float* ln3_b = (const float*)d_in[21];
    const float* f1_w  = (const float*)d_in[22];
    const float* f1_b  = (const float*)d_in[23];
    const float* f2_w  = (const float*)d_in[24];
    const float* f2_b  = (const float*)d_in[25];
    float* out = (float*)d_out;

    float *qkproj, *v, *o, *t2, *tgt1, *value, *offaw, *woffaw, *boffaw, *samp, *tgt2, *ffn;
    cudaGetSymbolAddress((void**)&qkproj, g_qkproj);
    cudaGetSymbolAddress((void**)&v,      g_v);
    cudaGetSymbolAddress((void**)&o,      g_o);
    cudaGetSymbolAddress((void**)&t2,     g_t2);
    cudaGetSymbolAddress((void**)&tgt1,   g_tgt1);
    cudaGetSymbolAddress((void**)&value,  g_value);
    cudaGetSymbolAddress((void**)&offaw,  g_offaw);
    cudaGetSymbolAddress((void**)&woffaw, g_woffaw);
    cudaGetSymbolAddress((void**)&boffaw, g_boffaw);
    cudaGetSymbolAddress((void**)&samp,   g_samp);
    cudaGetSymbolAddress((void**)&tgt2,   g_tgt2);
    cudaGetSymbolAddress((void**)&ffn,    g_ffn);

    // side streams + events for capture-legal fork/join (created once)
    static cudaStream_t sv = nullptr, sw = nullptr;
    static cudaEvent_t evRoot = nullptr, evV = nullptr, evVal = nullptr, evW = nullptr;
    if (!sv) {
        cudaStreamCreateWithFlags(&sv, cudaStreamNonBlocking);
        cudaStreamCreateWithFlags(&sw, cudaStreamNonBlocking);
        cudaEventCreateWithFlags(&evRoot, cudaEventDisableTiming);
        cudaEventCreateWithFlags(&evV,    cudaEventDisableTiming);
        cudaEventCreateWithFlags(&evVal,  cudaEventDisableTiming);
        cudaEventCreateWithFlags(&evW,    cudaEventDisableTiming);
    }

    // fork: root event on main stream
    cudaEventRecord(evRoot, 0);

    // stream sw: weight-concat memcpys, then the big value GEMM (hidden under self-attn)
    cudaStreamWaitEvent(sw, evRoot, 0);
    cudaMemcpyAsync(woffaw,             off_w, 256 * 256 * sizeof(float), cudaMemcpyDeviceToDevice, sw);
    cudaMemcpyAsync(woffaw + 256 * 256, aw_w,  128 * 256 * sizeof(float), cudaMemcpyDeviceToDevice, sw);
    cudaMemcpyAsync(boffaw,             off_b, 256 * sizeof(float),       cudaMemcpyDeviceToDevice, sw);
    cudaMemcpyAsync(boffaw + 256,       aw_b,  128 * sizeof(float),       cudaMemcpyDeviceToDevice, sw);
    cudaEventRecord(evW, sw);
    gemm_bf16<<<dim3(2, 680), 256, 0, sw>>>(src, val_w, val_b, value, BB * LSRCd, CCd, CCd, 0);
    cudaEventRecord(evVal, sw);

    // stream sv: V projection (overlaps qkproj)
    cudaStreamWaitEvent(sv, evRoot, 0);
    gemm_tf32_64<<<dim3(4, 64), 128, 0, sv>>>(tgt, nullptr, in_w + 2 * CCd * CCd, in_b + 2 * CCd, v, BQd, CCd, CCd, 0);
    cudaEventRecord(evV, sv);

    // ---- main stream: self-attention ----
    gemm_tf32_64<<<dim3(8, 64), 128>>>(tgt, qpos, in_w, in_b, qkproj, BQd, 512, CCd, 0);
    cudaStreamWaitEvent(0, evV, 0);
    flash_attn_mma<<<dim3(8, 32), 256>>>(qkproj, v, o);
    gemm_tf32_64<<<dim3(4, 64), 128>>>(o, nullptr, sa_w, sa_b, t2, BQd, CCd, CCd, 0);
    add_ln<<<BQd, 256>>>(tgt, t2, ln2_g, ln2_b, tgt1);

    // ---- deformable cross-attention ----
    cudaStreamWaitEvent(0, evW, 0);
    gemm_tf32_64<<<dim3(6, 64), 128>>>(tgt1, qpos, woffaw, boffaw, offaw, BQd, 384, CCd, 0);
    aw_softmax<<<(BQd * HHd + 255) / 256, 256>>>(offaw);
    cudaStreamWaitEvent(0, evVal, 0);
    deform_sample<<<BQd, 256>>>(value, ref, offaw, samp);
    gemm_tf32_64<<<dim3(4, 64), 128>>>(samp, nullptr, co_w, co_b, t2, BQd, CCd, CCd, 0);
    add_ln<<<BQd, 256>>>(tgt1, t2, ln1_g, ln1_b, tgt2);

    // ---- FFN ----
    gemm_bf16<<<dim3(8, 32), 256>>>(tgt2, f1_w, f1_b, ffn, BQd, DFFd, CCd, 1);
    gemm_tf32_64<<<dim3(4, 64), 128>>>(ffn, nullptr, f2_w, f2_b, t2, BQd, CCd, DFFd, 0);
    add_ln<<<BQd, 256>>>(tgt2, t2, ln3_g, ln3_b, out);
}

// round 12
// speedup vs baseline: 1.5074x; 1.0579x over previous
#include <cuda_runtime.h>
#include <cuda_bf16.h>
#include <math.h>
#include <stdint.h>

#define BB   4
#define LQd  1024
#define CCd  256
#define HHd  8
#define DHd  32
#define LLd  4
#define PPd  4
#define DFFd 1024
#define LSRCd 21760
#define BQd  (BB*LQd)   // 4096

// ------------------------- scratch (device globals; no allocs) ---------------
__device__ float g_qkproj[BQd*512];
__device__ float g_v     [BQd*CCd];
__device__ float g_o     [BQd*CCd];
__device__ float g_tgt1  [BQd*CCd];
__device__ float g_value [(size_t)BB*LSRCd*CCd];
__device__ float g_offaw [BQd*384];
__device__ float g_woffaw[384*CCd];
__device__ float g_boffaw[384];
__device__ float g_samp  [BQd*CCd];
__device__ float g_tgt2  [BQd*CCd];
__device__ float g_ffn   [BQd*DFFd];

// ------------------------- mma helpers ---------------------------------------
__device__ __forceinline__ uint32_t f2tf32(float x) {
    uint32_t r;
    asm("cvt.rna.tf32.f32 %0, %1;" : "=r"(r) : "f"(x));
    return r;
}

__device__ __forceinline__ void mma8(float4& d, const uint32_t* a, const uint32_t* b) {
    asm volatile("mma.sync.aligned.m16n8k8.row.col.f32.tf32.tf32.f32 "
                 "{%0,%1,%2,%3}, {%4,%5,%6,%7}, {%8,%9}, {%0,%1,%2,%3};"
                 : "+f"(d.x), "+f"(d.y), "+f"(d.z), "+f"(d.w)
                 : "r"(a[0]), "r"(a[1]), "r"(a[2]), "r"(a[3]),
                   "r"(b[0]), "r"(b[1]));
}

__device__ __forceinline__ void mma16bf(float4& d, const uint32_t* a, const uint32_t* b) {
    asm volatile("mma.sync.aligned.m16n8k16.row.col.f32.bf16.bf16.f32 "
                 "{%0,%1,%2,%3}, {%4,%5,%6,%7}, {%8,%9}, {%0,%1,%2,%3};"
                 : "+f"(d.x), "+f"(d.y), "+f"(d.z), "+f"(d.w)
                 : "r"(a[0]), "r"(a[1]), "r"(a[2]), "r"(a[3]),
                   "r"(b[0]), "r"(b[1]));
}

__device__ __forceinline__ uint32_t packbf(float x, float y) {
    __nv_bfloat162 h = __floats2bfloat162_rn(x, y);
    return *reinterpret_cast<uint32_t*>(&h);
}

// ------------------------- TF32 GEMM, 64x64 tile, 128 threads ----------------
#define TSTR 20

__global__ __launch_bounds__(128) void gemm_tf32_64(
    const float* __restrict__ A, const float* __restrict__ A2,
    const float* __restrict__ W,
    const float* __restrict__ bias, float* __restrict__ C,
    int M, int N, int K, int relu)
{
    __shared__ uint32_t As[2][64][TSTR];
    __shared__ uint32_t Bs[2][64][TSTR];
    const int tid  = threadIdx.x;
    const int warp = tid >> 5, lane = tid & 31;
    const int g = lane >> 2, t = lane & 3;
    const int wm = (warp >> 1) * 32, wn = (warp & 1) * 32;
    const int m0 = blockIdx.y * 64, n0 = blockIdx.x * 64;
    const int r_ld = tid >> 2, c_ld = (tid & 3) * 4;

    const float* Ap  = A + (size_t)(m0 + r_ld) * K + c_ld;
    const float* Ap2 = A2 ? A2 + (size_t)(m0 + r_ld) * K + c_ld : nullptr;
    const float* Wp  = W + (size_t)(n0 + r_ld) * K + c_ld;

    float4 acc[2][4];
#pragma unroll
    for (int i = 0; i < 2; i++)
#pragma unroll
        for (int j = 0; j < 4; j++) acc[i][j] = make_float4(0.f, 0.f, 0.f, 0.f);

#pragma unroll
    for (int i = 0; i < 2; i++) {
        float4 a = *(const float4*)(Ap + (size_t)(32 * i) * K);
        if (Ap2) {
            float4 a2 = *(const float4*)(Ap2 + (size_t)(32 * i) * K);
            a.x += a2.x; a.y += a2.y; a.z += a2.z; a.w += a2.w;
        }
        float4 b = *(const float4*)(Wp + (size_t)(32 * i) * K);
        uint32_t* as = &As[0][r_ld + 32 * i][c_ld];
        uint32_t* bs = &Bs[0][r_ld + 32 * i][c_ld];
        as[0] = f2tf32(a.x); as[1] = f2tf32(a.y); as[2] = f2tf32(a.z); as[3] = f2tf32(a.w);
        bs[0] = f2tf32(b.x); bs[1] = f2tf32(b.y); bs[2] = f2tf32(b.z); bs[3] = f2tf32(b.w);
    }
    __syncthreads();

    int buf = 0;
    for (int k0 = 16; k0 < K; k0 += 16) {
        float4 pa0 = *(const float4*)(Ap + k0);
        float4 pa1 = *(const float4*)(Ap + (size_t)32 * K + k0);
        if (Ap2) {
            float4 q0v = *(const float4*)(Ap2 + k0);
            float4 q1v = *(const float4*)(Ap2 + (size_t)32 * K + k0);
            pa0.x += q0v.x; pa0.y += q0v.y; pa0.z += q0v.z; pa0.w += q0v.w;
            pa1.x += q1v.x; pa1.y += q1v.y; pa1.z += q1v.z; pa1.w += q1v.w;
        }
        float4 pb0 = *(const float4*)(Wp + k0);
        float4 pb1 = *(const float4*)(Wp + (size_t)32 * K + k0);

#pragma unroll
        for (int ks = 0; ks < 2; ks++) {
            const int kk = ks * 8;
            uint32_t af[2][4], bf[4][2];
#pragma unroll
            for (int mf = 0; mf < 2; mf++) {
                af[mf][0] = As[buf][wm + mf * 16 + g    ][kk + t];
                af[mf][1] = As[buf][wm + mf * 16 + g + 8][kk + t];
                af[mf][2] = As[buf][wm + mf * 16 + g    ][kk + t + 4];
                af[mf][3] = As[buf][wm + mf * 16 + g + 8][kk + t + 4];
            }
#pragma unroll
            for (int nf = 0; nf < 4; nf++) {
                bf[nf][0] = Bs[buf][wn + nf * 8 + g][kk + t];
                bf[nf][1] = Bs[buf][wn + nf * 8 + g][kk + t + 4];
            }
#pragma unroll
            for (int mf = 0; mf < 2; mf++)
#pragma unroll
                for (int nf = 0; nf < 4; nf++)
                    mma8(acc[mf][nf], af[mf], bf[nf]);
        }

        {
            uint32_t* as = &As[buf ^ 1][r_ld][c_ld];
            uint32_t* bs = &Bs[buf ^ 1][r_ld][c_ld];
            as[0] = f2tf32(pa0.x); as[1] = f2tf32(pa0.y); as[2] = f2tf32(pa0.z); as[3] = f2tf32(pa0.w);
            bs[0] = f2tf32(pb0.x); bs[1] = f2tf32(pb0.y); bs[2] = f2tf32(pb0.z); bs[3] = f2tf32(pb0.w);
            uint32_t* as2 = &As[buf ^ 1][r_ld + 32][c_ld];
            uint32_t* bs2 = &Bs[buf ^ 1][r_ld + 32][c_ld];
            as2[0] = f2tf32(pa1.x); as2[1] = f2tf32(pa1.y); as2[2] = f2tf32(pa1.z); as2[3] = f2tf32(pa1.w);
            bs2[0] = f2tf32(pb1.x); bs2[1] = f2tf32(pb1.y); bs2[2] = f2tf32(pb1.z); bs2[3] = f2tf32(pb1.w);
        }
        __syncthreads();
        buf ^= 1;
    }

#pragma unroll
    for (int ks = 0; ks < 2; ks++) {
        const int kk = ks * 8;
        uint32_t af[2][4], bf[4][2];
#pragma unroll
        for (int mf = 0; mf < 2; mf++) {
            af[mf][0] = As[buf][wm + mf * 16 + g    ][kk + t];
            af[mf][1] = As[buf][wm + mf * 16 + g + 8][kk + t];
            af[mf][2] = As[buf][wm + mf * 16 + g    ][kk + t + 4];
            af[mf][3] = As[buf][wm + mf * 16 + g + 8][kk + t + 4];
        }
#pragma unroll
        for (int nf = 0; nf < 4; nf++) {
            bf[nf][0] = Bs[buf][wn + nf * 8 + g][kk + t];
            bf[nf][1] = Bs[buf][wn + nf * 8 + g][kk + t + 4];
        }
#pragma unroll
        for (int mf = 0; mf < 2; mf++)
#pragma unroll
            for (int nf = 0; nf < 4; nf++)
                mma8(acc[mf][nf], af[mf], bf[nf]);
    }

#pragma unroll
    for (int mf = 0; mf < 2; mf++) {
        int row = m0 + wm + mf * 16 + g;
#pragma unroll
        for (int nf = 0; nf < 4; nf++) {
            int col = n0 + wn + nf * 8 + 2 * t;
            float b0 = bias[col], b1 = bias[col + 1];
            float4 v = acc[mf][nf];
            float2 lo = make_float2(v.x + b0, v.y + b1);
            float2 hi = make_float2(v.z + b0, v.w + b1);
            if (relu) {
                lo.x = fmaxf(lo.x, 0.f); lo.y = fmaxf(lo.y, 0.f);
                hi.x = fmaxf(hi.x, 0.f); hi.y = fmaxf(hi.y, 0.f);
            }
            *(float2*)&C[(size_t)row * N + col]       = lo;
            *(float2*)&C[(size_t)(row + 8) * N + col] = hi;
        }
    }
}

// ------------------------- fused TF32 GEMM + residual + LayerNorm ------------
// C = LN(res + A @ W^T + bias) * gamma + beta.  N fixed = 256 (full row/CTA).
// M-tile 16, 256 threads = 8 warps; warp w covers cols w*32..w*32+31.
__global__ __launch_bounds__(256) void gemm_ln_tf32(
    const float* __restrict__ A, const float* __restrict__ W,
    const float* __restrict__ bias, const float* __restrict__ res,
    const float* __restrict__ gamma, const float* __restrict__ beta,
    float* __restrict__ C, int K)
{
    __shared__ uint32_t As[2][16][TSTR];
    __shared__ uint32_t Bs[2][256][TSTR];
    __shared__ float    Cs[16][260];
    const int tid  = threadIdx.x;
    const int warp = tid >> 5, lane = tid & 31;
    const int g = lane >> 2, t = lane & 3;
    const int m0 = blockIdx.x * 16;
    const int ra = tid >> 2, ca = (tid & 3) * 4;   // A loader (tid<64), B loader rows

    float4 acc[4];
#pragma unroll
    for (int j = 0; j < 4; j++) acc[j] = make_float4(0.f, 0.f, 0.f, 0.f);

    // initial tile
    if (tid < 64) {
        float4 a = *(const float4*)(A + (size_t)(m0 + ra) * K + ca);
        uint32_t* as = &As[0][ra][ca];
        as[0] = f2tf32(a.x); as[1] = f2tf32(a.y); as[2] = f2tf32(a.z); as[3] = f2tf32(a.w);
    }
#pragma unroll
    for (int i = 0; i < 4; i++) {
        int r = ra + 64 * i;
        float4 b = *(const float4*)(W + (size_t)r * K + ca);
        uint32_t* bs = &Bs[0][r][ca];
        bs[0] = f2tf32(b.x); bs[1] = f2tf32(b.y); bs[2] = f2tf32(b.z); bs[3] = f2tf32(b.w);
    }
    __syncthreads();

    int buf = 0;
    for (int k0 = 16; k0 < K; k0 += 16) {
        float4 pa = make_float4(0.f, 0.f, 0.f, 0.f);
        if (tid < 64) pa = *(const float4*)(A + (size_t)(m0 + ra) * K + k0 + ca);
        float4 pb[4];
#pragma unroll
        for (int i = 0; i < 4; i++)
            pb[i] = *(const float4*)(W + (size_t)(ra + 64 * i) * K + k0 + ca);

#pragma unroll
        for (int ks = 0; ks < 2; ks++) {
            const int kk = ks * 8;
            uint32_t af[4], bf[4][2];
            af[0] = As[buf][g    ][kk + t];
            af[1] = As[buf][g + 8][kk + t];
            af[2] = As[buf][g    ][kk + t + 4];
            af[3] = As[buf][g + 8][kk + t + 4];
#pragma unroll
            for (int nf = 0; nf < 4; nf++) {
                bf[nf][0] = Bs[buf][warp * 32 + nf * 8 + g][kk + t];
                bf[nf][1] = Bs[buf][warp * 32 + nf * 8 + g][kk + t + 4];
            }
#pragma unroll
            for (int nf = 0; nf < 4; nf++)
                mma8(acc[nf], af, bf[nf]);
        }

        if (tid < 64) {
            uint32_t* as = &As[buf ^ 1][ra][ca];
            as[0] = f2tf32(pa.x); as[1] = f2tf32(pa.y); as[2] = f2tf32(pa.z); as[3] = f2tf32(pa.w);
        }
#pragma unroll
        for (int i = 0; i < 4; i++) {
            uint32_t* bs = &Bs[buf ^ 1][ra + 64 * i][ca];
            bs[0] = f2tf32(pb[i].x); bs[1] = f2tf32(pb[i].y); bs[2] = f2tf32(pb[i].z); bs[3] = f2tf32(pb[i].w);
        }
        __syncthreads();
        buf ^= 1;
    }

#pragma unroll
    for (int ks = 0; ks < 2; ks++) {
        const int kk = ks * 8;
        uint32_t af[4], bf[4][2];
        af[0] = As[buf][g    ][kk + t];
        af[1] = As[buf][g + 8][kk + t];
        af[2] = As[buf][g    ][kk + t + 4];
        af[3] = As[buf][g + 8][kk + t + 4];
#pragma unroll
        for (int nf = 0; nf < 4; nf++) {
            bf[nf][0] = Bs[buf][warp * 32 + nf * 8 + g][kk + t];
            bf[nf][1] = Bs[buf][warp * 32 + nf * 8 + g][kk + t + 4];
        }
#pragma unroll
        for (int nf = 0; nf < 4; nf++)
            mma8(acc[nf], af, bf[nf]);
    }

    // bias + residual -> smem
#pragma unroll
    for (int nf = 0; nf < 4; nf++) {
        int col = warp * 32 + nf * 8 + 2 * t;
        float b0 = bias[col], b1 = bias[col + 1];
        Cs[g    ][col]     = acc[nf].x + b0 + res[(size_t)(m0 + g) * 256 + col];
        Cs[g    ][col + 1] = acc[nf].y + b1 + res[(size_t)(m0 + g) * 256 + col + 1];
        Cs[g + 8][col]     = acc[nf].z + b0 + res[(size_t)(m0 + g + 8) * 256 + col];
        Cs[g + 8][col + 1] = acc[nf].w + b1 + res[(size_t)(m0 + g + 8) * 256 + col + 1];
    }
    __syncthreads();

    // LayerNorm: 16 threads per row, 16 cols per thread (col = sub + 16*j)
    {
        int row = tid >> 4, sub = tid & 15;
        float vals[16];
        float s = 0.f, sq = 0.f;
#pragma unroll
        for (int j = 0; j < 16; j++) {
            float x = Cs[row][sub + 16 * j];
            vals[j] = x; s += x; sq += x * x;
        }
#pragma unroll
        for (int m = 1; m < 16; m <<= 1) {
            s  += __shfl_xor_sync(0xffffffffu, s,  m, 16);
            sq += __shfl_xor_sync(0xffffffffu, sq, m, 16);
        }
        float mean = s * (1.f / 256.f);
        float var  = sq * (1.f / 256.f) - mean * mean;
        float inv  = rsqrtf(var + 1e-5f);
#pragma unroll
        for (int j = 0; j < 16; j++) {
            int col = sub + 16 * j;
            C[(size_t)(m0 + row) * 256 + col] =
                (vals[j] - mean) * inv * gamma[col] + beta[col];
        }
    }
}

// ------------------------- BF16 tensor-core GEMM (128x128) -------------------
__global__ __launch_bounds__(256) void gemm_bf16(
    const float* __restrict__ A, const float* __restrict__ W,
    const float* __restrict__ bias, float* __restrict__ C,
    int M, int N, int K, int relu)
{
    __shared__ uint32_t As[2][128][12];
    __shared__ uint32_t Bs[2][128][12];
    const int tid  = threadIdx.x;
    const int warp = tid >> 5, lane = tid & 31;
    const int g = lane >> 2, t = lane & 3;
    const int wm = (warp >> 2) * 64, wn = (warp & 3) * 32;
    const int m0 = blockIdx.y * 128, n0 = blockIdx.x * 128;
    const int r_ld = tid >> 2, c_ld = (tid & 3) * 4;

    const float* Ap = A + (size_t)(m0 + r_ld) * K + c_ld;
    const float* Wp = W + (size_t)(n0 + r_ld) * K + c_ld;

    float4 acc[4][4];
#pragma unroll
    for (int i = 0; i < 4; i++)
#pragma unroll
        for (int j = 0; j < 4; j++) acc[i][j] = make_float4(0.f, 0.f, 0.f, 0.f);

#pragma unroll
    for (int i = 0; i < 2; i++) {
        float4 a = *(const float4*)(Ap + (size_t)(64 * i) * K);
        float4 b = *(const float4*)(Wp + (size_t)(64 * i) * K);
        uint32_t* as = &As[0][r_ld + 64 * i][c_ld >> 1];
        uint32_t* bs = &Bs[0][r_ld + 64 * i][c_ld >> 1];
        as[0] = packbf(a.x, a.y); as[1] = packbf(a.z, a.w);
        bs[0] = packbf(b.x, b.y); bs[1] = packbf(b.z, b.w);
    }
    __syncthreads();

    int buf = 0;
    for (int k0 = 16; k0 < K; k0 += 16) {
        float4 pa0 = *(const float4*)(Ap + k0);
        float4 pa1 = *(const float4*)(Ap + (size_t)64 * K + k0);
        float4 pb0 = *(const float4*)(Wp + k0);
        float4 pb1 = *(const float4*)(Wp + (size_t)64 * K + k0);

        {
            uint32_t af[4][4], bf[4][2];
#pragma unroll
            for (int mf = 0; mf < 4; mf++) {
                af[mf][0] = As[buf][wm + mf * 16 + g    ][t];
                af[mf][1] = As[buf][wm + mf * 16 + g + 8][t];
                af[mf][2] = As[buf][wm + mf * 16 + g    ][t + 4];
                af[mf][3] = As[buf][wm + mf * 16 + g + 8][t + 4];
            }
#pragma unroll
            for (int nf = 0; nf < 4; nf++) {
                bf[nf][0] = Bs[buf][wn + nf * 8 + g][t];
                bf[nf][1] = Bs[buf][wn + nf * 8 + g][t + 4];
            }
#pragma unroll
            for (int mf = 0; mf < 4; mf++)
#pragma unroll
                for (int nf = 0; nf < 4; nf++)
                    mma16bf(acc[mf][nf], af[mf], bf[nf]);
        }

        {
            uint32_t* as = &As[buf ^ 1][r_ld][c_ld >> 1];
            uint32_t* bs = &Bs[buf ^ 1][r_ld][c_ld >> 1];
            as[0] = packbf(pa0.x, pa0.y); as[1] = packbf(pa0.z, pa0.w);
            bs[0] = packbf(pb0.x, pb0.y); bs[1] = packbf(pb0.z, pb0.w);
            uint32_t* as2 = &As[buf ^ 1][r_ld + 64][c_ld >> 1];
            uint32_t* bs2 = &Bs[buf ^ 1][r_ld + 64][c_ld >> 1];
            as2[0] = packbf(pa1.x, pa1.y); as2[1] = packbf(pa1.z, pa1.w);
            bs2[0] = packbf(pb1.x, pb1.y); bs2[1] = packbf(pb1.z, pb1.w);
        }
        __syncthreads();
        buf ^= 1;
    }

    {
        uint32_t af[4][4], bf[4][2];
#pragma unroll
        for (int mf = 0; mf < 4; mf++) {
            af[mf][0] = As[buf][wm + mf * 16 + g    ][t];
            af[mf][1] = As[buf][wm + mf * 16 + g + 8][t];
            af[mf][2] = As[buf][wm + mf * 16 + g    ][t + 4];
            af[mf][3] = As[buf][wm + mf * 16 + g + 8][t + 4];
        }
#pragma unroll
        for (int nf = 0; nf < 4; nf++) {
            bf[nf][0] = Bs[buf][wn + nf * 8 + g][t];
            bf[nf][1] = Bs[buf][wn + nf * 8 + g][t + 4];
        }
#pragma unroll
        for (int mf = 0; mf < 4; mf++)
#pragma unroll
            for (int nf = 0; nf < 4; nf++)
                mma16bf(acc[mf][nf], af[mf], bf[nf]);
    }

#pragma unroll
    for (int mf = 0; mf < 4; mf++) {
        int row = m0 + wm + mf * 16 + g;
#pragma unroll
        for (int nf = 0; nf < 4; nf++) {
            int col = n0 + wn + nf * 8 + 2 * t;
            float b0 = bias[col], b1 = bias[col + 1];
            float4 v = acc[mf][nf];
            float2 lo = make_float2(v.x + b0, v.y + b1);
            float2 hi = make_float2(v.z + b0, v.w + b1);
            if (relu) {
                lo.x = fmaxf(lo.x, 0.f); lo.y = fmaxf(lo.y, 0.f);
                hi.x = fmaxf(hi.x, 0.f); hi.y = fmaxf(hi.y, 0.f);
            }
            *(float2*)&C[(size_t)row * N + col]       = lo;
            *(float2*)&C[(size_t)(row + 8) * N + col] = hi;
        }
    }
}

// ------------------------- tensor-core flash attention -----------------------
// grid (LQ/64=16, B*H=32), 128 thr = 4 warps; warp = 16 q-rows x 64 keys.
__global__ __launch_bounds__(128) void flash_attn_mma(
    const float* __restrict__ qkproj, const float* __restrict__ vsrc,
    float* __restrict__ O)
{
    __shared__ uint32_t sm[5760];
    uint32_t* Ks = sm;              // [64][36] tf32
    uint32_t* Vs = sm + 2304;      // [32][36] bf16 pairs
    uint32_t* Ps = sm + 3456;      // [4][16][36] bf16 pairs per warp
    uint32_t* Qstage = sm;         // overlay [64][36] (pre-loop only)

    const int bh = blockIdx.y, b = bh >> 3, h = bh & 7;
    const int q0 = blockIdx.x * 64;
    const int tid = threadIdx.x, warp = tid >> 5, lane = tid & 31;
    const int g = lane >> 2, t = lane & 3;
    const float SC = 0.1767766952966368932f;

    const float* qp = qkproj + (size_t)b * LQd * 512 + h * DHd;
    const float* kp = qp + 256;
    const float* vp = vsrc + (size_t)b * LQd * CCd + h * DHd;

#pragma unroll
    for (int i = 0; i < 16; i++) {
        int idx = tid + i * 128;
        int row = idx >> 5, d = idx & 31;
        Qstage[row * 36 + d] = f2tf32(qp[(size_t)(q0 + row) * 512 + d] * SC);
    }
    __syncthreads();
    uint32_t qf[4][4];
#pragma unroll
    for (int kc = 0; kc < 4; kc++) {
        int r = (warp * 16 + g) * 36;
        qf[kc][0] = Qstage[r + kc * 8 + t];
        qf[kc][1] = Qstage[r + 8 * 36 + kc * 8 + t];
        qf[kc][2] = Qstage[r + kc * 8 + t + 4];
        qf[kc][3] = Qstage[r + 8 * 36 + kc * 8 + t + 4];
    }

    uint32_t* Pw = Ps + warp * 16 * 36;
    float m0r = -1e30f, m1r = -1e30f, l0r = 0.f, l1r = 0.f;
    float4 oacc[4];
#pragma unroll
    for (int i = 0; i < 4; i++) oacc[i] = make_float4(0.f, 0.f, 0.f, 0.f);

    for (int kt = 0; kt < 16; kt++) {
        const float* kbase = kp + (size_t)kt * 64 * 512;
        const float* vbase = vp + (size_t)kt * 64 * 256;
        __syncthreads();
#pragma unroll
        for (int i = 0; i < 16; i++) {
            int idx = tid + i * 128;
            int key = idx >> 5, d = idx & 31;
            Ks[key * 36 + d] = f2tf32(kbase[(size_t)key * 512 + d]);
        }
#pragma unroll
        for (int i = 0; i < 8; i++) {
            int idx = tid + i * 128;
            int kpair = idx >> 5, d = idx & 31;
            float v0 = vbase[(size_t)(2 * kpair) * 256 + d];
            float v1 = vbase[(size_t)(2 * kpair + 1) * 256 + d];
            Vs[d * 36 + kpair] = packbf(v0, v1);
        }
        __syncthreads();

        float4 sacc[8];
#pragma unroll
        for (int nf = 0; nf < 8; nf++) sacc[nf] = make_float4(0.f, 0.f, 0.f, 0.f);
#pragma unroll
        for (int nf = 0; nf < 8; nf++) {
#pragma unroll
            for (int kc = 0; kc < 4; kc++) {
                uint32_t bfr[2];
                bfr[0] = Ks[(nf * 8 + g) * 36 + kc * 8 + t];
                bfr[1] = Ks[(nf * 8 + g) * 36 + kc * 8 + t + 4];
                mma8(sacc[nf], qf[kc], bfr);
            }
        }

        float mx0 = -1e30f, mx1 = -1e30f;
#pragma unroll
        for (int nf = 0; nf < 8; nf++) {
            mx0 = fmaxf(mx0, fmaxf(sacc[nf].x, sacc[nf].y));
            mx1 = fmaxf(mx1, fmaxf(sacc[nf].z, sacc[nf].w));
        }
        mx0 = fmaxf(mx0, __shfl_xor_sync(0xffffffffu, mx0, 1));
        mx0 = fmaxf(mx0, __shfl_xor_sync(0xffffffffu, mx0, 2));
        mx1 = fmaxf(mx1, __shfl_xor_sync(0xffffffffu, mx1, 1));
        mx1 = fmaxf(mx1, __shfl_xor_sync(0xffffffffu, mx1, 2));
        float mn0 = fmaxf(m0r, mx0), mn1 = fmaxf(m1r, mx1);
        float cf0 = __expf(m0r - mn0), cf1 = __expf(m1r - mn1);
        float rs0 = 0.f, rs1 = 0.f;
#pragma unroll
        for (int nf = 0; nf < 8; nf++) {
            float p0 = __expf(sacc[nf].x - mn0);
            float p1 = __expf(sacc[nf].y - mn0);
            float p2 = __expf(sacc[nf].z - mn1);
            float p3 = __expf(sacc[nf].w - mn1);
            rs0 += p0 + p1; rs1 += p2 + p3;
            Pw[(g    ) * 36 + nf * 4 + t] = packbf(p0, p1);
            Pw[(g + 8) * 36 + nf * 4 + t] = packbf(p2, p3);
        }
        rs0 += __shfl_xor_sync(0xffffffffu, rs0, 1);
        rs0 += __shfl_xor_sync(0xffffffffu, rs0, 2);
        rs1 += __shfl_xor_sync(0xffffffffu, rs1, 1);
        rs1 += __shfl_xor_sync(0xffffffffu, rs1, 2);
        l0r = l0r * cf0 + rs0; l1r = l1r * cf1 + rs1;
        m0r = mn0; m1r = mn1;
#pragma unroll
        for (int nf = 0; nf < 4; nf++) {
            oacc[nf].x *= cf0; oacc[nf].y *= cf0;
            oacc[nf].z *= cf1; oacc[nf].w *= cf1;
        }
        __syncwarp();

#pragma unroll
        for (int kc = 0; kc < 4; kc++) {
            uint32_t af[4];
            af[0] = Pw[(g    ) * 36 + kc * 8 + t];
            af[1] = Pw[(g + 8) * 36 + kc * 8 + t];
            af[2] = Pw[(g    ) * 36 + kc * 8 + t + 4];
            af[3] = Pw[(g + 8) * 36 + kc * 8 + t + 4];
#pragma unroll
            for (int nf = 0; nf < 4; nf++) {
                uint32_t bfr[2];
                bfr[0] = Vs[(nf * 8 + g) * 36 + kc * 8 + t];
                bfr[1] = Vs[(nf * 8 + g) * 36 + kc * 8 + t + 4];
                mma16bf(oacc[nf], af, bfr);
            }
        }
    }

    float inv0 = 1.f / l0r, inv1 = 1.f / l1r;
    int row = q0 + warp * 16 + g;
#pragma unroll
    for (int nf = 0; nf < 4; nf++) {
        int col = h * DHd + nf * 8 + 2 * t;
        *(float2*)&O[(size_t)(b * LQd + row) * CCd + col] =
            make_float2(oacc[nf].x * inv0, oacc[nf].y * inv0);
        *(float2*)&O[(size_t)(b * LQd + row + 8) * CCd + col] =
            make_float2(oacc[nf].z * inv1, oacc[nf].w * inv1);
    }
}

// ------------------------- attention-weight softmax over L*P=16 --------------
__global__ void aw_softmax(float* __restrict__ a)
{
    int gi = blockIdx.x * blockDim.x + threadIdx.x;
    if (gi >= BQd * HHd) return;
    int bq = gi >> 3, h = gi & 7;
    float* p = a + (size_t)bq * 384 + 256 + h * 16;
    float x[16];
    float m = -1e30f;
#pragma unroll
    for (int i = 0; i < 16; i++) { x[i] = p[i]; m = fmaxf(m, x[i]); }
    float s = 0.f;
#pragma unroll
    for (int i = 0; i < 16; i++) { x[i] = __expf(x[i] - m); s += x[i]; }
    float inv = 1.f / s;
#pragma unroll
    for (int i = 0; i < 16; i++) p[i] = x[i] * inv;
}

// ------------------------- multi-scale deformable sampling -------------------
__global__ void deform_sample(const float* __restrict__ value, const float* __restrict__ ref,
                              const float* __restrict__ offaw, float* __restrict__ out)
{
    const int levH[4] = {128, 64, 32, 16};
    const int levW[4] = {128, 64, 32, 16};
    const int levS[4] = {0, 16384, 20480, 21504};
    int bq = blockIdx.x;
    int b  = bq >> 10;
    int h  = threadIdx.x >> 5;
    int d  = threadIdx.x & 31;
    float acc = 0.f;
#pragma unroll
    for (int l = 0; l < 4; l++) {
        float rx = ref[((size_t)bq * LLd + l) * 2 + 0];
        float ry = ref[((size_t)bq * LLd + l) * 2 + 1];
        int w = levW[l], hh = levH[l], st = levS[l];
        float fw = (float)w, fh = (float)hh;
#pragma unroll
        for (int p = 0; p < 4; p++) {
            size_t oidx = (size_t)bq * 384 + h * 32 + (l * 4 + p) * 2;
            float lx = rx + offaw[oidx]     / fw;
            float ly = ry + offaw[oidx + 1] / fh;
            float x = lx * fw - 0.5f;
            float y = ly * fh - 0.5f;
            float x0f = floorf(x), y0f = floorf(y);
            int x0 = (int)x0f, y0 = (int)y0f;
            float wx1 = x - x0f, wx0 = 1.f - wx1;
            float wy1 = y - y0f, wy0 = 1.f - wy1;
            float a = offaw[(size_t)bq * 384 + 256 + h * 16 + l * 4 + p];
            float s = 0.f;
#pragma unroll
            for (int cy = 0; cy < 2; cy++) {
#pragma unroll
                for (int cx = 0; cx < 2; cx++) {
                    int ix = x0 + cx, iy = y0 + cy;
                    if (ix >= 0 && ix < w && iy >= 0 && iy < hh) {
                        float wgt = (cx ? wx1 : wx0) * (cy ? wy1 : wy0);
                        size_t vidx = (((size_t)(b * LSRCd + st + iy * w + ix)) * HHd + h) * DHd + d;
                        s += wgt * value[vidx];
                    }
                }
            }
            acc += a * s;
        }
    }
    out[(size_t)bq * CCd + h * DHd + d] = acc;
}

// ------------------------- launch --------------------------------------------
extern "C" void kernel_launch(void* const* d_in, const int* in_sizes, int n_in,
                              void* d_out, int out_size)
{
    (void)in_sizes; (void)n_in; (void)out_size;
    const float* tgt   = (const float*)d_in[0];
    const float* qpos  = (const float*)d_in[1];
    const float* ref   = (const float*)d_in[2];
    const float* src   = (const float*)d_in[3];
    const float* in_w  = (const float*)d_in[4];
    const float* in_b  = (const float*)d_in[5];
    const float* sa_w  = (const float*)d_in[6];
    const float* sa_b  = (const float*)d_in[7];
    const float* off_w = (const float*)d_in[8];
    const float* off_b = (const float*)d_in[9];
    const float* aw_w  = (const float*)d_in[10];
    const float* aw_b  = (const float*)d_in[11];
    const float* val_w = (const float*)d_in[12];
    const float* val_b = (const float*)d_in[13];
    const float* co_w  = (const float*)d_in[14];
    const float* co_b  = (const float*)d_in[15];
    const float* ln1_g = (const float*)d_in[16];
    const float* ln1_b = (const float*)d_in[17];
    const float* ln2_g = (const float*)d_in[18];
    const float* ln2_b = (const float*)d_in[19];
    const float* ln3_g = (const float*)d_in[20];
    const float* ln3_b = (const float*)d_in[21];
    const float* f1_w  = (const float*)d_in[22];
    const float* f1_b  = (const float*)d_in[23];
    const float* f2_w  = (const float*)d_in[24];
    const float* f2_b  = (const float*)d_in[25];
    float* out = (float*)d_out;

    float *qkproj, *v, *o, *tgt1, *value, *offaw, *woffaw, *boffaw, *samp, *tgt2, *ffn;
    cudaGetSymbolAddress((void**)&qkproj, g_qkproj);
    cudaGetSymbolAddress((void**)&v,      g_v);
    cudaGetSymbolAddress((void**)&o,      g_o);
    cudaGetSymbolAddress((void**)&tgt1,   g_tgt1);
    cudaGetSymbolAddress((void**)&value,  g_value);
    cudaGetSymbolAddress((void**)&offaw,  g_offaw);
    cudaGetSymbolAddress((void**)&woffaw, g_woffaw);
    cudaGetSymbolAddress((void**)&boffaw, g_boffaw);
    cudaGetSymbolAddress((void**)&samp,   g_samp);
    cudaGetSymbolAddress((void**)&tgt2,   g_tgt2);
    cudaGetSymbolAddress((void**)&ffn,    g_ffn);

    // side streams + events for capture-legal fork/join (created once)
    static cudaStream_t sv = nullptr, sw = nullptr;
    static cudaEvent_t evRoot = nullptr, evV = nullptr, evVal = nullptr, evW = nullptr;
    if (!sv) {
        cudaStreamCreateWithFlags(&sv, cudaStreamNonBlocking);
        cudaStreamCreateWithFlags(&sw, cudaStreamNonBlocking);
        cudaEventCreateWithFlags(&evRoot, cudaEventDisableTiming);
        cudaEventCreateWithFlags(&evV,    cudaEventDisableTiming);
        cudaEventCreateWithFlags(&evVal,  cudaEventDisableTiming);
        cudaEventCreateWithFlags(&evW,    cudaEventDisableTiming);
    }

    cudaEventRecord(evRoot, 0);

    // stream sw: weight concat + big value GEMM (hidden under self-attn)
    cudaStreamWaitEvent(sw, evRoot, 0);
    cudaMemcpyAsync(woffaw,             off_w, 256 * 256 * sizeof(float), cudaMemcpyDeviceToDevice, sw);
    cudaMemcpyAsync(woffaw + 256 * 256, aw_w,  128 * 256 * sizeof(float), cudaMemcpyDeviceToDevice, sw);
    cudaMemcpyAsync(boffaw,             off_b, 256 * sizeof(float),       cudaMemcpyDeviceToDevice, sw);
    cudaMemcpyAsync(boffaw + 256,       aw_b,  128 * sizeof(float),       cudaMemcpyDeviceToDevice, sw);
    cudaEventRecord(evW, sw);
    gemm_bf16<<<dim3(2, 680), 256, 0, sw>>>(src, val_w, val_b, value, BB * LSRCd, CCd, CCd, 0);
    cudaEventRecord(evVal, sw);

    // stream sv: V projection (overlaps qkproj)
    cudaStreamWaitEvent(sv, evRoot, 0);
    gemm_tf32_64<<<dim3(4, 64), 128, 0, sv>>>(tgt, nullptr, in_w + 2 * CCd * CCd, in_b + 2 * CCd, v, BQd, CCd, CCd, 0);
    cudaEventRecord(evV, sv);

    // ---- main stream: self-attention ----
    gemm_tf32_64<<<dim3(8, 64), 128>>>(tgt, qpos, in_w, in_b, qkproj, BQd, 512, CCd, 0);
    cudaStreamWaitEvent(0, evV, 0);
    flash_attn_mma<<<dim3(16, 32), 128>>>(qkproj, v, o);
    gemm_ln_tf32<<<BQd / 16, 256>>>(o, sa_w, sa_b, tgt, ln2_g, ln2_b, tgt1, CCd);

    // ---- deformable cross-attention ----
    cudaStreamWaitEvent(0, evW, 0);
    gemm_tf32_64<<<dim3(6, 64), 128>>>(tgt1, qpos, woffaw, boffaw, offaw, BQd, 384, CCd, 0);
    aw_softmax<<<(BQd * HHd + 255) / 256, 256>>>(offaw);
    cudaStreamWaitEvent(0, evVal, 0);
    deform_sample<<<BQd, 256>>>(value, ref, offaw, samp);
    gemm_ln_tf32<<<BQd / 16, 256>>>(samp, co_w, co_b, tgt1, ln1_g, ln1_b, tgt2, CCd);

    // ---- FFN ----
    gemm_bf16<<<dim3(8, 32), 256>>>(tgt2, f1_w, f1_b, ffn, BQd, DFFd, CCd, 1);
    gemm_ln_tf32<<<BQd / 16, 256>>>(ffn, f2_w, f2_b, tgt2, ln3_g, ln3_b, out, DFFd);
}

// round 13
// speedup vs baseline: 1.5432x; 1.0238x over previous
#include <cuda_runtime.h>
#include <cuda_bf16.h>
#include <math.h>
#include <stdint.h>

#define BB   4
#define LQd  1024
#define CCd  256
#define HHd  8
#define DHd  32
#define LLd  4
#define PPd  4
#define DFFd 1024
#define LSRCd 21760
#define BQd  (BB*LQd)   // 4096

// ------------------------- scratch (device globals; no allocs) ---------------
__device__ float g_qkproj[BQd*512];
__device__ float g_v     [BQd*CCd];
__device__ float g_o     [BQd*CCd];
__device__ float g_tgt1  [BQd*CCd];
__device__ float g_value [(size_t)BB*LSRCd*CCd];
__device__ float g_offaw [BQd*384];
__device__ float g_woffaw[384*CCd];
__device__ float g_boffaw[384];
__device__ float g_samp  [BQd*CCd];
__device__ float g_tgt2  [BQd*CCd];
__device__ float g_ffn   [BQd*DFFd];

// ------------------------- mma helpers ---------------------------------------
__device__ __forceinline__ uint32_t f2tf32(float x) {
    uint32_t r;
    asm("cvt.rna.tf32.f32 %0, %1;" : "=r"(r) : "f"(x));
    return r;
}

__device__ __forceinline__ void mma8(float4& d, const uint32_t* a, const uint32_t* b) {
    asm volatile("mma.sync.aligned.m16n8k8.row.col.f32.tf32.tf32.f32 "
                 "{%0,%1,%2,%3}, {%4,%5,%6,%7}, {%8,%9}, {%0,%1,%2,%3};"
                 : "+f"(d.x), "+f"(d.y), "+f"(d.z), "+f"(d.w)
                 : "r"(a[0]), "r"(a[1]), "r"(a[2]), "r"(a[3]),
                   "r"(b[0]), "r"(b[1]));
}

__device__ __forceinline__ void mma16bf(float4& d, const uint32_t* a, const uint32_t* b) {
    asm volatile("mma.sync.aligned.m16n8k16.row.col.f32.bf16.bf16.f32 "
                 "{%0,%1,%2,%3}, {%4,%5,%6,%7}, {%8,%9}, {%0,%1,%2,%3};"
                 : "+f"(d.x), "+f"(d.y), "+f"(d.z), "+f"(d.w)
                 : "r"(a[0]), "r"(a[1]), "r"(a[2]), "r"(a[3]),
                   "r"(b[0]), "r"(b[1]));
}

__device__ __forceinline__ uint32_t packbf(float x, float y) {
    __nv_bfloat162 h = __floats2bfloat162_rn(x, y);
    return *reinterpret_cast<uint32_t*>(&h);
}

// ------------------------- TF32 GEMM, 64x64 tile, 128 threads ----------------
#define TSTR 20

__global__ __launch_bounds__(128) void gemm_tf32_64(
    const float* __restrict__ A, const float* __restrict__ A2,
    const float* __restrict__ W,
    const float* __restrict__ bias, float* __restrict__ C,
    int M, int N, int K, int relu)
{
    __shared__ uint32_t As[2][64][TSTR];
    __shared__ uint32_t Bs[2][64][TSTR];
    const int tid  = threadIdx.x;
    const int warp = tid >> 5, lane = tid & 31;
    const int g = lane >> 2, t = lane & 3;
    const int wm = (warp >> 1) * 32, wn = (warp & 1) * 32;
    const int m0 = blockIdx.y * 64, n0 = blockIdx.x * 64;
    const int r_ld = tid >> 2, c_ld = (tid & 3) * 4;

    const float* Ap  = A + (size_t)(m0 + r_ld) * K + c_ld;
    const float* Ap2 = A2 ? A2 + (size_t)(m0 + r_ld) * K + c_ld : nullptr;
    const float* Wp  = W + (size_t)(n0 + r_ld) * K + c_ld;

    float4 acc[2][4];
#pragma unroll
    for (int i = 0; i < 2; i++)
#pragma unroll
        for (int j = 0; j < 4; j++) acc[i][j] = make_float4(0.f, 0.f, 0.f, 0.f);

#pragma unroll
    for (int i = 0; i < 2; i++) {
        float4 a = *(const float4*)(Ap + (size_t)(32 * i) * K);
        if (Ap2) {
            float4 a2 = *(const float4*)(Ap2 + (size_t)(32 * i) * K);
            a.x += a2.x; a.y += a2.y; a.z += a2.z; a.w += a2.w;
        }
        float4 b = *(const float4*)(Wp + (size_t)(32 * i) * K);
        uint32_t* as = &As[0][r_ld + 32 * i][c_ld];
        uint32_t* bs = &Bs[0][r_ld + 32 * i][c_ld];
        as[0] = f2tf32(a.x); as[1] = f2tf32(a.y); as[2] = f2tf32(a.z); as[3] = f2tf32(a.w);
        bs[0] = f2tf32(b.x); bs[1] = f2tf32(b.y); bs[2] = f2tf32(b.z); bs[3] = f2tf32(b.w);
    }
    __syncthreads();

    int buf = 0;
    for (int k0 = 16; k0 < K; k0 += 16) {
        float4 pa0 = *(const float4*)(Ap + k0);
        float4 pa1 = *(const float4*)(Ap + (size_t)32 * K + k0);
        if (Ap2) {
            float4 q0v = *(const float4*)(Ap2 + k0);
            float4 q1v = *(const float4*)(Ap2 + (size_t)32 * K + k0);
            pa0.x += q0v.x; pa0.y += q0v.y; pa0.z += q0v.z; pa0.w += q0v.w;
            pa1.x += q1v.x; pa1.y += q1v.y; pa1.z += q1v.z; pa1.w += q1v.w;
        }
        float4 pb0 = *(const float4*)(Wp + k0);
        float4 pb1 = *(const float4*)(Wp + (size_t)32 * K + k0);

#pragma unroll
        for (int ks = 0; ks < 2; ks++) {
            const int kk = ks * 8;
            uint32_t af[2][4], bf[4][2];
#pragma unroll
            for (int mf = 0; mf < 2; mf++) {
                af[mf][0] = As[buf][wm + mf * 16 + g    ][kk + t];
                af[mf][1] = As[buf][wm + mf * 16 + g + 8][kk + t];
                af[mf][2] = As[buf][wm + mf * 16 + g    ][kk + t + 4];
                af[mf][3] = As[buf][wm + mf * 16 + g + 8][kk + t + 4];
            }
#pragma unroll
            for (int nf = 0; nf < 4; nf++) {
                bf[nf][0] = Bs[buf][wn + nf * 8 + g][kk + t];
                bf[nf][1] = Bs[buf][wn + nf * 8 + g][kk + t + 4];
            }
#pragma unroll
            for (int mf = 0; mf < 2; mf++)
#pragma unroll
                for (int nf = 0; nf < 4; nf++)
                    mma8(acc[mf][nf], af[mf], bf[nf]);
        }

        {
            uint32_t* as = &As[buf ^ 1][r_ld][c_ld];
            uint32_t* bs = &Bs[buf ^ 1][r_ld][c_ld];
            as[0] = f2tf32(pa0.x); as[1] = f2tf32(pa0.y); as[2] = f2tf32(pa0.z); as[3] = f2tf32(pa0.w);
            bs[0] = f2tf32(pb0.x); bs[1] = f2tf32(pb0.y); bs[2] = f2tf32(pb0.z); bs[3] = f2tf32(pb0.w);
            uint32_t* as2 = &As[buf ^ 1][r_ld + 32][c_ld];
            uint32_t* bs2 = &Bs[buf ^ 1][r_ld + 32][c_ld];
            as2[0] = f2tf32(pa1.x); as2[1] = f2tf32(pa1.y); as2[2] = f2tf32(pa1.z); as2[3] = f2tf32(pa1.w);
            bs2[0] = f2tf32(pb1.x); bs2[1] = f2tf32(pb1.y); bs2[2] = f2tf32(pb1.z); bs2[3] = f2tf32(pb1.w);
        }
        __syncthreads();
        buf ^= 1;
    }

#pragma unroll
    for (int ks = 0; ks < 2; ks++) {
        const int kk = ks * 8;
        uint32_t af[2][4], bf[4][2];
#pragma unroll
        for (int mf = 0; mf < 2; mf++) {
            af[mf][0] = As[buf][wm + mf * 16 + g    ][kk + t];
            af[mf][1] = As[buf][wm + mf * 16 + g + 8][kk + t];
            af[mf][2] = As[buf][wm + mf * 16 + g    ][kk + t + 4];
            af[mf][3] = As[buf][wm + mf * 16 + g + 8][kk + t + 4];
        }
#pragma unroll
        for (int nf = 0; nf < 4; nf++) {
            bf[nf][0] = Bs[buf][wn + nf * 8 + g][kk + t];
            bf[nf][1] = Bs[buf][wn + nf * 8 + g][kk + t + 4];
        }
#pragma unroll
        for (int mf = 0; mf < 2; mf++)
#pragma unroll
            for (int nf = 0; nf < 4; nf++)
                mma8(acc[mf][nf], af[mf], bf[nf]);
    }

#pragma unroll
    for (int mf = 0; mf < 2; mf++) {
        int row = m0 + wm + mf * 16 + g;
#pragma unroll
        for (int nf = 0; nf < 4; nf++) {
            int col = n0 + wn + nf * 8 + 2 * t;
            float b0 = bias[col], b1 = bias[col + 1];
            float4 v = acc[mf][nf];
            float2 lo = make_float2(v.x + b0, v.y + b1);
            float2 hi = make_float2(v.z + b0, v.w + b1);
            if (relu) {
                lo.x = fmaxf(lo.x, 0.f); lo.y = fmaxf(lo.y, 0.f);
                hi.x = fmaxf(hi.x, 0.f); hi.y = fmaxf(hi.y, 0.f);
            }
            *(float2*)&C[(size_t)row * N + col]       = lo;
            *(float2*)&C[(size_t)(row + 8) * N + col] = hi;
        }
    }
}

// ------------------------- fused TF32 GEMM + residual + LayerNorm ------------
__global__ __launch_bounds__(256) void gemm_ln_tf32(
    const float* __restrict__ A, const float* __restrict__ W,
    const float* __restrict__ bias, const float* __restrict__ res,
    const float* __restrict__ gamma, const float* __restrict__ beta,
    float* __restrict__ C, int K)
{
    __shared__ uint32_t As[2][16][TSTR];
    __shared__ uint32_t Bs[2][256][TSTR];
    __shared__ float    Cs[16][260];
    const int tid  = threadIdx.x;
    const int warp = tid >> 5, lane = tid & 31;
    const int g = lane >> 2, t = lane & 3;
    const int m0 = blockIdx.x * 16;
    const int ra = tid >> 2, ca = (tid & 3) * 4;

    float4 acc[4];
#pragma unroll
    for (int j = 0; j < 4; j++) acc[j] = make_float4(0.f, 0.f, 0.f, 0.f);

    if (tid < 64) {
        float4 a = *(const float4*)(A + (size_t)(m0 + ra) * K + ca);
        uint32_t* as = &As[0][ra][ca];
        as[0] = f2tf32(a.x); as[1] = f2tf32(a.y); as[2] = f2tf32(a.z); as[3] = f2tf32(a.w);
    }
#pragma unroll
    for (int i = 0; i < 4; i++) {
        int r = ra + 64 * i;
        float4 b = *(const float4*)(W + (size_t)r * K + ca);
        uint32_t* bs = &Bs[0][r][ca];
        bs[0] = f2tf32(b.x); bs[1] = f2tf32(b.y); bs[2] = f2tf32(b.z); bs[3] = f2tf32(b.w);
    }
    __syncthreads();

    int buf = 0;
    for (int k0 = 16; k0 < K; k0 += 16) {
        float4 pa = make_float4(0.f, 0.f, 0.f, 0.f);
        if (tid < 64) pa = *(const float4*)(A + (size_t)(m0 + ra) * K + k0 + ca);
        float4 pb[4];
#pragma unroll
        for (int i = 0; i < 4; i++)
            pb[i] = *(const float4*)(W + (size_t)(ra + 64 * i) * K + k0 + ca);

#pragma unroll
        for (int ks = 0; ks < 2; ks++) {
            const int kk = ks * 8;
            uint32_t af[4], bf[4][2];
            af[0] = As[buf][g    ][kk + t];
            af[1] = As[buf][g + 8][kk + t];
            af[2] = As[buf][g    ][kk + t + 4];
            af[3] = As[buf][g + 8][kk + t + 4];
#pragma unroll
            for (int nf = 0; nf < 4; nf++) {
                bf[nf][0] = Bs[buf][warp * 32 + nf * 8 + g][kk + t];
                bf[nf][1] = Bs[buf][warp * 32 + nf * 8 + g][kk + t + 4];
            }
#pragma unroll
            for (int nf = 0; nf < 4; nf++)
                mma8(acc[nf], af, bf[nf]);
        }

        if (tid < 64) {
            uint32_t* as = &As[buf ^ 1][ra][ca];
            as[0] = f2tf32(pa.x); as[1] = f2tf32(pa.y); as[2] = f2tf32(pa.z); as[3] = f2tf32(pa.w);
        }
#pragma unroll
        for (int i = 0; i < 4; i++) {
            uint32_t* bs = &Bs[buf ^ 1][ra + 64 * i][ca];
            bs[0] = f2tf32(pb[i].x); bs[1] = f2tf32(pb[i].y); bs[2] = f2tf32(pb[i].z); bs[3] = f2tf32(pb[i].w);
        }
        __syncthreads();
        buf ^= 1;
    }

#pragma unroll
    for (int ks = 0; ks < 2; ks++) {
        const int kk = ks * 8;
        uint32_t af[4], bf[4][2];
        af[0] = As[buf][g    ][kk + t];
        af[1] = As[buf][g + 8][kk + t];
        af[2] = As[buf][g    ][kk + t + 4];
        af[3] = As[buf][g + 8][kk + t + 4];
#pragma unroll
        for (int nf = 0; nf < 4; nf++) {
            bf[nf][0] = Bs[buf][warp * 32 + nf * 8 + g][kk + t];
            bf[nf][1] = Bs[buf][warp * 32 + nf * 8 + g][kk + t + 4];
        }
#pragma unroll
        for (int nf = 0; nf < 4; nf++)
            mma8(acc[nf], af, bf[nf]);
    }

#pragma unroll
    for (int nf = 0; nf < 4; nf++) {
        int col = warp * 32 + nf * 8 + 2 * t;
        float b0 = bias[col], b1 = bias[col + 1];
        Cs[g    ][col]     = acc[nf].x + b0 + res[(size_t)(m0 + g) * 256 + col];
        Cs[g    ][col + 1] = acc[nf].y + b1 + res[(size_t)(m0 + g) * 256 + col + 1];
        Cs[g + 8][col]     = acc[nf].z + b0 + res[(size_t)(m0 + g + 8) * 256 + col];
        Cs[g + 8][col + 1] = acc[nf].w + b1 + res[(size_t)(m0 + g + 8) * 256 + col + 1];
    }
    __syncthreads();

    {
        int row = tid >> 4, sub = tid & 15;
        float vals[16];
        float s = 0.f, sq = 0.f;
#pragma unroll
        for (int j = 0; j < 16; j++) {
            float x = Cs[row][sub + 16 * j];
            vals[j] = x; s += x; sq += x * x;
        }
#pragma unroll
        for (int m = 1; m < 16; m <<= 1) {
            s  += __shfl_xor_sync(0xffffffffu, s,  m, 16);
            sq += __shfl_xor_sync(0xffffffffu, sq, m, 16);
        }
        float mean = s * (1.f / 256.f);
        float var  = sq * (1.f / 256.f) - mean * mean;
        float inv  = rsqrtf(var + 1e-5f);
#pragma unroll
        for (int j = 0; j < 16; j++) {
            int col = sub + 16 * j;
            C[(size_t)(m0 + row) * 256 + col] =
                (vals[j] - mean) * inv * gamma[col] + beta[col];
        }
    }
}

// ------------------------- BF16 tensor-core GEMM (128x128) -------------------
__global__ __launch_bounds__(256) void gemm_bf16(
    const float* __restrict__ A, const float* __restrict__ W,
    const float* __restrict__ bias, float* __restrict__ C,
    int M, int N, int K, int relu)
{
    __shared__ uint32_t As[2][128][12];
    __shared__ uint32_t Bs[2][128][12];
    const int tid  = threadIdx.x;
    const int warp = tid >> 5, lane = tid & 31;
    const int g = lane >> 2, t = lane & 3;
    const int wm = (warp >> 2) * 64, wn = (warp & 3) * 32;
    const int m0 = blockIdx.y * 128, n0 = blockIdx.x * 128;
    const int r_ld = tid >> 2, c_ld = (tid & 3) * 4;

    const float* Ap = A + (size_t)(m0 + r_ld) * K + c_ld;
    const float* Wp = W + (size_t)(n0 + r_ld) * K + c_ld;

    float4 acc[4][4];
#pragma unroll
    for (int i = 0; i < 4; i++)
#pragma unroll
        for (int j = 0; j < 4; j++) acc[i][j] = make_float4(0.f, 0.f, 0.f, 0.f);

#pragma unroll
    for (int i = 0; i < 2; i++) {
        float4 a = *(const float4*)(Ap + (size_t)(64 * i) * K);
        float4 b = *(const float4*)(Wp + (size_t)(64 * i) * K);
        uint32_t* as = &As[0][r_ld + 64 * i][c_ld >> 1];
        uint32_t* bs = &Bs[0][r_ld + 64 * i][c_ld >> 1];
        as[0] = packbf(a.x, a.y); as[1] = packbf(a.z, a.w);
        bs[0] = packbf(b.x, b.y); bs[1] = packbf(b.z, b.w);
    }
    __syncthreads();

    int buf = 0;
    for (int k0 = 16; k0 < K; k0 += 16) {
        float4 pa0 = *(const float4*)(Ap + k0);
        float4 pa1 = *(const float4*)(Ap + (size_t)64 * K + k0);
        float4 pb0 = *(const float4*)(Wp + k0);
        float4 pb1 = *(const float4*)(Wp + (size_t)64 * K + k0);

        {
            uint32_t af[4][4], bf[4][2];
#pragma unroll
            for (int mf = 0; mf < 4; mf++) {
                af[mf][0] = As[buf][wm + mf * 16 + g    ][t];
                af[mf][1] = As[buf][wm + mf * 16 + g + 8][t];
                af[mf][2] = As[buf][wm + mf * 16 + g    ][t + 4];
                af[mf][3] = As[buf][wm + mf * 16 + g + 8][t + 4];
            }
#pragma unroll
            for (int nf = 0; nf < 4; nf++) {
                bf[nf][0] = Bs[buf][wn + nf * 8 + g][t];
                bf[nf][1] = Bs[buf][wn + nf * 8 + g][t + 4];
            }
#pragma unroll
            for (int mf = 0; mf < 4; mf++)
#pragma unroll
                for (int nf = 0; nf < 4; nf++)
                    mma16bf(acc[mf][nf], af[mf], bf[nf]);
        }

        {
            uint32_t* as = &As[buf ^ 1][r_ld][c_ld >> 1];
            uint32_t* bs = &Bs[buf ^ 1][r_ld][c_ld >> 1];
            as[0] = packbf(pa0.x, pa0.y); as[1] = packbf(pa0.z, pa0.w);
            bs[0] = packbf(pb0.x, pb0.y); bs[1] = packbf(pb0.z, pb0.w);
            uint32_t* as2 = &As[buf ^ 1][r_ld + 64][c_ld >> 1];
            uint32_t* bs2 = &Bs[buf ^ 1][r_ld + 64][c_ld >> 1];
            as2[0] = packbf(pa1.x, pa1.y); as2[1] = packbf(pa1.z, pa1.w);
            bs2[0] = packbf(pb1.x, pb1.y); bs2[1] = packbf(pb1.z, pb1.w);
        }
        __syncthreads();
        buf ^= 1;
    }

    {
        uint32_t af[4][4], bf[4][2];
#pragma unroll
        for (int mf = 0; mf < 4; mf++) {
            af[mf][0] = As[buf][wm + mf * 16 + g    ][t];
            af[mf][1] = As[buf][wm + mf * 16 + g + 8][t];
            af[mf][2] = As[buf][wm + mf * 16 + g    ][t + 4];
            af[mf][3] = As[buf][wm + mf * 16 + g + 8][t + 4];
        }
#pragma unroll
        for (int nf = 0; nf < 4; nf++) {
            bf[nf][0] = Bs[buf][wn + nf * 8 + g][t];
            bf[nf][1] = Bs[buf][wn + nf * 8 + g][t + 4];
        }
#pragma unroll
        for (int mf = 0; mf < 4; mf++)
#pragma unroll
            for (int nf = 0; nf < 4; nf++)
                mma16bf(acc[mf][nf], af[mf], bf[nf]);
    }

#pragma unroll
    for (int mf = 0; mf < 4; mf++) {
        int row = m0 + wm + mf * 16 + g;
#pragma unroll
        for (int nf = 0; nf < 4; nf++) {
            int col = n0 + wn + nf * 8 + 2 * t;
            float b0 = bias[col], b1 = bias[col + 1];
            float4 v = acc[mf][nf];
            float2 lo = make_float2(v.x + b0, v.y + b1);
            float2 hi = make_float2(v.z + b0, v.w + b1);
            if (relu) {
                lo.x = fmaxf(lo.x, 0.f); lo.y = fmaxf(lo.y, 0.f);
                hi.x = fmaxf(hi.x, 0.f); hi.y = fmaxf(hi.y, 0.f);
            }
            *(float2*)&C[(size_t)row * N + col]       = lo;
            *(float2*)&C[(size_t)(row + 8) * N + col] = hi;
        }
    }
}

// ------------------------- tensor-core flash attention -----------------------
// grid (8, 32), 256 thr = 8 warps; warp = 16 q-rows x 64 keys (R10 config).
__global__ __launch_bounds__(256) void flash_attn_mma(
    const float* __restrict__ qkproj, const float* __restrict__ vsrc,
    float* __restrict__ O)
{
    __shared__ uint32_t sm[8064];
    uint32_t* Ks = sm;              // [64][36] tf32
    uint32_t* Vs = sm + 2304;      // [32][36] bf16 pairs
    uint32_t* Ps = sm + 3456;      // [8][16][36] bf16 pairs per warp
    uint32_t* Qstage = sm;         // overlay [128][36] (pre-loop only)

    const int bh = blockIdx.y, b = bh >> 3, h = bh & 7;
    const int q0 = blockIdx.x * 128;
    const int tid = threadIdx.x, warp = tid >> 5, lane = tid & 31;
    const int g = lane >> 2, t = lane & 3;
    const float SC = 0.1767766952966368932f;

    const float* qp = qkproj + (size_t)b * LQd * 512 + h * DHd;
    const float* kp = qp + 256;
    const float* vp = vsrc + (size_t)b * LQd * CCd + h * DHd;

#pragma unroll
    for (int i = 0; i < 16; i++) {
        int idx = tid + i * 256;
        int row = idx >> 5, d = idx & 31;
        Qstage[row * 36 + d] = f2tf32(qp[(size_t)(q0 + row) * 512 + d] * SC);
    }
    __syncthreads();
    uint32_t qf[4][4];
#pragma unroll
    for (int kc = 0; kc < 4; kc++) {
        int r = (warp * 16 + g) * 36;
        qf[kc][0] = Qstage[r + kc * 8 + t];
        qf[kc][1] = Qstage[r + 8 * 36 + kc * 8 + t];
        qf[kc][2] = Qstage[r + kc * 8 + t + 4];
        qf[kc][3] = Qstage[r + 8 * 36 + kc * 8 + t + 4];
    }

    uint32_t* Pw = Ps + warp * 16 * 36;
    float m0r = -1e30f, m1r = -1e30f, l0r = 0.f, l1r = 0.f;
    float4 oacc[4];
#pragma unroll
    for (int i = 0; i < 4; i++) oacc[i] = make_float4(0.f, 0.f, 0.f, 0.f);

    for (int kt = 0; kt < 16; kt++) {
        const float* kbase = kp + (size_t)kt * 64 * 512;
        const float* vbase = vp + (size_t)kt * 64 * 256;
        __syncthreads();
#pragma unroll
        for (int i = 0; i < 8; i++) {
            int idx = tid + i * 256;
            int key = idx >> 5, d = idx & 31;
            Ks[key * 36 + d] = f2tf32(kbase[(size_t)key * 512 + d]);
        }
#pragma unroll
        for (int i = 0; i < 4; i++) {
            int idx = tid + i * 256;
            int kpair = idx >> 5, d = idx & 31;
            float v0 = vbase[(size_t)(2 * kpair) * 256 + d];
            float v1 = vbase[(size_t)(2 * kpair + 1) * 256 + d];
            Vs[d * 36 + kpair] = packbf(v0, v1);
        }
        __syncthreads();

        float4 sacc[8];
#pragma unroll
        for (int nf = 0; nf < 8; nf++) sacc[nf] = make_float4(0.f, 0.f, 0.f, 0.f);
#pragma unroll
        for (int nf = 0; nf < 8; nf++) {
#pragma unroll
            for (int kc = 0; kc < 4; kc++) {
                uint32_t bfr[2];
                bfr[0] = Ks[(nf * 8 + g) * 36 + kc * 8 + t];
                bfr[1] = Ks[(nf * 8 + g) * 36 + kc * 8 + t + 4];
                mma8(sacc[nf], qf[kc], bfr);
            }
        }

        float mx0 = -1e30f, mx1 = -1e30f;
#pragma unroll
        for (int nf = 0; nf < 8; nf++) {
            mx0 = fmaxf(mx0, fmaxf(sacc[nf].x, sacc[nf].y));
            mx1 = fmaxf(mx1, fmaxf(sacc[nf].z, sacc[nf].w));
        }
        mx0 = fmaxf(mx0, __shfl_xor_sync(0xffffffffu, mx0, 1));
        mx0 = fmaxf(mx0, __shfl_xor_sync(0xffffffffu, mx0, 2));
        mx1 = fmaxf(mx1, __shfl_xor_sync(0xffffffffu, mx1, 1));
        mx1 = fmaxf(mx1, __shfl_xor_sync(0xffffffffu, mx1, 2));
        float mn0 = fmaxf(m0r, mx0), mn1 = fmaxf(m1r, mx1);
        float cf0 = __expf(m0r - mn0), cf1 = __expf(m1r - mn1);
        float rs0 = 0.f, rs1 = 0.f;
#pragma unroll
        for (int nf = 0; nf < 8; nf++) {
            float p0 = __expf(sacc[nf].x - mn0);
            float p1 = __expf(sacc[nf].y - mn0);
            float p2 = __expf(sacc[nf].z - mn1);
            float p3 = __expf(sacc[nf].w - mn1);
            rs0 += p0 + p1; rs1 += p2 + p3;
            Pw[(g    ) * 36 + nf * 4 + t] = packbf(p0, p1);
            Pw[(g + 8) * 36 + nf * 4 + t] = packbf(p2, p3);
        }
        rs0 += __shfl_xor_sync(0xffffffffu, rs0, 1);
        rs0 += __shfl_xor_sync(0xffffffffu, rs0, 2);
        rs1 += __shfl_xor_sync(0xffffffffu, rs1, 1);
        rs1 += __shfl_xor_sync(0xffffffffu, rs1, 2);
        l0r = l0r * cf0 + rs0; l1r = l1r * cf1 + rs1;
        m0r = mn0; m1r = mn1;
#pragma unroll
        for (int nf = 0; nf < 4; nf++) {
            oacc[nf].x *= cf0; oacc[nf].y *= cf0;
            oacc[nf].z *= cf1; oacc[nf].w *= cf1;
        }
        __syncwarp();

#pragma unroll
        for (int kc = 0; kc < 4; kc++) {
            uint32_t af[4];
            af[0] = Pw[(g    ) * 36 + kc * 8 + t];
            af[1] = Pw[(g + 8) * 36 + kc * 8 + t];
            af[2] = Pw[(g    ) * 36 + kc * 8 + t + 4];
            af[3] = Pw[(g + 8) * 36 + kc * 8 + t + 4];
#pragma unroll
            for (int nf = 0; nf < 4; nf++) {
                uint32_t bfr[2];
                bfr[0] = Vs[(nf * 8 + g) * 36 + kc * 8 + t];
                bfr[1] = Vs[(nf * 8 + g) * 36 + kc * 8 + t + 4];
                mma16bf(oacc[nf], af, bfr);
            }
        }
    }

    float inv0 = 1.f / l0r, inv1 = 1.f / l1r;
    int row = q0 + warp * 16 + g;
#pragma unroll
    for (int nf = 0; nf < 4; nf++) {
        int col = h * DHd + nf * 8 + 2 * t;
        *(float2*)&O[(size_t)(b * LQd + row) * CCd + col] =
            make_float2(oacc[nf].x * inv0, oacc[nf].y * inv0);
        *(float2*)&O[(size_t)(b * LQd + row + 8) * CCd + col] =
            make_float2(oacc[nf].z * inv1, oacc[nf].w * inv1);
    }
}

// ------------------------- multi-scale deformable sampling (+fused softmax) --
__global__ void deform_sample(const float* __restrict__ value, const float* __restrict__ ref,
                              const float* __restrict__ offaw, float* __restrict__ out)
{
    const int levH[4] = {128, 64, 32, 16};
    const int levW[4] = {128, 64, 32, 16};
    const int levS[4] = {0, 16384, 20480, 21504};
    int bq = blockIdx.x;
    int b  = bq >> 10;
    int h  = threadIdx.x >> 5;
    int d  = threadIdx.x & 31;

    // fused softmax over the 16 attention logits for (bq,h)
    const float* ap = offaw + (size_t)bq * 384 + 256 + h * 16;
    float awv[16];
    float mxa = -1e30f;
#pragma unroll
    for (int i = 0; i < 16; i++) { awv[i] = ap[i]; mxa = fmaxf(mxa, awv[i]); }
    float sa = 0.f;
#pragma unroll
    for (int i = 0; i < 16; i++) { awv[i] = __expf(awv[i] - mxa); sa += awv[i]; }
    float inva = 1.f / sa;

    float acc = 0.f;
#pragma unroll
    for (int l = 0; l < 4; l++) {
        float rx = ref[((size_t)bq * LLd + l) * 2 + 0];
        float ry = ref[((size_t)bq * LLd + l) * 2 + 1];
        int w = levW[l], hh = levH[l], st = levS[l];
        float fw = (float)w, fh = (float)hh;
#pragma unroll
        for (int p = 0; p < 4; p++) {
            size_t oidx = (size_t)bq * 384 + h * 32 + (l * 4 + p) * 2;
            float lx = rx + offaw[oidx]     / fw;
            float ly = ry + offaw[oidx + 1] / fh;
            float x = lx * fw - 0.5f;
            float y = ly * fh - 0.5f;
            float x0f = floorf(x), y0f = floorf(y);
            int x0 = (int)x0f, y0 = (int)y0f;
            float wx1 = x - x0f, wx0 = 1.f - wx1;
            float wy1 = y - y0f, wy0 = 1.f - wy1;
            float a = awv[l * 4 + p] * inva;
            float s = 0.f;
#pragma unroll
            for (int cy = 0; cy < 2; cy++) {
#pragma unroll
                for (int cx = 0; cx < 2; cx++) {
                    int ix = x0 + cx, iy = y0 + cy;
                    if (ix >= 0 && ix < w && iy >= 0 && iy < hh) {
                        float wgt = (cx ? wx1 : wx0) * (cy ? wy1 : wy0);
                        size_t vidx = (((size_t)(b * LSRCd + st + iy * w + ix)) * HHd + h) * DHd + d;
                        s += wgt * value[vidx];
                    }
                }
            }
            acc += a * s;
        }
    }
    out[(size_t)bq * CCd + h * DHd + d] = acc;
}

// ------------------------- launch --------------------------------------------
extern "C" void kernel_launch(void* const* d_in, const int* in_sizes, int n_in,
                              void* d_out, int out_size)
{
    (void)in_sizes; (void)n_in; (void)out_size;
    const float* tgt   = (const float*)d_in[0];
    const float* qpos  = (const float*)d_in[1];
    const float* ref   = (const float*)d_in[2];
    const float* src   = (const float*)d_in[3];
    const float* in_w  = (const float*)d_in[4];
    const float* in_b  = (const float*)d_in[5];
    const float* sa_w  = (const float*)d_in[6];
    const float* sa_b  = (const float*)d_in[7];
    const float* off_w = (const float*)d_in[8];
    const float* off_b = (const float*)d_in[9];
    const float* aw_w  = (const float*)d_in[10];
    const float* aw_b  = (const float*)d_in[11];
    const float* val_w = (const float*)d_in[12];
    const float* val_b = (const float*)d_in[13];
    const float* co_w  = (const float*)d_in[14];
    const float* co_b  = (const float*)d_in[15];
    const float* ln1_g = (const float*)d_in[16];
    const float* ln1_b = (const float*)d_in[17];
    const float* ln2_g = (const float*)d_in[18];
    const float* ln2_b = (const float*)d_in[19];
    const float* ln3_g = (const float*)d_in[20];
    const float* ln3_b = (const float*)d_in[21];
    const float* f1_w  = (const float*)d_in[22];
    const float* f1_b  = (const float*)d_in[23];
    const float* f2_w  = (const float*)d_in[24];
    const float* f2_b  = (const float*)d_in[25];
    float* out = (float*)d_out;

    float *qkproj, *v, *o, *tgt1, *value, *offaw, *woffaw, *boffaw, *samp, *tgt2, *ffn;
    cudaGetSymbolAddress((void**)&qkproj, g_qkproj);
    cudaGetSymbolAddress((void**)&v,      g_v);
    cudaGetSymbolAddress((void**)&o,      g_o);
    cudaGetSymbolAddress((void**)&tgt1,   g_tgt1);
    cudaGetSymbolAddress((void**)&value,  g_value);
    cudaGetSymbolAddress((void**)&offaw,  g_offaw);
    cudaGetSymbolAddress((void**)&woffaw, g_woffaw);
    cudaGetSymbolAddress((void**)&boffaw, g_boffaw);
    cudaGetSymbolAddress((void**)&samp,   g_samp);
    cudaGetSymbolAddress((void**)&tgt2,   g_tgt2);
    cudaGetSymbolAddress((void**)&ffn,    g_ffn);

    static cudaStream_t sv = nullptr, sw = nullptr;
    static cudaEvent_t evRoot = nullptr, evV = nullptr, evVal = nullptr, evW = nullptr;
    if (!sv) {
        cudaStreamCreateWithFlags(&sv, cudaStreamNonBlocking);
        cudaStreamCreateWithFlags(&sw, cudaStreamNonBlocking);
        cudaEventCreateWithFlags(&evRoot, cudaEventDisableTiming);
        cudaEventCreateWithFlags(&evV,    cudaEventDisableTiming);
        cudaEventCreateWithFlags(&evVal,  cudaEventDisableTiming);
        cudaEventCreateWithFlags(&evW,    cudaEventDisableTiming);
    }

    cudaEventRecord(evRoot, 0);

    // stream sw: weight concat + big value GEMM (hidden under self-attn)
    cudaStreamWaitEvent(sw, evRoot, 0);
    cudaMemcpyAsync(woffaw,             off_w, 256 * 256 * sizeof(float), cudaMemcpyDeviceToDevice, sw);
    cudaMemcpyAsync(woffaw + 256 * 256, aw_w,  128 * 256 * sizeof(float), cudaMemcpyDeviceToDevice, sw);
    cudaMemcpyAsync(boffaw,             off_b, 256 * sizeof(float),       cudaMemcpyDeviceToDevice, sw);
    cudaMemcpyAsync(boffaw + 256,       aw_b,  128 * sizeof(float),       cudaMemcpyDeviceToDevice, sw);
    cudaEventRecord(evW, sw);
    gemm_bf16<<<dim3(2, 680), 256, 0, sw>>>(src, val_w, val_b, value, BB * LSRCd, CCd, CCd, 0);
    cudaEventRecord(evVal, sw);

    // stream sv: V projection (overlaps qkproj)
    cudaStreamWaitEvent(sv, evRoot, 0);
    gemm_tf32_64<<<dim3(4, 64), 128, 0, sv>>>(tgt, nullptr, in_w + 2 * CCd * CCd, in_b + 2 * CCd, v, BQd, CCd, CCd, 0);
    cudaEventRecord(evV, sv);

    // ---- main stream: self-attention ----
    gemm_tf32_64<<<dim3(8, 64), 128>>>(tgt, qpos, in_w, in_b, qkproj, BQd, 512, CCd, 0);
    cudaStreamWaitEvent(0, evV, 0);
    flash_attn_mma<<<dim3(8, 32), 256>>>(qkproj, v, o);
    gemm_ln_tf32<<<BQd / 16, 256>>>(o, sa_w, sa_b, tgt, ln2_g, ln2_b, tgt1, CCd);

    // ---- deformable cross-attention ----
    cudaStreamWaitEvent(0, evW, 0);
    gemm_tf32_64<<<dim3(6, 64), 128>>>(tgt1, qpos, woffaw, boffaw, offaw, BQd, 384, CCd, 0);
    cudaStreamWaitEvent(0, evVal, 0);
    deform_sample<<<BQd, 256>>>(value, ref, offaw, samp);
    gemm_ln_tf32<<<BQd / 16, 256>>>(samp, co_w, co_b, tgt1, ln1_g, ln1_b, tgt2, CCd);

    // ---- FFN ----
    gemm_bf16<<<dim3(8, 32), 256>>>(tgt2, f1_w, f1_b, ffn, BQd, DFFd, CCd, 1);
    gemm_ln_tf32<<<BQd / 16, 256>>>(ffn, f2_w, f2_b, tgt2, ln3_g, ln3_b, out, DFFd);
}

// round 14
// speedup vs baseline: 1.5618x; 1.0120x over previous
#include <cuda_runtime.h>
#include <cuda_bf16.h>
#include <math.h>
#include <stdint.h>

#define BB   4
#define LQd  1024
#define CCd  256
#define HHd  8
#define DHd  32
#define LLd  4
#define PPd  4
#define DFFd 1024
#define LSRCd 21760
#define BQd  (BB*LQd)   // 4096

// ------------------------- scratch (device globals; no allocs) ---------------
__device__ float g_qkproj[BQd*512];
__device__ float g_v     [BQd*CCd];
__device__ float g_o     [BQd*CCd];
__device__ float g_tgt1  [BQd*CCd];
__device__ __nv_bfloat16 g_valbf[(size_t)BB*LSRCd*CCd];   // 44.5 MB bf16 value
__device__ float g_offaw [BQd*384];
__device__ float g_woffaw[384*CCd];
__device__ float g_boffaw[384];
__device__ float g_samp  [BQd*CCd];
__device__ float g_tgt2  [BQd*CCd];
__device__ float g_ffn   [BQd*DFFd];

// ------------------------- mma helpers ---------------------------------------
__device__ __forceinline__ uint32_t f2tf32(float x) {
    uint32_t r;
    asm("cvt.rna.tf32.f32 %0, %1;" : "=r"(r) : "f"(x));
    return r;
}

__device__ __forceinline__ void mma8(float4& d, const uint32_t* a, const uint32_t* b) {
    asm volatile("mma.sync.aligned.m16n8k8.row.col.f32.tf32.tf32.f32 "
                 "{%0,%1,%2,%3}, {%4,%5,%6,%7}, {%8,%9}, {%0,%1,%2,%3};"
                 : "+f"(d.x), "+f"(d.y), "+f"(d.z), "+f"(d.w)
                 : "r"(a[0]), "r"(a[1]), "r"(a[2]), "r"(a[3]),
                   "r"(b[0]), "r"(b[1]));
}

__device__ __forceinline__ void mma16bf(float4& d, const uint32_t* a, const uint32_t* b) {
    asm volatile("mma.sync.aligned.m16n8k16.row.col.f32.bf16.bf16.f32 "
                 "{%0,%1,%2,%3}, {%4,%5,%6,%7}, {%8,%9}, {%0,%1,%2,%3};"
                 : "+f"(d.x), "+f"(d.y), "+f"(d.z), "+f"(d.w)
                 : "r"(a[0]), "r"(a[1]), "r"(a[2]), "r"(a[3]),
                   "r"(b[0]), "r"(b[1]));
}

__device__ __forceinline__ uint32_t packbf(float x, float y) {
    __nv_bfloat162 h = __floats2bfloat162_rn(x, y);
    return *reinterpret_cast<uint32_t*>(&h);
}

// ------------------------- TF32 GEMM, 64x64 tile, 128 threads ----------------
#define TSTR 20

__global__ __launch_bounds__(128) void gemm_tf32_64(
    const float* __restrict__ A, const float* __restrict__ A2,
    const float* __restrict__ W,
    const float* __restrict__ bias, float* __restrict__ C,
    int M, int N, int K, int relu)
{
    __shared__ uint32_t As[2][64][TSTR];
    __shared__ uint32_t Bs[2][64][TSTR];
    const int tid  = threadIdx.x;
    const int warp = tid >> 5, lane = tid & 31;
    const int g = lane >> 2, t = lane & 3;
    const int wm = (warp >> 1) * 32, wn = (warp & 1) * 32;
    const int m0 = blockIdx.y * 64, n0 = blockIdx.x * 64;
    const int r_ld = tid >> 2, c_ld = (tid & 3) * 4;

    const float* Ap  = A + (size_t)(m0 + r_ld) * K + c_ld;
    const float* Ap2 = A2 ? A2 + (size_t)(m0 + r_ld) * K + c_ld : nullptr;
    const float* Wp  = W + (size_t)(n0 + r_ld) * K + c_ld;

    float4 acc[2][4];
#pragma unroll
    for (int i = 0; i < 2; i++)
#pragma unroll
        for (int j = 0; j < 4; j++) acc[i][j] = make_float4(0.f, 0.f, 0.f, 0.f);

#pragma unroll
    for (int i = 0; i < 2; i++) {
        float4 a = *(const float4*)(Ap + (size_t)(32 * i) * K);
        if (Ap2) {
            float4 a2 = *(const float4*)(Ap2 + (size_t)(32 * i) * K);
            a.x += a2.x; a.y += a2.y; a.z += a2.z; a.w += a2.w;
        }
        float4 b = *(const float4*)(Wp + (size_t)(32 * i) * K);
        uint32_t* as = &As[0][r_ld + 32 * i][c_ld];
        uint32_t* bs = &Bs[0][r_ld + 32 * i][c_ld];
        as[0] = f2tf32(a.x); as[1] = f2tf32(a.y); as[2] = f2tf32(a.z); as[3] = f2tf32(a.w);
        bs[0] = f2tf32(b.x); bs[1] = f2tf32(b.y); bs[2] = f2tf32(b.z); bs[3] = f2tf32(b.w);
    }
    __syncthreads();

    int buf = 0;
    for (int k0 = 16; k0 < K; k0 += 16) {
        float4 pa0 = *(const float4*)(Ap + k0);
        float4 pa1 = *(const float4*)(Ap + (size_t)32 * K + k0);
        if (Ap2) {
            float4 q0v = *(const float4*)(Ap2 + k0);
            float4 q1v = *(const float4*)(Ap2 + (size_t)32 * K + k0);
            pa0.x += q0v.x; pa0.y += q0v.y; pa0.z += q0v.z; pa0.w += q0v.w;
            pa1.x += q1v.x; pa1.y += q1v.y; pa1.z += q1v.z; pa1.w += q1v.w;
        }
        float4 pb0 = *(const float4*)(Wp + k0);
        float4 pb1 = *(const float4*)(Wp + (size_t)32 * K + k0);

#pragma unroll
        for (int ks = 0; ks < 2; ks++) {
            const int kk = ks * 8;
            uint32_t af[2][4], bf[4][2];
#pragma unroll
            for (int mf = 0; mf < 2; mf++) {
                af[mf][0] = As[buf][wm + mf * 16 + g    ][kk + t];
                af[mf][1] = As[buf][wm + mf * 16 + g + 8][kk + t];
                af[mf][2] = As[buf][wm + mf * 16 + g    ][kk + t + 4];
                af[mf][3] = As[buf][wm + mf * 16 + g + 8][kk + t + 4];
            }
#pragma unroll
            for (int nf = 0; nf < 4; nf++) {
                bf[nf][0] = Bs[buf][wn + nf * 8 + g][kk + t];
                bf[nf][1] = Bs[buf][wn + nf * 8 + g][kk + t + 4];
            }
#pragma unroll
            for (int mf = 0; mf < 2; mf++)
#pragma unroll
                for (int nf = 0; nf < 4; nf++)
                    mma8(acc[mf][nf], af[mf], bf[nf]);
        }

        {
            uint32_t* as = &As[buf ^ 1][r_ld][c_ld];
            uint32_t* bs = &Bs[buf ^ 1][r_ld][c_ld];
            as[0] = f2tf32(pa0.x); as[1] = f2tf32(pa0.y); as[2] = f2tf32(pa0.z); as[3] = f2tf32(pa0.w);
            bs[0] = f2tf32(pb0.x); bs[1] = f2tf32(pb0.y); bs[2] = f2tf32(pb0.z); bs[3] = f2tf32(pb0.w);
            uint32_t* as2 = &As[buf ^ 1][r_ld + 32][c_ld];
            uint32_t* bs2 = &Bs[buf ^ 1][r_ld + 32][c_ld];
            as2[0] = f2tf32(pa1.x); as2[1] = f2tf32(pa1.y); as2[2] = f2tf32(pa1.z); as2[3] = f2tf32(pa1.w);
            bs2[0] = f2tf32(pb1.x); bs2[1] = f2tf32(pb1.y); bs2[2] = f2tf32(pb1.z); bs2[3] = f2tf32(pb1.w);
        }
        __syncthreads();
        buf ^= 1;
    }

#pragma unroll
    for (int ks = 0; ks < 2; ks++) {
        const int kk = ks * 8;
        uint32_t af[2][4], bf[4][2];
#pragma unroll
        for (int mf = 0; mf < 2; mf++) {
            af[mf][0] = As[buf][wm + mf * 16 + g    ][kk + t];
            af[mf][1] = As[buf][wm + mf * 16 + g + 8][kk + t];
            af[mf][2] = As[buf][wm + mf * 16 + g    ][kk + t + 4];
            af[mf][3] = As[buf][wm + mf * 16 + g + 8][kk + t + 4];
        }
#pragma unroll
        for (int nf = 0; nf < 4; nf++) {
            bf[nf][0] = Bs[buf][wn + nf * 8 + g][kk + t];
            bf[nf][1] = Bs[buf][wn + nf * 8 + g][kk + t + 4];
        }
#pragma unroll
        for (int mf = 0; mf < 2; mf++)
#pragma unroll
            for (int nf = 0; nf < 4; nf++)
                mma8(acc[mf][nf], af[mf], bf[nf]);
    }

#pragma unroll
    for (int mf = 0; mf < 2; mf++) {
        int row = m0 + wm + mf * 16 + g;
#pragma unroll
        for (int nf = 0; nf < 4; nf++) {
            int col = n0 + wn + nf * 8 + 2 * t;
            float b0 = bias[col], b1 = bias[col + 1];
            float4 v = acc[mf][nf];
            float2 lo = make_float2(v.x + b0, v.y + b1);
            float2 hi = make_float2(v.z + b0, v.w + b1);
            if (relu) {
                lo.x = fmaxf(lo.x, 0.f); lo.y = fmaxf(lo.y, 0.f);
                hi.x = fmaxf(hi.x, 0.f); hi.y = fmaxf(hi.y, 0.f);
            }
            *(float2*)&C[(size_t)row * N + col]       = lo;
            *(float2*)&C[(size_t)(row + 8) * N + col] = hi;
        }
    }
}

// ------------------------- fused TF32 GEMM + residual + LayerNorm ------------
__global__ __launch_bounds__(256) void gemm_ln_tf32(
    const float* __restrict__ A, const float* __restrict__ W,
    const float* __restrict__ bias, const float* __restrict__ res,
    const float* __restrict__ gamma, const float* __restrict__ beta,
    float* __restrict__ C, int K)
{
    __shared__ uint32_t As[2][16][TSTR];
    __shared__ uint32_t Bs[2][256][TSTR];
    __shared__ float    Cs[16][260];
    const int tid  = threadIdx.x;
    const int warp = tid >> 5, lane = tid & 31;
    const int g = lane >> 2, t = lane & 3;
    const int m0 = blockIdx.x * 16;
    const int ra = tid >> 2, ca = (tid & 3) * 4;

    float4 acc[4];
#pragma unroll
    for (int j = 0; j < 4; j++) acc[j] = make_float4(0.f, 0.f, 0.f, 0.f);

    if (tid < 64) {
        float4 a = *(const float4*)(A + (size_t)(m0 + ra) * K + ca);
        uint32_t* as = &As[0][ra][ca];
        as[0] = f2tf32(a.x); as[1] = f2tf32(a.y); as[2] = f2tf32(a.z); as[3] = f2tf32(a.w);
    }
#pragma unroll
    for (int i = 0; i < 4; i++) {
        int r = ra + 64 * i;
        float4 b = *(const float4*)(W + (size_t)r * K + ca);
        uint32_t* bs = &Bs[0][r][ca];
        bs[0] = f2tf32(b.x); bs[1] = f2tf32(b.y); bs[2] = f2tf32(b.z); bs[3] = f2tf32(b.w);
    }
    __syncthreads();

    int buf = 0;
    for (int k0 = 16; k0 < K; k0 += 16) {
        float4 pa = make_float4(0.f, 0.f, 0.f, 0.f);
        if (tid < 64) pa = *(const float4*)(A + (size_t)(m0 + ra) * K + k0 + ca);
        float4 pb[4];
#pragma unroll
        for (int i = 0; i < 4; i++)
            pb[i] = *(const float4*)(W + (size_t)(ra + 64 * i) * K + k0 + ca);

#pragma unroll
        for (int ks = 0; ks < 2; ks++) {
            const int kk = ks * 8;
            uint32_t af[4], bf[4][2];
            af[0] = As[buf][g    ][kk + t];
            af[1] = As[buf][g + 8][kk + t];
            af[2] = As[buf][g    ][kk + t + 4];
            af[3] = As[buf][g + 8][kk + t + 4];
#pragma unroll
            for (int nf = 0; nf < 4; nf++) {
                bf[nf][0] = Bs[buf][warp * 32 + nf * 8 + g][kk + t];
                bf[nf][1] = Bs[buf][warp * 32 + nf * 8 + g][kk + t + 4];
            }
#pragma unroll
            for (int nf = 0; nf < 4; nf++)
                mma8(acc[nf], af, bf[nf]);
        }

        if (tid < 64) {
            uint32_t* as = &As[buf ^ 1][ra][ca];
            as[0] = f2tf32(pa.x); as[1] = f2tf32(pa.y); as[2] = f2tf32(pa.z); as[3] = f2tf32(pa.w);
        }
#pragma unroll
        for (int i = 0; i < 4; i++) {
            uint32_t* bs = &Bs[buf ^ 1][ra + 64 * i][ca];
            bs[0] = f2tf32(pb[i].x); bs[1] = f2tf32(pb[i].y); bs[2] = f2tf32(pb[i].z); bs[3] = f2tf32(pb[i].w);
        }
        __syncthreads();
        buf ^= 1;
    }

#pragma unroll
    for (int ks = 0; ks < 2; ks++) {
        const int kk = ks * 8;
        uint32_t af[4], bf[4][2];
        af[0] = As[buf][g    ][kk + t];
        af[1] = As[buf][g + 8][kk + t];
        af[2] = As[buf][g    ][kk + t + 4];
        af[3] = As[buf][g + 8][kk + t + 4];
#pragma unroll
        for (int nf = 0; nf < 4; nf++) {
            bf[nf][0] = Bs[buf][warp * 32 + nf * 8 + g][kk + t];
            bf[nf][1] = Bs[buf][warp * 32 + nf * 8 + g][kk + t + 4];
        }
#pragma unroll
        for (int nf = 0; nf < 4; nf++)
            mma8(acc[nf], af, bf[nf]);
    }

#pragma unroll
    for (int nf = 0; nf < 4; nf++) {
        int col = warp * 32 + nf * 8 + 2 * t;
        float b0 = bias[col], b1 = bias[col + 1];
        Cs[g    ][col]     = acc[nf].x + b0 + res[(size_t)(m0 + g) * 256 + col];
        Cs[g    ][col + 1] = acc[nf].y + b1 + res[(size_t)(m0 + g) * 256 + col + 1];
        Cs[g + 8][col]     = acc[nf].z + b0 + res[(size_t)(m0 + g + 8) * 256 + col];
        Cs[g + 8][col + 1] = acc[nf].w + b1 + res[(size_t)(m0 + g + 8) * 256 + col + 1];
    }
    __syncthreads();

    {
        int row = tid >> 4, sub = tid & 15;
        float vals[16];
        float s = 0.f, sq = 0.f;
#pragma unroll
        for (int j = 0; j < 16; j++) {
            float x = Cs[row][sub + 16 * j];
            vals[j] = x; s += x; sq += x * x;
        }
#pragma unroll
        for (int m = 1; m < 16; m <<= 1) {
            s  += __shfl_xor_sync(0xffffffffu, s,  m, 16);
            sq += __shfl_xor_sync(0xffffffffu, sq, m, 16);
        }
        float mean = s * (1.f / 256.f);
        float var  = sq * (1.f / 256.f) - mean * mean;
        float inv  = rsqrtf(var + 1e-5f);
#pragma unroll
        for (int j = 0; j < 16; j++) {
            int col = sub + 16 * j;
            C[(size_t)(m0 + row) * 256 + col] =
                (vals[j] - mean) * inv * gamma[col] + beta[col];
        }
    }
}

// ------------------------- BF16 tensor-core GEMM (128x128), fp32 out ---------
__global__ __launch_bounds__(256) void gemm_bf16(
    const float* __restrict__ A, const float* __restrict__ W,
    const float* __restrict__ bias, float* __restrict__ C,
    int M, int N, int K, int relu)
{
    __shared__ uint32_t As[2][128][12];
    __shared__ uint32_t Bs[2][128][12];
    const int tid  = threadIdx.x;
    const int warp = tid >> 5, lane = tid & 31;
    const int g = lane >> 2, t = lane & 3;
    const int wm = (warp >> 2) * 64, wn = (warp & 3) * 32;
    const int m0 = blockIdx.y * 128, n0 = blockIdx.x * 128;
    const int r_ld = tid >> 2, c_ld = (tid & 3) * 4;

    const float* Ap = A + (size_t)(m0 + r_ld) * K + c_ld;
    const float* Wp = W + (size_t)(n0 + r_ld) * K + c_ld;

    float4 acc[4][4];
#pragma unroll
    for (int i = 0; i < 4; i++)
#pragma unroll
        for (int j = 0; j < 4; j++) acc[i][j] = make_float4(0.f, 0.f, 0.f, 0.f);

#pragma unroll
    for (int i = 0; i < 2; i++) {
        float4 a = *(const float4*)(Ap + (size_t)(64 * i) * K);
        float4 b = *(const float4*)(Wp + (size_t)(64 * i) * K);
        uint32_t* as = &As[0][r_ld + 64 * i][c_ld >> 1];
        uint32_t* bs = &Bs[0][r_ld + 64 * i][c_ld >> 1];
        as[0] = packbf(a.x, a.y); as[1] = packbf(a.z, a.w);
        bs[0] = packbf(b.x, b.y); bs[1] = packbf(b.z, b.w);
    }
    __syncthreads();

    int buf = 0;
    for (int k0 = 16; k0 < K; k0 += 16) {
        float4 pa0 = *(const float4*)(Ap + k0);
        float4 pa1 = *(const float4*)(Ap + (size_t)64 * K + k0);
        float4 pb0 = *(const float4*)(Wp + k0);
        float4 pb1 = *(const float4*)(Wp + (size_t)64 * K + k0);

        {
            uint32_t af[4][4], bf[4][2];
#pragma unroll
            for (int mf = 0; mf < 4; mf++) {
                af[mf][0] = As[buf][wm + mf * 16 + g    ][t];
                af[mf][1] = As[buf][wm + mf * 16 + g + 8][t];
                af[mf][2] = As[buf][wm + mf * 16 + g    ][t + 4];
                af[mf][3] = As[buf][wm + mf * 16 + g + 8][t + 4];
            }
#pragma unroll
            for (int nf = 0; nf < 4; nf++) {
                bf[nf][0] = Bs[buf][wn + nf * 8 + g][t];
                bf[nf][1] = Bs[buf][wn + nf * 8 + g][t + 4];
            }
#pragma unroll
            for (int mf = 0; mf < 4; mf++)
#pragma unroll
                for (int nf = 0; nf < 4; nf++)
                    mma16bf(acc[mf][nf], af[mf], bf[nf]);
        }

        {
            uint32_t* as = &As[buf ^ 1][r_ld][c_ld >> 1];
            uint32_t* bs = &Bs[buf ^ 1][r_ld][c_ld >> 1];
            as[0] = packbf(pa0.x, pa0.y); as[1] = packbf(pa0.z, pa0.w);
            bs[0] = packbf(pb0.x, pb0.y); bs[1] = packbf(pb0.z, pb0.w);
            uint32_t* as2 = &As[buf ^ 1][r_ld + 64][c_ld >> 1];
            uint32_t* bs2 = &Bs[buf ^ 1][r_ld + 64][c_ld >> 1];
            as2[0] = packbf(pa1.x, pa1.y); as2[1] = packbf(pa1.z, pa1.w);
            bs2[0] = packbf(pb1.x, pb1.y); bs2[1] = packbf(pb1.z, pb1.w);
        }
        __syncthreads();
        buf ^= 1;
    }

    {
        uint32_t af[4][4], bf[4][2];
#pragma unroll
        for (int mf = 0; mf < 4; mf++) {
            af[mf][0] = As[buf][wm + mf * 16 + g    ][t];
            af[mf][1] = As[buf][wm + mf * 16 + g + 8][t];
            af[mf][2] = As[buf][wm + mf * 16 + g    ][t + 4];
            af[mf][3] = As[buf][wm + mf * 16 + g + 8][t + 4];
        }
#pragma unroll
        for (int nf = 0; nf < 4; nf++) {
            bf[nf][0] = Bs[buf][wn + nf * 8 + g][t];
            bf[nf][1] = Bs[buf][wn + nf * 8 + g][t + 4];
        }
#pragma unroll
        for (int mf = 0; mf < 4; mf++)
#pragma unroll
            for (int nf = 0; nf < 4; nf++)
                mma16bf(acc[mf][nf], af[mf], bf[nf]);
    }

#pragma unroll
    for (int mf = 0; mf < 4; mf++) {
        int row = m0 + wm + mf * 16 + g;
#pragma unroll
        for (int nf = 0; nf < 4; nf++) {
            int col = n0 + wn + nf * 8 + 2 * t;
            float b0 = bias[col], b1 = bias[col + 1];
            float4 v = acc[mf][nf];
            float2 lo = make_float2(v.x + b0, v.y + b1);
            float2 hi = make_float2(v.z + b0, v.w + b1);
            if (relu) {
                lo.x = fmaxf(lo.x, 0.f); lo.y = fmaxf(lo.y, 0.f);
                hi.x = fmaxf(hi.x, 0.f); hi.y = fmaxf(hi.y, 0.f);
            }
            *(float2*)&C[(size_t)row * N + col]       = lo;
            *(float2*)&C[(size_t)(row + 8) * N + col] = hi;
        }
    }
}

// ------------------------- BF16 GEMM with bf16 output (value proj) -----------
__global__ __launch_bounds__(256) void gemm_bf16_obf(
    const float* __restrict__ A, const float* __restrict__ W,
    const float* __restrict__ bias, __nv_bfloat16* __restrict__ C,
    int M, int N, int K)
{
    __shared__ uint32_t As[2][128][12];
    __shared__ uint32_t Bs[2][128][12];
    const int tid  = threadIdx.x;
    const int warp = tid >> 5, lane = tid & 31;
    const int g = lane >> 2, t = lane & 3;
    const int wm = (warp >> 2) * 64, wn = (warp & 3) * 32;
    const int m0 = blockIdx.y * 128, n0 = blockIdx.x * 128;
    const int r_ld = tid >> 2, c_ld = (tid & 3) * 4;

    const float* Ap = A + (size_t)(m0 + r_ld) * K + c_ld;
    const float* Wp = W + (size_t)(n0 + r_ld) * K + c_ld;

    float4 acc[4][4];
#pragma unroll
    for (int i = 0; i < 4; i++)
#pragma unroll
        for (int j = 0; j < 4; j++) acc[i][j] = make_float4(0.f, 0.f, 0.f, 0.f);

#pragma unroll
    for (int i = 0; i < 2; i++) {
        float4 a = *(const float4*)(Ap + (size_t)(64 * i) * K);
        float4 b = *(const float4*)(Wp + (size_t)(64 * i) * K);
        uint32_t* as = &As[0][r_ld + 64 * i][c_ld >> 1];
        uint32_t* bs = &Bs[0][r_ld + 64 * i][c_ld >> 1];
        as[0] = packbf(a.x, a.y); as[1] = packbf(a.z, a.w);
        bs[0] = packbf(b.x, b.y); bs[1] = packbf(b.z, b.w);
    }
    __syncthreads();

    int buf = 0;
    for (int k0 = 16; k0 < K; k0 += 16) {
        float4 pa0 = *(const float4*)(Ap + k0);
        float4 pa1 = *(const float4*)(Ap + (size_t)64 * K + k0);
        float4 pb0 = *(const float4*)(Wp + k0);
        float4 pb1 = *(const float4*)(Wp + (size_t)64 * K + k0);

        {
            uint32_t af[4][4], bf[4][2];
#pragma unroll
            for (int mf = 0; mf < 4; mf++) {
                af[mf][0] = As[buf][wm + mf * 16 + g    ][t];
                af[mf][1] = As[buf][wm + mf * 16 + g + 8][t];
                af[mf][2] = As[buf][wm + mf * 16 + g    ][t + 4];
                af[mf][3] = As[buf][wm + mf * 16 + g + 8][t + 4];
            }
#pragma unroll
            for (int nf = 0; nf < 4; nf++) {
                bf[nf][0] = Bs[buf][wn + nf * 8 + g][t];
                bf[nf][1] = Bs[buf][wn + nf * 8 + g][t + 4];
            }
#pragma unroll
            for (int mf = 0; mf < 4; mf++)
#pragma unroll
                for (int nf = 0; nf < 4; nf++)
                    mma16bf(acc[mf][nf], af[mf], bf[nf]);
        }

        {
            uint32_t* as = &As[buf ^ 1][r_ld][c_ld >> 1];
            uint32_t* bs = &Bs[buf ^ 1][r_ld][c_ld >> 1];
            as[0] = packbf(pa0.x, pa0.y); as[1] = packbf(pa0.z, pa0.w);
            bs[0] = packbf(pb0.x, pb0.y); bs[1] = packbf(pb0.z, pb0.w);
            uint32_t* as2 = &As[buf ^ 1][r_ld + 64][c_ld >> 1];
            uint32_t* bs2 = &Bs[buf ^ 1][r_ld + 64][c_ld >> 1];
            as2[0] = packbf(pa1.x, pa1.y); as2[1] = packbf(pa1.z, pa1.w);
            bs2[0] = packbf(pb1.x, pb1.y); bs2[1] = packbf(pb1.z, pb1.w);
        }
        __syncthreads();
        buf ^= 1;
    }

    {
        uint32_t af[4][4], bf[4][2];
#pragma unroll
        for (int mf = 0; mf < 4; mf++) {
            af[mf][0] = As[buf][wm + mf * 16 + g    ][t];
            af[mf][1] = As[buf][wm + mf * 16 + g + 8][t];
            af[mf][2] = As[buf][wm + mf * 16 + g    ][t + 4];
            af[mf][3] = As[buf][wm + mf * 16 + g + 8][t + 4];
        }
#pragma unroll
        for (int nf = 0; nf < 4; nf++) {
            bf[nf][0] = Bs[buf][wn + nf * 8 + g][t];
            bf[nf][1] = Bs[buf][wn + nf * 8 + g][t + 4];
        }
#pragma unroll
        for (int mf = 0; mf < 4; mf++)
#pragma unroll
            for (int nf = 0; nf < 4; nf++)
                mma16bf(acc[mf][nf], af[mf], bf[nf]);
    }

#pragma unroll
    for (int mf = 0; mf < 4; mf++) {
        int row = m0 + wm + mf * 16 + g;
#pragma unroll
        for (int nf = 0; nf < 4; nf++) {
            int col = n0 + wn + nf * 8 + 2 * t;
            float b0 = bias[col], b1 = bias[col + 1];
            float4 v = acc[mf][nf];
            *(uint32_t*)&C[(size_t)row * N + col]       = packbf(v.x + b0, v.y + b1);
            *(uint32_t*)&C[(size_t)(row + 8) * N + col] = packbf(v.z + b0, v.w + b1);
        }
    }
}

// ------------------------- tensor-core flash attention -----------------------
// grid (8, 32), 256 thr = 8 warps; warp = 16 q-rows x 64 keys.
__global__ __launch_bounds__(256) void flash_attn_mma(
    const float* __restrict__ qkproj, const float* __restrict__ vsrc,
    float* __restrict__ O)
{
    __shared__ uint32_t sm[8064];
    uint32_t* Ks = sm;
    uint32_t* Vs = sm + 2304;
    uint32_t* Ps = sm + 3456;
    uint32_t* Qstage = sm;

    const int bh = blockIdx.y, b = bh >> 3, h = bh & 7;
    const int q0 = blockIdx.x * 128;
    const int tid = threadIdx.x, warp = tid >> 5, lane = tid & 31;
    const int g = lane >> 2, t = lane & 3;
    const float SC = 0.1767766952966368932f;

    const float* qp = qkproj + (size_t)b * LQd * 512 + h * DHd;
    const float* kp = qp + 256;
    const float* vp = vsrc + (size_t)b * LQd * CCd + h * DHd;

#pragma unroll
    for (int i = 0; i < 16; i++) {
        int idx = tid + i * 256;
        int row = idx >> 5, d = idx & 31;
        Qstage[row * 36 + d] = f2tf32(qp[(size_t)(q0 + row) * 512 + d] * SC);
    }
    __syncthreads();
    uint32_t qf[4][4];
#pragma unroll
    for (int kc = 0; kc < 4; kc++) {
        int r = (warp * 16 + g) * 36;
        qf[kc][0] = Qstage[r + kc * 8 + t];
        qf[kc][1] = Qstage[r + 8 * 36 + kc * 8 + t];
        qf[kc][2] = Qstage[r + kc * 8 + t + 4];
        qf[kc][3] = Qstage[r + 8 * 36 + kc * 8 + t + 4];
    }

    uint32_t* Pw = Ps + warp * 16 * 36;
    float m0r = -1e30f, m1r = -1e30f, l0r = 0.f, l1r = 0.f;
    float4 oacc[4];
#pragma unroll
    for (int i = 0; i < 4; i++) oacc[i] = make_float4(0.f, 0.f, 0.f, 0.f);

    for (int kt = 0; kt < 16; kt++) {
        const float* kbase = kp + (size_t)kt * 64 * 512;
        const float* vbase = vp + (size_t)kt * 64 * 256;
        __syncthreads();
#pragma unroll
        for (int i = 0; i < 8; i++) {
            int idx = tid + i * 256;
            int key = idx >> 5, d = idx & 31;
            Ks[key * 36 + d] = f2tf32(kbase[(size_t)key * 512 + d]);
        }
#pragma unroll
        for (int i = 0; i < 4; i++) {
            int idx = tid + i * 256;
            int kpair = idx >> 5, d = idx & 31;
            float v0 = vbase[(size_t)(2 * kpair) * 256 + d];
            float v1 = vbase[(size_t)(2 * kpair + 1) * 256 + d];
            Vs[d * 36 + kpair] = packbf(v0, v1);
        }
        __syncthreads();

        float4 sacc[8];
#pragma unroll
        for (int nf = 0; nf < 8; nf++) sacc[nf] = make_float4(0.f, 0.f, 0.f, 0.f);
#pragma unroll
        for (int nf = 0; nf < 8; nf++) {
#pragma unroll
            for (int kc = 0; kc < 4; kc++) {
                uint32_t bfr[2];
                bfr[0] = Ks[(nf * 8 + g) * 36 + kc * 8 + t];
                bfr[1] = Ks[(nf * 8 + g) * 36 + kc * 8 + t + 4];
                mma8(sacc[nf], qf[kc], bfr);
            }
        }

        float mx0 = -1e30f, mx1 = -1e30f;
#pragma unroll
        for (int nf = 0; nf < 8; nf++) {
            mx0 = fmaxf(mx0, fmaxf(sacc[nf].x, sacc[nf].y));
            mx1 = fmaxf(mx1, fmaxf(sacc[nf].z, sacc[nf].w));
        }
        mx0 = fmaxf(mx0, __shfl_xor_sync(0xffffffffu, mx0, 1));
        mx0 = fmaxf(mx0, __shfl_xor_sync(0xffffffffu, mx0, 2));
        mx1 = fmaxf(mx1, __shfl_xor_sync(0xffffffffu, mx1, 1));
        mx1 = fmaxf(mx1, __shfl_xor_sync(0xffffffffu, mx1, 2));
        float mn0 = fmaxf(m0r, mx0), mn1 = fmaxf(m1r, mx1);
        float cf0 = __expf(m0r - mn0), cf1 = __expf(m1r - mn1);
        float rs0 = 0.f, rs1 = 0.f;
#pragma unroll
        for (int nf = 0; nf < 8; nf++) {
            float p0 = __expf(sacc[nf].x - mn0);
            float p1 = __expf(sacc[nf].y - mn0);
            float p2 = __expf(sacc[nf].z - mn1);
            float p3 = __expf(sacc[nf].w - mn1);
            rs0 += p0 + p1; rs1 += p2 + p3;
            Pw[(g    ) * 36 + nf * 4 + t] = packbf(p0, p1);
            Pw[(g + 8) * 36 + nf * 4 + t] = packbf(p2, p3);
        }
        rs0 += __shfl_xor_sync(0xffffffffu, rs0, 1);
        rs0 += __shfl_xor_sync(0xffffffffu, rs0, 2);
        rs1 += __shfl_xor_sync(0xffffffffu, rs1, 1);
        rs1 += __shfl_xor_sync(0xffffffffu, rs1, 2);
        l0r = l0r * cf0 + rs0; l1r = l1r * cf1 + rs1;
        m0r = mn0; m1r = mn1;
#pragma unroll
        for (int nf = 0; nf < 4; nf++) {
            oacc[nf].x *= cf0; oacc[nf].y *= cf0;
            oacc[nf].z *= cf1; oacc[nf].w *= cf1;
        }
        __syncwarp();

#pragma unroll
        for (int kc = 0; kc < 4; kc++) {
            uint32_t af[4];
            af[0] = Pw[(g    ) * 36 + kc * 8 + t];
            af[1] = Pw[(g + 8) * 36 + kc * 8 + t];
            af[2] = Pw[(g    ) * 36 + kc * 8 + t + 4];
            af[3] = Pw[(g + 8) * 36 + kc * 8 + t + 4];
#pragma unroll
            for (int nf = 0; nf < 4; nf++) {
                uint32_t bfr[2];
                bfr[0] = Vs[(nf * 8 + g) * 36 + kc * 8 + t];
                bfr[1] = Vs[(nf * 8 + g) * 36 + kc * 8 + t + 4];
                mma16bf(oacc[nf], af, bfr);
            }
        }
    }

    float inv0 = 1.f / l0r, inv1 = 1.f / l1r;
    int row = q0 + warp * 16 + g;
#pragma unroll
    for (int nf = 0; nf < 4; nf++) {
        int col = h * DHd + nf * 8 + 2 * t;
        *(float2*)&O[(size_t)(b * LQd + row) * CCd + col] =
            make_float2(oacc[nf].x * inv0, oacc[nf].y * inv0);
        *(float2*)&O[(size_t)(b * LQd + row + 8) * CCd + col] =
            make_float2(oacc[nf].z * inv1, oacc[nf].w * inv1);
    }
}

// ------------------------- multi-scale deformable sampling (bf16 value) ------
__global__ void deform_sample(const __nv_bfloat16* __restrict__ value, const float* __restrict__ ref,
                              const float* __restrict__ offaw, float* __restrict__ out)
{
    const int levH[4] = {128, 64, 32, 16};
    const int levW[4] = {128, 64, 32, 16};
    const int levS[4] = {0, 16384, 20480, 21504};
    int bq = blockIdx.x;
    int b  = bq >> 10;
    int h  = threadIdx.x >> 5;
    int d  = threadIdx.x & 31;

    // fused softmax over the 16 attention logits for (bq,h)
    const float* ap = offaw + (size_t)bq * 384 + 256 + h * 16;
    float awv[16];
    float mxa = -1e30f;
#pragma unroll
    for (int i = 0; i < 16; i++) { awv[i] = ap[i]; mxa = fmaxf(mxa, awv[i]); }
    float sa = 0.f;
#pragma unroll
    for (int i = 0; i < 16; i++) { awv[i] = __expf(awv[i] - mxa); sa += awv[i]; }
    float inva = 1.f / sa;

    float acc = 0.f;
#pragma unroll
    for (int l = 0; l < 4; l++) {
        float rx = ref[((size_t)bq * LLd + l) * 2 + 0];
        float ry = ref[((size_t)bq * LLd + l) * 2 + 1];
        int w = levW[l], hh = levH[l], st = levS[l];
        float fw = (float)w, fh = (float)hh;
#pragma unroll
        for (int p = 0; p < 4; p++) {
            size_t oidx = (size_t)bq * 384 + h * 32 + (l * 4 + p) * 2;
            float lx = rx + offaw[oidx]     / fw;
            float ly = ry + offaw[oidx + 1] / fh;
            float x = lx * fw - 0.5f;
            float y = ly * fh - 0.5f;
            float x0f = floorf(x), y0f = floorf(y);
            int x0 = (int)x0f, y0 = (int)y0f;
            float wx1 = x - x0f, wx0 = 1.f - wx1;
            float wy1 = y - y0f, wy0 = 1.f - wy1;
            float a = awv[l * 4 + p] * inva;
            float s = 0.f;
#pragma unroll
            for (int cy = 0; cy < 2; cy++) {
#pragma unroll
                for (int cx = 0; cx < 2; cx++) {
                    int ix = x0 + cx, iy = y0 + cy;
                    if (ix >= 0 && ix < w && iy >= 0 && iy < hh) {
                        float wgt = (cx ? wx1 : wx0) * (cy ? wy1 : wy0);
                        size_t vidx = (((size_t)(b * LSRCd + st + iy * w + ix)) * HHd + h) * DHd + d;
                        s += wgt * __bfloat162float(value[vidx]);
                    }
                }
            }
            acc += a * s;
        }
    }
    out[(size_t)bq * CCd + h * DHd + d] = acc;
}

// ------------------------- launch --------------------------------------------
extern "C" void kernel_launch(void* const* d_in, const int* in_sizes, int n_in,
                              void* d_out, int out_size)
{
    (void)in_sizes; (void)n_in; (void)out_size;
    const float* tgt   = (const float*)d_in[0];
    const float* qpos  = (const float*)d_in[1];
    const float* ref   = (const float*)d_in[2];
    const float* src   = (const float*)d_in[3];
    const float* in_w  = (const float*)d_in[4];
    const float* in_b  = (const float*)d_in[5];
    const float* sa_w  = (const float*)d_in[6];
    const float* sa_b  = (const float*)d_in[7];
    const float* off_w = (const float*)d_in[8];
    const float* off_b = (const float*)d_in[9];
    const float* aw_w  = (const float*)d_in[10];
    const float* aw_b  = (const float*)d_in[11];
    const float* val_w = (const float*)d_in[12];
    const float* val_b = (const float*)d_in[13];
    const float* co_w  = (const float*)d_in[14];
    const float* co_b  = (const float*)d_in[15];
    const float* ln1_g = (const float*)d_in[16];
    const float* ln1_b = (const float*)d_in[17];
    const float* ln2_g = (const float*)d_in[18];
    const float* ln2_b = (const float*)d_in[19];
    const float* ln3_g = (const float*)d_in[20];
    const float* ln3_b = (const float*)d_in[21];
    const float* f1_w  = (const float*)d_in[22];
    const float* f1_b  = (const float*)d_in[23];
    const float* f2_w  = (const float*)d_in[24];
    const float* f2_b  = (const float*)d_in[25];
    float* out = (float*)d_out;

    float *qkproj, *v, *o, *tgt1, *offaw, *woffaw, *boffaw, *samp, *tgt2, *ffn;
    __nv_bfloat16* valbf;
    cudaGetSymbolAddress((void**)&qkproj, g_qkproj);
    cudaGetSymbolAddress((void**)&v,      g_v);
    cudaGetSymbolAddress((void**)&o,      g_o);
    cudaGetSymbolAddress((void**)&tgt1,   g_tgt1);
    cudaGetSymbolAddress((void**)&valbf,  g_valbf);
    cudaGetSymbolAddress((void**)&offaw,  g_offaw);
    cudaGetSymbolAddress((void**)&woffaw, g_woffaw);
    cudaGetSymbolAddress((void**)&boffaw, g_boffaw);
    cudaGetSymbolAddress((void**)&samp,   g_samp);
    cudaGetSymbolAddress((void**)&tgt2,   g_tgt2);
    cudaGetSymbolAddress((void**)&ffn,    g_ffn);

    static cudaStream_t sv = nullptr, sw = nullptr;
    static cudaEvent_t evRoot = nullptr, evV = nullptr, evVal = nullptr, evW = nullptr;
    if (!sv) {
        cudaStreamCreateWithFlags(&sv, cudaStreamNonBlocking);
        cudaStreamCreateWithFlags(&sw, cudaStreamNonBlocking);
        cudaEventCreateWithFlags(&evRoot, cudaEventDisableTiming);
        cudaEventCreateWithFlags(&evV,    cudaEventDisableTiming);
        cudaEventCreateWithFlags(&evVal,  cudaEventDisableTiming);
        cudaEventCreateWithFlags(&evW,    cudaEventDisableTiming);
    }

    cudaEventRecord(evRoot, 0);

    // stream sw: weight concat + big value GEMM (bf16 output; hidden under self-attn)
    cudaStreamWaitEvent(sw, evRoot, 0);
    cudaMemcpyAsync(woffaw,             off_w, 256 * 256 * sizeof(float), cudaMemcpyDeviceToDevice, sw);
    cudaMemcpyAsync(woffaw + 256 * 256, aw_w,  128 * 256 * sizeof(float), cudaMemcpyDeviceToDevice, sw);
    cudaMemcpyAsync(boffaw,             off_b, 256 * sizeof(float),       cudaMemcpyDeviceToDevice, sw);
    cudaMemcpyAsync(boffaw + 256,       aw_b,  128 * sizeof(float),       cudaMemcpyDeviceToDevice, sw);
    cudaEventRecord(evW, sw);
    gemm_bf16_obf<<<dim3(2, 680), 256, 0, sw>>>(src, val_w, val_b, valbf, BB * LSRCd, CCd, CCd);
    cudaEventRecord(evVal, sw);

    // stream sv: V projection (overlaps qkproj)
    cudaStreamWaitEvent(sv, evRoot, 0);
    gemm_tf32_64<<<dim3(4, 64), 128, 0, sv>>>(tgt, nullptr, in_w + 2 * CCd * CCd, in_b + 2 * CCd, v, BQd, CCd, CCd, 0);
    cudaEventRecord(evV, sv);

    // ---- main stream: self-attention ----
    gemm_tf32_64<<<dim3(8, 64), 128>>>(tgt, qpos, in_w, in_b, qkproj, BQd, 512, CCd, 0);
    cudaStreamWaitEvent(0, evV, 0);
    flash_attn_mma<<<dim3(8, 32), 256>>>(qkproj, v, o);
    gemm_ln_tf32<<<BQd / 16, 256>>>(o, sa_w, sa_b, tgt, ln2_g, ln2_b, tgt1, CCd);

    // ---- deformable cross-attention ----
    cudaStreamWaitEvent(0, evW, 0);
    gemm_tf32_64<<<dim3(6, 64), 128>>>(tgt1, qpos, woffaw, boffaw, offaw, BQd, 384, CCd, 0);
    cudaStreamWaitEvent(0, evVal, 0);
    deform_sample<<<BQd, 256>>>(valbf, ref, offaw, samp);
    gemm_ln_tf32<<<BQd / 16, 256>>>(samp, co_w, co_b, tgt1, ln1_g, ln1_b, tgt2, CCd);

    // ---- FFN ----
    gemm_bf16<<<dim3(8, 32), 256>>>(tgt2, f1_w, f1_b, ffn, BQd, DFFd, CCd, 1);
    gemm_ln_tf32<<<BQd / 16, 256>>>(ffn, f2_w, f2_b, tgt2, ln3_g, ln3_b, out, DFFd);
}